// round 2
// baseline (speedup 1.0000x reference)
#include <cuda_runtime.h>

#define CIN1  64
#define COUT  128
#define KTAPS 27
#define NMAX  131072

// ---- scratch (static device globals; no allocation in kernel_launch) ----
__device__ float  g_h1[(size_t)NMAX * COUT];
__device__ float  g_h2[(size_t)NMAX * COUT];
__device__ float  g_res[(size_t)NMAX * COUT];
__device__ float2 g_W1p[KTAPS * (CIN1 / 2) * COUT];
__device__ float2 g_W2p[KTAPS * (COUT / 2) * COUT];
__device__ float2 g_Wdp[(CIN1 / 2) * COUT];
__device__ float  g_part[2 * 256 * COUT];
__device__ float  g_st[6 * COUT];   // [s1|t1|sd|td|s2|t2] each 128

// packed f32x2 FMA (sm_100+): two independent fp32 FMAs per instruction
__device__ __forceinline__ unsigned long long fma2(unsigned long long a,
                                                   unsigned long long b,
                                                   unsigned long long c) {
  unsigned long long d;
  asm("fma.rn.f32x2 %0, %1, %2, %3;" : "=l"(d) : "l"(a), "l"(b), "l"(c));
  return d;
}

// Pre-pair W along the reduction dim: Wp[k][cp][c] = (W[k][2cp][c], W[k][2cp+1][c])
__global__ void pack_w(const float* __restrict__ W, float2* __restrict__ Wp,
                       int KT, int CIN) {
  int total = KT * (CIN / 2) * COUT;
  for (int i = blockIdx.x * blockDim.x + threadIdx.x; i < total;
       i += gridDim.x * blockDim.x) {
    int c  = i % COUT;
    int cp = (i / COUT) % (CIN / 2);
    int k  = i / (COUT * (CIN / 2));
    Wp[i] = make_float2(W[((size_t)k * CIN + 2 * cp) * COUT + c],
                        W[((size_t)k * CIN + 2 * cp + 1) * COUT + c]);
  }
}

// Gathered GEMM: out[n][d] = sum_k sum_c in(nbr[n][k])[c] * W[k][c][d]
// Tile: 64 points x 128 cout per block, 256 threads, each 8 pts x 4 cols.
// Reduction dim paired into f32x2 lanes (acc.lo = even ci, acc.hi = odd ci).
template <int CIN, bool GATHER, bool BNIN>
__global__ __launch_bounds__(256, 2)
void conv_kernel(const float* __restrict__ X, const int* __restrict__ nbr,
                 const float2* __restrict__ Wp, int KT,
                 const float* __restrict__ st, float* __restrict__ out, int n) {
  constexpr int STRIDE = CIN + 8;             // 2-way-max STS conflicts
  __shared__ float xs[64 * STRIDE];
  __shared__ int   idx_s[64 * KTAPS];
  __shared__ float s_s[COUT], s_t[COUT];

  const int t  = threadIdx.x;
  const int n0 = blockIdx.x * 64;

  if (BNIN) {
    if (t < COUT) { s_s[t] = st[t]; s_t[t] = st[COUT + t]; }
  }
  if (GATHER) {
    for (int i = t; i < 64 * KTAPS; i += 256) {
      int row = n0 + i / KTAPS;
      idx_s[i] = (row < n) ? nbr[(size_t)row * KTAPS + (i % KTAPS)] : 0;
    }
  }

  const int tcol = t & 31, trow = t >> 5;
  const int c0 = tcol * 4, p0 = trow * 8;
  const int r = t >> 2, seg = t & 3;          // gather: 4 threads per row

  unsigned long long acc[8][4];
#pragma unroll
  for (int p = 0; p < 8; p++)
#pragma unroll
    for (int i = 0; i < 4; i++) acc[p][i] = 0ull;

  for (int k = 0; k < KT; k++) {
    __syncthreads();
    int src;
    if (GATHER) {
      src = idx_s[r * KTAPS + k];
    } else {
      src = n0 + r;
      if (src >= n) src = n - 1;
    }
    const float4* rp = (const float4*)(X + (size_t)src * CIN);
#pragma unroll
    for (int j = 0; j < CIN / 16; j++) {
      int cf = 4 * j + seg;                   // float4 chunk index in the row
      float4 v = rp[cf];
      if (BNIN) {
        int ci = cf * 4;
        v.x = fmaxf(0.f, v.x * s_s[ci] + s_t[ci]);
        v.y = fmaxf(0.f, v.y * s_s[ci + 1] + s_t[ci + 1]);
        v.z = fmaxf(0.f, v.z * s_s[ci + 2] + s_t[ci + 2]);
        v.w = fmaxf(0.f, v.w * s_s[ci + 3] + s_t[ci + 3]);
      }
      *(float4*)&xs[r * STRIDE + cf * 4] = v;
    }
    __syncthreads();

    const unsigned long long* wrow =
        (const unsigned long long*)(Wp + (size_t)k * (CIN / 2) * COUT);
#pragma unroll 4
    for (int cp = 0; cp < CIN / 2; cp++) {
      const unsigned long long* wb = wrow + (size_t)cp * COUT + c0;
      unsigned long long w0 = wb[0], w1 = wb[1], w2 = wb[2], w3 = wb[3];
#pragma unroll
      for (int p = 0; p < 8; p++) {
        unsigned long long xv =
            *(const unsigned long long*)&xs[(p0 + p) * STRIDE + 2 * cp];
        acc[p][0] = fma2(xv, w0, acc[p][0]);
        acc[p][1] = fma2(xv, w1, acc[p][1]);
        acc[p][2] = fma2(xv, w2, acc[p][2]);
        acc[p][3] = fma2(xv, w3, acc[p][3]);
      }
    }
  }

#pragma unroll
  for (int p = 0; p < 8; p++) {
    int np = n0 + p0 + p;
    if (np < n) {
      float4 o;
      float2 a0 = *(float2*)&acc[p][0];
      float2 a1 = *(float2*)&acc[p][1];
      float2 a2 = *(float2*)&acc[p][2];
      float2 a3 = *(float2*)&acc[p][3];
      o.x = a0.x + a0.y;
      o.y = a1.x + a1.y;
      o.z = a2.x + a2.y;
      o.w = a3.x + a3.y;
      *(float4*)&out[(size_t)np * COUT + c0] = o;
    }
  }
}

// Deterministic two-stage BN stats
__global__ void stats_partial(const float* __restrict__ h,
                              float* __restrict__ part, int n) {
  int c = threadIdx.x;   // 128
  int b = blockIdx.x;    // 256
  float s = 0.f, q = 0.f;
  for (int r = b; r < n; r += 256) {
    float v = h[(size_t)r * COUT + c];
    s += v;
    q += v * v;
  }
  part[b * COUT + c] = s;
  part[256 * COUT + b * COUT + c] = q;
}

__global__ void stats_final(const float* __restrict__ part,
                            const float* __restrict__ g,
                            const float* __restrict__ bta,
                            float* __restrict__ st, int n) {
  int c = threadIdx.x;   // 128
  float s = 0.f, q = 0.f;
  for (int b = 0; b < 256; b++) {
    s += part[b * COUT + c];
    q += part[256 * COUT + b * COUT + c];
  }
  float mu  = s / (float)n;
  float var = q / (float)n - mu * mu;
  float sc  = g[c] * rsqrtf(var + 1e-5f);
  st[c]        = sc;
  st[COUT + c] = bta[c] - mu * sc;
}

// out = relu(bn2(h2pre)) + bn_d(respre)
__global__ void final_add(const float* __restrict__ h2,
                          const float* __restrict__ res,
                          const float* __restrict__ st2,
                          const float* __restrict__ std_,
                          float* __restrict__ out, int n) {
  int i = blockIdx.x * blockDim.x + threadIdx.x;
  int total = n * (COUT / 4);
  if (i < total) {
    int c0 = (i & (COUT / 4 - 1)) * 4;
    float4 h  = ((const float4*)h2)[i];
    float4 r  = ((const float4*)res)[i];
    float4 s2 = *(const float4*)&st2[c0];
    float4 t2 = *(const float4*)&st2[COUT + c0];
    float4 sd = *(const float4*)&std_[c0];
    float4 td = *(const float4*)&std_[COUT + c0];
    float4 o;
    o.x = fmaxf(0.f, h.x * s2.x + t2.x) + (r.x * sd.x + td.x);
    o.y = fmaxf(0.f, h.y * s2.y + t2.y) + (r.y * sd.y + td.y);
    o.z = fmaxf(0.f, h.z * s2.z + t2.z) + (r.z * sd.z + td.z);
    o.w = fmaxf(0.f, h.w * s2.w + t2.w) + (r.w * sd.w + td.w);
    ((float4*)out)[i] = o;
  }
}

extern "C" void kernel_launch(void* const* d_in, const int* in_sizes, int n_in,
                              void* d_out, int out_size) {
  const float* x   = (const float*)d_in[0];
  const int*   nbr = (const int*)d_in[1];   // JAX x64 disabled -> int32
  const float* W1  = (const float*)d_in[2];
  const float* g1  = (const float*)d_in[3];
  const float* b1  = (const float*)d_in[4];
  const float* W2  = (const float*)d_in[5];
  const float* g2  = (const float*)d_in[6];
  const float* b2  = (const float*)d_in[7];
  const float* Wd  = (const float*)d_in[8];
  const float* gd  = (const float*)d_in[9];
  const float* bd  = (const float*)d_in[10];
  float*       out = (float*)d_out;
  const int n = in_sizes[0] / CIN1;

  float *h1, *h2, *res, *part, *st;
  float2 *W1p, *W2p, *Wdp;
  cudaGetSymbolAddress((void**)&h1,  g_h1);
  cudaGetSymbolAddress((void**)&h2,  g_h2);
  cudaGetSymbolAddress((void**)&res, g_res);
  cudaGetSymbolAddress((void**)&W1p, g_W1p);
  cudaGetSymbolAddress((void**)&W2p, g_W2p);
  cudaGetSymbolAddress((void**)&Wdp, g_Wdp);
  cudaGetSymbolAddress((void**)&part, g_part);
  cudaGetSymbolAddress((void**)&st,  g_st);

  pack_w<<<432, 256>>>(W1, W1p, KTAPS, CIN1);
  pack_w<<<864, 256>>>(W2, W2p, KTAPS, COUT);
  pack_w<<<16,  256>>>(Wd, Wdp, 1, CIN1);

  const int nb = (n + 63) / 64;

  // conv1 -> h1pre; bn1 stats
  conv_kernel<CIN1, true, false><<<nb, 256>>>(x, nbr, W1p, KTAPS, st, h1, n);
  stats_partial<<<256, 128>>>(h1, part, n);
  stats_final<<<1, 128>>>(part, g1, b1, st + 0, n);

  // downsample branch: respre = x @ Wd; bn_d stats
  conv_kernel<CIN1, false, false><<<nb, 256>>>(x, nbr, Wdp, 1, st, res, n);
  stats_partial<<<256, 128>>>(res, part, n);
  stats_final<<<1, 128>>>(part, gd, bd, st + 2 * COUT, n);

  // conv2 (bn1+relu applied on gathered rows) -> h2pre; bn2 stats
  conv_kernel<COUT, true, true><<<nb, 256>>>(h1, nbr, W2p, KTAPS, st + 0, h2, n);
  stats_partial<<<256, 128>>>(h2, part, n);
  stats_final<<<1, 128>>>(part, g2, b2, st + 4 * COUT, n);

  // out = relu(bn2(h2pre)) + bn_d(respre)
  const int tot4 = n * (COUT / 4);
  final_add<<<(tot4 + 255) / 256, 256>>>(h2, res, st + 4 * COUT, st + 2 * COUT,
                                         out, n);
}

// round 4
// speedup vs baseline: 1.1544x; 1.1544x over previous
#include <cuda_runtime.h>

#define CIN1  64
#define COUT  128
#define KTAPS 27
#define NMAX  131072

// ---- scratch (static device globals; no allocation in kernel_launch) ----
__device__ float  g_h1[(size_t)NMAX * COUT];
__device__ float  g_h2[(size_t)NMAX * COUT];
__device__ float  g_res[(size_t)NMAX * COUT];
__device__ float2 g_W1p[KTAPS * (CIN1 / 2) * COUT];
__device__ float2 g_W2p[KTAPS * (COUT / 2) * COUT];
__device__ float2 g_Wdp[(CIN1 / 2) * COUT];
__device__ float  g_part[2 * 256 * COUT];
__device__ float  g_st[6 * COUT];   // [s1|t1|sd|td|s2|t2] each 128

// packed f32x2 FMA (sm_100+): two independent fp32 FMAs per instruction
__device__ __forceinline__ unsigned long long fma2(unsigned long long a,
                                                   unsigned long long b,
                                                   unsigned long long c) {
  unsigned long long d;
  asm("fma.rn.f32x2 %0, %1, %2, %3;" : "=l"(d) : "l"(a), "l"(b), "l"(c));
  return d;
}

// Pre-pair W along the reduction dim: Wp[k][cp][c] = (W[k][2cp][c], W[k][2cp+1][c])
__global__ void pack_w(const float* __restrict__ W, float2* __restrict__ Wp,
                       int KT, int CIN) {
  int total = KT * (CIN / 2) * COUT;
  for (int i = blockIdx.x * blockDim.x + threadIdx.x; i < total;
       i += gridDim.x * blockDim.x) {
    int c  = i % COUT;
    int cp = (i / COUT) % (CIN / 2);
    int k  = i / (COUT * (CIN / 2));
    Wp[i] = make_float2(W[((size_t)k * CIN + 2 * cp) * COUT + c],
                        W[((size_t)k * CIN + 2 * cp + 1) * COUT + c]);
  }
}

// Gathered GEMM: out[n][d] = sum_k sum_c in(nbr[n][k])[c] * W[k][c][d]
// Tile: 64 points x 128 cout per block, 256 threads, each 8 pts x 4 cols.
// All inner-loop memory ops are 128-bit; x tile double-buffered in dyn smem.
template <int CIN, bool GATHER, bool BNIN>
__global__ __launch_bounds__(256, 2)
void conv_kernel(const float* __restrict__ X, const int* __restrict__ nbr,
                 const float2* __restrict__ Wp, int KT,
                 const float* __restrict__ st, float* __restrict__ out, int n) {
  constexpr int STRIDE = CIN + 8;           // floats, multiple of 4 (16B align)
  constexpr int NCHUNK = CIN / 16;          // float4 chunks per thread per row
  extern __shared__ float xs_dyn[];         // 2 * 64 * STRIDE floats
  __shared__ int   idx_s[64 * KTAPS];
  __shared__ float s_s[COUT], s_t[COUT];

  const int t  = threadIdx.x;
  const int n0 = blockIdx.x * 64;

  if (BNIN && t < COUT) { s_s[t] = st[t]; s_t[t] = st[COUT + t]; }
  if (GATHER) {
    for (int i = t; i < 64 * KTAPS; i += 256) {
      int row = n0 + i / KTAPS;
      idx_s[i] = (row < n) ? nbr[(size_t)row * KTAPS + (i % KTAPS)] : 0;
    }
  }

  const int tcol = t & 31, trow = t >> 5;
  const int c0 = tcol * 4, p0 = trow * 8;
  const int r = t >> 2, seg = t & 3;        // gather: 4 threads per row

  __syncthreads();                          // idx_s / s_s ready

  float4 stg[NCHUNK];

  // load one gathered row-slice for tap k into registers
  auto ldrow = [&](int k) {
    int src;
    if (GATHER) {
      src = idx_s[r * KTAPS + k];
    } else {
      src = n0 + r;
      if (src >= n) src = n - 1;
    }
    const float4* rp = (const float4*)(X + (size_t)src * CIN);
#pragma unroll
    for (int j = 0; j < NCHUNK; j++) stg[j] = rp[seg + 4 * j];
  };
  // store staged registers (with optional bn1+relu) into smem buffer b
  auto strow = [&](int b) {
    float* base = xs_dyn + b * (64 * STRIDE) + r * STRIDE;
#pragma unroll
    for (int j = 0; j < NCHUNK; j++) {
      int cf = seg + 4 * j;
      float4 v = stg[j];
      if (BNIN) {
        float4 sc = *(const float4*)&s_s[cf * 4];
        float4 tb = *(const float4*)&s_t[cf * 4];
        v.x = fmaxf(0.f, v.x * sc.x + tb.x);
        v.y = fmaxf(0.f, v.y * sc.y + tb.y);
        v.z = fmaxf(0.f, v.z * sc.z + tb.z);
        v.w = fmaxf(0.f, v.w * sc.w + tb.w);
      }
      *(float4*)(base + cf * 4) = v;
    }
  };

  unsigned long long acc[8][4];
#pragma unroll
  for (int p = 0; p < 8; p++)
#pragma unroll
    for (int i = 0; i < 4; i++) acc[p][i] = 0ull;

  ldrow(0);
  strow(0);
  __syncthreads();

  for (int k = 0; k < KT; k++) {
    if (k + 1 < KT) ldrow(k + 1);           // prefetch next tap's gather

    const unsigned long long* wrow =
        (const unsigned long long*)(Wp + (size_t)k * (CIN / 2) * COUT);
    const float* xbase = xs_dyn + (k & 1) * (64 * STRIDE);

#pragma unroll 2
    for (int cp = 0; cp < CIN / 2; cp += 2) {
      const unsigned long long* wb0 = wrow + (size_t)cp * COUT + c0;
      const unsigned long long* wb1 = wrow + (size_t)(cp + 1) * COUT + c0;
      ulonglong2 wa  = *(const ulonglong2*)wb0;        // couts c0,c0+1 @ cp
      ulonglong2 wa2 = *(const ulonglong2*)(wb0 + 2);  // couts c0+2,c0+3 @ cp
      ulonglong2 wc  = *(const ulonglong2*)wb1;        // @ cp+1
      ulonglong2 wc2 = *(const ulonglong2*)(wb1 + 2);
#pragma unroll
      for (int p = 0; p < 8; p++) {
        ulonglong2 xv =
            *(const ulonglong2*)(xbase + (p0 + p) * STRIDE + 2 * cp);
        acc[p][0] = fma2(xv.x, wa.x,  acc[p][0]);
        acc[p][1] = fma2(xv.x, wa.y,  acc[p][1]);
        acc[p][2] = fma2(xv.x, wa2.x, acc[p][2]);
        acc[p][3] = fma2(xv.x, wa2.y, acc[p][3]);
        acc[p][0] = fma2(xv.y, wc.x,  acc[p][0]);
        acc[p][1] = fma2(xv.y, wc.y,  acc[p][1]);
        acc[p][2] = fma2(xv.y, wc2.x, acc[p][2]);
        acc[p][3] = fma2(xv.y, wc2.y, acc[p][3]);
      }
    }

    if (k + 1 < KT) strow((k + 1) & 1);
    __syncthreads();
  }

#pragma unroll
  for (int p = 0; p < 8; p++) {
    int np = n0 + p0 + p;
    if (np < n) {
      float4 o;
      float2 a0 = *(float2*)&acc[p][0];
      float2 a1 = *(float2*)&acc[p][1];
      float2 a2 = *(float2*)&acc[p][2];
      float2 a3 = *(float2*)&acc[p][3];
      o.x = a0.x + a0.y;
      o.y = a1.x + a1.y;
      o.z = a2.x + a2.y;
      o.w = a3.x + a3.y;
      *(float4*)&out[(size_t)np * COUT + c0] = o;
    }
  }
}

// Deterministic two-stage BN stats
__global__ void stats_partial(const float* __restrict__ h,
                              float* __restrict__ part, int n) {
  int c = threadIdx.x;   // 128
  int b = blockIdx.x;    // 256
  float s = 0.f, q = 0.f;
  for (int r = b; r < n; r += 256) {
    float v = h[(size_t)r * COUT + c];
    s += v;
    q += v * v;
  }
  part[b * COUT + c] = s;
  part[256 * COUT + b * COUT + c] = q;
}

__global__ void stats_final(const float* __restrict__ part,
                            const float* __restrict__ g,
                            const float* __restrict__ bta,
                            float* __restrict__ st, int n) {
  int c = threadIdx.x;   // 128
  float s = 0.f, q = 0.f;
  for (int b = 0; b < 256; b++) {
    s += part[b * COUT + c];
    q += part[256 * COUT + b * COUT + c];
  }
  float mu  = s / (float)n;
  float var = q / (float)n - mu * mu;
  float sc  = g[c] * rsqrtf(var + 1e-5f);
  st[c]        = sc;
  st[COUT + c] = bta[c] - mu * sc;
}

// out = relu(bn2(h2pre)) + bn_d(respre)
__global__ void final_add(const float* __restrict__ h2,
                          const float* __restrict__ res,
                          const float* __restrict__ st2,
                          const float* __restrict__ std_,
                          float* __restrict__ out, int n) {
  int i = blockIdx.x * blockDim.x + threadIdx.x;
  int total = n * (COUT / 4);
  if (i < total) {
    int c0 = (i & (COUT / 4 - 1)) * 4;
    float4 h  = ((const float4*)h2)[i];
    float4 r  = ((const float4*)res)[i];
    float4 s2 = *(const float4*)&st2[c0];
    float4 t2 = *(const float4*)&st2[COUT + c0];
    float4 sd = *(const float4*)&std_[c0];
    float4 td = *(const float4*)&std_[COUT + c0];
    float4 o;
    o.x = fmaxf(0.f, h.x * s2.x + t2.x) + (r.x * sd.x + td.x);
    o.y = fmaxf(0.f, h.y * s2.y + t2.y) + (r.y * sd.y + td.y);
    o.z = fmaxf(0.f, h.z * s2.z + t2.z) + (r.z * sd.z + td.z);
    o.w = fmaxf(0.f, h.w * s2.w + t2.w) + (r.w * sd.w + td.w);
    ((float4*)out)[i] = o;
  }
}

extern "C" void kernel_launch(void* const* d_in, const int* in_sizes, int n_in,
                              void* d_out, int out_size) {
  const float* x   = (const float*)d_in[0];
  const int*   nbr = (const int*)d_in[1];   // JAX x64 disabled -> int32
  const float* W1  = (const float*)d_in[2];
  const float* g1  = (const float*)d_in[3];
  const float* b1  = (const float*)d_in[4];
  const float* W2  = (const float*)d_in[5];
  const float* g2  = (const float*)d_in[6];
  const float* b2  = (const float*)d_in[7];
  const float* Wd  = (const float*)d_in[8];
  const float* gd  = (const float*)d_in[9];
  const float* bd  = (const float*)d_in[10];
  float*       out = (float*)d_out;
  const int n = in_sizes[0] / CIN1;

  float *h1, *h2, *res, *part, *st;
  float2 *W1p, *W2p, *Wdp;
  cudaGetSymbolAddress((void**)&h1,  g_h1);
  cudaGetSymbolAddress((void**)&h2,  g_h2);
  cudaGetSymbolAddress((void**)&res, g_res);
  cudaGetSymbolAddress((void**)&W1p, g_W1p);
  cudaGetSymbolAddress((void**)&W2p, g_W2p);
  cudaGetSymbolAddress((void**)&Wdp, g_Wdp);
  cudaGetSymbolAddress((void**)&part, g_part);
  cudaGetSymbolAddress((void**)&st,  g_st);

  const int smem1 = 2 * 64 * (CIN1 + 8) * 4;   // 36864 B
  const int smem2 = 2 * 64 * (COUT + 8) * 4;   // 69632 B
  cudaFuncSetAttribute(conv_kernel<CIN1, true,  false>,
                       cudaFuncAttributeMaxDynamicSharedMemorySize, smem1);
  cudaFuncSetAttribute(conv_kernel<CIN1, false, false>,
                       cudaFuncAttributeMaxDynamicSharedMemorySize, smem1);
  cudaFuncSetAttribute(conv_kernel<COUT, true,  true>,
                       cudaFuncAttributeMaxDynamicSharedMemorySize, smem2);

  pack_w<<<432, 256>>>(W1, W1p, KTAPS, CIN1);
  pack_w<<<864, 256>>>(W2, W2p, KTAPS, COUT);
  pack_w<<<16,  256>>>(Wd, Wdp, 1, CIN1);

  const int nb = (n + 63) / 64;

  // conv1 -> h1pre; bn1 stats
  conv_kernel<CIN1, true, false><<<nb, 256, smem1>>>(x, nbr, W1p, KTAPS, st, h1, n);
  stats_partial<<<256, 128>>>(h1, part, n);
  stats_final<<<1, 128>>>(part, g1, b1, st + 0, n);

  // downsample branch: respre = x @ Wd; bn_d stats
  conv_kernel<CIN1, false, false><<<nb, 256, smem1>>>(x, nbr, Wdp, 1, st, res, n);
  stats_partial<<<256, 128>>>(res, part, n);
  stats_final<<<1, 128>>>(part, gd, bd, st + 2 * COUT, n);

  // conv2 (bn1+relu applied on gathered rows) -> h2pre; bn2 stats
  conv_kernel<COUT, true, true><<<nb, 256, smem2>>>(h1, nbr, W2p, KTAPS, st + 0, h2, n);
  stats_partial<<<256, 128>>>(h2, part, n);
  stats_final<<<1, 128>>>(part, g2, b2, st + 4 * COUT, n);

  // out = relu(bn2(h2pre)) + bn_d(respre)
  const int tot4 = n * (COUT / 4);
  final_add<<<(tot4 + 255) / 256, 256>>>(h2, res, st + 4 * COUT, st + 2 * COUT,
                                         out, n);
}

// round 6
// speedup vs baseline: 2.4974x; 2.1634x over previous
#include <cuda_runtime.h>
#include <cuda_bf16.h>
#include <cstdint>

#define CIN1  64
#define COUT  128
#define KTAPS 27
#define NMAX  131072

// ---- scratch (static device globals; no allocation in kernel_launch) ----
__device__ float g_h1[(size_t)NMAX * COUT];
__device__ float g_h2[(size_t)NMAX * COUT];
__device__ float g_res[(size_t)NMAX * COUT];
// pre-swizzled bf16 weight tile images: [tap][cout=128 rows][CIN bf16], hi/lo
__device__ __align__(16) char g_B1h[KTAPS * 128 * CIN1 * 2];
__device__ __align__(16) char g_B1l[KTAPS * 128 * CIN1 * 2];
__device__ __align__(16) char g_B2h[KTAPS * 128 * COUT * 2];
__device__ __align__(16) char g_B2l[KTAPS * 128 * COUT * 2];
__device__ float2 g_Wdp[(CIN1 / 2) * COUT];
__device__ float  g_part[2 * 256 * COUT];
__device__ float  g_st[6 * COUT];   // [s1|t1|sd|td|s2|t2]

// ------------------------- helpers -------------------------
__device__ __forceinline__ uint32_t smem_u32(const void* p) {
  uint32_t a;
  asm("{ .reg .u64 t; cvta.to.shared.u64 t, %1; cvt.u32.u64 %0, t; }"
      : "=r"(a) : "l"(p));
  return a;
}
__device__ __forceinline__ unsigned long long fma2(unsigned long long a,
                                                   unsigned long long b,
                                                   unsigned long long c) {
  unsigned long long d;
  asm("fma.rn.f32x2 %0, %1, %2, %3;" : "=l"(d) : "l"(a), "l"(b), "l"(c));
  return d;
}
__device__ __forceinline__ void ldsm4(uint32_t* r, uint32_t addr) {
  asm volatile("ldmatrix.sync.aligned.m8n8.x4.shared.b16 {%0,%1,%2,%3}, [%4];"
               : "=r"(r[0]), "=r"(r[1]), "=r"(r[2]), "=r"(r[3]) : "r"(addr));
}
__device__ __forceinline__ void mma_bf16(float* c, const uint32_t* a,
                                         const uint32_t* b) {
  asm volatile(
      "mma.sync.aligned.m16n8k16.row.col.f32.bf16.bf16.f32 "
      "{%0,%1,%2,%3}, {%4,%5,%6,%7}, {%8,%9}, {%0,%1,%2,%3};"
      : "+f"(c[0]), "+f"(c[1]), "+f"(c[2]), "+f"(c[3])
      : "r"(a[0]), "r"(a[1]), "r"(a[2]), "r"(a[3]), "r"(b[0]), "r"(b[1]));
}
// 16B-chunk XOR swizzle inside a row (chunk idx c, row low bits r7)
__device__ __host__ __forceinline__ uint32_t swz16(uint32_t c, uint32_t r7) {
  return (c & ~7u) | ((c ^ r7) & 7u);
}

// ------------------------- weight packing -------------------------
// W [k][cin][cout] f32 -> per-tap tile image [cout row][cin bf16] hi/lo,
// swizzled exactly as the smem tiles the MMA reads.
__global__ void pack_w_mma(const float* __restrict__ W, char* __restrict__ Bh,
                           char* __restrict__ Bl, int KT, int CIN) {
  int ROWB = CIN * 2;
  size_t TILE = (size_t)128 * ROWB;
  int total = KT * CIN * COUT;
  for (int i = blockIdx.x * blockDim.x + threadIdx.x; i < total;
       i += gridDim.x * blockDim.x) {
    int cout = i % COUT;
    int cin  = (i / COUT) % CIN;
    int k    = i / (COUT * CIN);
    float v = W[((size_t)k * CIN + cin) * COUT + cout];
    __nv_bfloat16 h = __float2bfloat16(v);
    __nv_bfloat16 l = __float2bfloat16(v - __bfloat162float(h));
    uint32_t c = (uint32_t)cin >> 3;
    uint32_t off = (uint32_t)cout * ROWB + swz16(c, cout & 7) * 16 +
                   ((uint32_t)cin & 7) * 2;
    *(__nv_bfloat16*)(Bh + (size_t)k * TILE + off) = h;
    *(__nv_bfloat16*)(Bl + (size_t)k * TILE + off) = l;
  }
}

// ------------------------- mma.sync gathered conv -------------------------
// Block: D[128 pts, 128 couts] = sum over 27 taps A_k[128,CIN] * W_k[CIN,128]^T
// 3-term bf16 split (hh + lh + hl), fp32 accumulate in registers.
template <int CIN, bool BNIN>
__global__ __launch_bounds__(256, 1)
void mma_conv(const float* __restrict__ X, const int* __restrict__ nbr,
              const char* __restrict__ Bh, const char* __restrict__ Bl,
              const float* __restrict__ st, float* __restrict__ out, int n) {
  constexpr int ROWB   = CIN * 2;
  constexpr int TILE   = 128 * ROWB;
  constexpr int KSTEPS = CIN / 16;
  constexpr int SEGS   = CIN / 32;     // threads per gathered row
  constexpr int RPP    = 256 / SEGS;   // rows per pass
  extern __shared__ __align__(16) char dsm[];
  char* AHp = dsm;
  char* ALp = dsm + TILE;
  char* BHp = dsm + 2 * TILE;
  char* BLp = dsm + 3 * TILE;
  __shared__ int   idx_s[128 * KTAPS];
  __shared__ float s_s[COUT], s_t[COUT];

  const int t = threadIdx.x, lane = t & 31, wid = t >> 5;
  const int n0 = blockIdx.x * 128;

  if (BNIN && t < COUT) { s_s[t] = st[t]; s_t[t] = st[COUT + t]; }
  for (int i = t; i < 128 * KTAPS; i += 256) {
    int row = n0 + i / KTAPS;
    idx_s[i] = (row < n) ? nbr[(size_t)row * KTAPS + (i % KTAPS)] : 0;
  }
  __syncthreads();

  const int wm = wid & 3, wn = wid >> 2;
  const int aRowL = lane & 15;               // A ldmatrix row within tile
  const int aKh   = lane >> 4;               // A k-half (chunk offset)
  const int bRowL = ((lane >> 4) << 3) | (lane & 7);
  const int bKh   = (lane >> 3) & 1;
  const uint32_t AHu = smem_u32(AHp), ALu = smem_u32(ALp);
  const uint32_t BHu = smem_u32(BHp), BLu = smem_u32(BLp);
  const int rr = t / SEGS, seg = t % SEGS;

  float acc[2][8][4];
#pragma unroll
  for (int m = 0; m < 2; m++)
#pragma unroll
    for (int f = 0; f < 8; f++)
#pragma unroll
      for (int q = 0; q < 4; q++) acc[m][f][q] = 0.f;

  for (int k = 0; k < KTAPS; k++) {
    // ---- B: async copy of pre-swizzled weight tiles (overlapped) ----
    {
      const char* sh = Bh + (size_t)k * TILE;
      const char* sl = Bl + (size_t)k * TILE;
      for (int i = t * 16; i < TILE; i += 256 * 16) {
        asm volatile("cp.async.cg.shared.global [%0], [%1], 16;"
                     :: "r"(BHu + i), "l"(sh + i));
        asm volatile("cp.async.cg.shared.global [%0], [%1], 16;"
                     :: "r"(BLu + i), "l"(sl + i));
      }
      asm volatile("cp.async.commit_group;" ::: "memory");
    }
    // ---- A: gather + bn(+relu) + hi/lo bf16 split into swizzled smem ----
    for (int rb = 0; rb < 128; rb += RPP) {
      int row = rb + rr;
      int src = idx_s[row * KTAPS + k];
      const float4* rp = (const float4*)(X + (size_t)src * CIN) + seg * 8;
      uint32_t r7 = row & 7;
      char* hrow = AHp + row * ROWB;
      char* lrow = ALp + row * ROWB;
#pragma unroll
      for (int j = 0; j < 8; j++) {
        float4 v = rp[j];
        if (BNIN) {
          int ci = seg * 32 + j * 4;
          float4 sc = *(const float4*)&s_s[ci];
          float4 tb = *(const float4*)&s_t[ci];
          v.x = fmaxf(0.f, v.x * sc.x + tb.x);
          v.y = fmaxf(0.f, v.y * sc.y + tb.y);
          v.z = fmaxf(0.f, v.z * sc.z + tb.z);
          v.w = fmaxf(0.f, v.w * sc.w + tb.w);
        }
        __nv_bfloat16 hx = __float2bfloat16(v.x);
        __nv_bfloat16 hy = __float2bfloat16(v.y);
        __nv_bfloat16 hz = __float2bfloat16(v.z);
        __nv_bfloat16 hw = __float2bfloat16(v.w);
        __nv_bfloat162 h01 = __halves2bfloat162(hx, hy);
        __nv_bfloat162 h23 = __halves2bfloat162(hz, hw);
        __nv_bfloat162 l01 = __floats2bfloat162_rn(v.x - __bfloat162float(hx),
                                                   v.y - __bfloat162float(hy));
        __nv_bfloat162 l23 = __floats2bfloat162_rn(v.z - __bfloat162float(hz),
                                                   v.w - __bfloat162float(hw));
        uint32_t e0 = seg * 32 + j * 4;
        uint32_t off = swz16(e0 >> 3, r7) * 16 + (e0 & 7) * 2;
        *(uint2*)(hrow + off) =
            make_uint2(*(uint32_t*)&h01, *(uint32_t*)&h23);
        *(uint2*)(lrow + off) =
            make_uint2(*(uint32_t*)&l01, *(uint32_t*)&l23);
      }
    }
    asm volatile("cp.async.wait_group 0;" ::: "memory");
    __syncthreads();

    // ---- MMA over k-steps ----
#pragma unroll
    for (int ks = 0; ks < KSTEPS; ks++) {
      uint32_t ah[2][4], al[2][4], bb[16];
      uint32_t cbase = 2 * ks;
#pragma unroll
      for (int mt = 0; mt < 2; mt++) {
        uint32_t row = wm * 32 + mt * 16 + aRowL;
        uint32_t off = row * ROWB + swz16(cbase + aKh, row & 7) * 16;
        ldsm4(ah[mt], AHu + off);
        ldsm4(al[mt], ALu + off);
      }
#pragma unroll
      for (int i = 0; i < 4; i++) {
        uint32_t row = wn * 64 + i * 16 + bRowL;
        uint32_t off = row * ROWB + swz16(cbase + bKh, row & 7) * 16;
        ldsm4(&bb[i * 4], BHu + off);
      }
#pragma unroll
      for (int mt = 0; mt < 2; mt++)
#pragma unroll
        for (int f = 0; f < 8; f++) {
          mma_bf16(acc[mt][f], ah[mt], &bb[f * 2]);
          mma_bf16(acc[mt][f], al[mt], &bb[f * 2]);
        }
#pragma unroll
      for (int i = 0; i < 4; i++) {
        uint32_t row = wn * 64 + i * 16 + bRowL;
        uint32_t off = row * ROWB + swz16(cbase + bKh, row & 7) * 16;
        ldsm4(&bb[i * 4], BLu + off);
      }
#pragma unroll
      for (int mt = 0; mt < 2; mt++)
#pragma unroll
        for (int f = 0; f < 8; f++)
          mma_bf16(acc[mt][f], ah[mt], &bb[f * 2]);
    }
    __syncthreads();
  }

  // ---- epilogue: fragment regs -> gmem ----
#pragma unroll
  for (int mt = 0; mt < 2; mt++)
#pragma unroll
    for (int f = 0; f < 8; f++) {
      int row = n0 + wm * 32 + mt * 16 + (lane >> 2);
      int col = wn * 64 + f * 8 + 2 * (lane & 3);
      if (row < n)
        *(float2*)&out[(size_t)row * COUT + col] =
            make_float2(acc[mt][f][0], acc[mt][f][1]);
      if (row + 8 < n)
        *(float2*)&out[(size_t)(row + 8) * COUT + col] =
            make_float2(acc[mt][f][2], acc[mt][f][3]);
    }
}

// ------------------------- downsample (1x1 conv, FFMA2) -------------------------
__global__ void pack_w(const float* __restrict__ W, float2* __restrict__ Wp,
                       int KT, int CIN) {
  int total = KT * (CIN / 2) * COUT;
  for (int i = blockIdx.x * blockDim.x + threadIdx.x; i < total;
       i += gridDim.x * blockDim.x) {
    int c  = i % COUT;
    int cp = (i / COUT) % (CIN / 2);
    int k  = i / (COUT * (CIN / 2));
    Wp[i] = make_float2(W[((size_t)k * CIN + 2 * cp) * COUT + c],
                        W[((size_t)k * CIN + 2 * cp + 1) * COUT + c]);
  }
}

__global__ __launch_bounds__(256, 2)
void dconv_kernel(const float* __restrict__ X, const float2* __restrict__ Wp,
                  float* __restrict__ out, int n) {
  constexpr int CIN = CIN1;
  constexpr int STRIDE = CIN + 8;
  __shared__ float xs[64 * STRIDE];
  const int t = threadIdx.x;
  const int n0 = blockIdx.x * 64;
  const int tcol = t & 31, trow = t >> 5;
  const int c0 = tcol * 4, p0 = trow * 8;
  const int r = t >> 2, seg = t & 3;
  {
    int src = n0 + r;
    if (src >= n) src = n - 1;
    const float4* rp = (const float4*)(X + (size_t)src * CIN);
#pragma unroll
    for (int j = 0; j < CIN / 16; j++)
      *(float4*)&xs[r * STRIDE + (seg + 4 * j) * 4] = rp[seg + 4 * j];
  }
  __syncthreads();
  unsigned long long acc[8][4];
#pragma unroll
  for (int p = 0; p < 8; p++)
#pragma unroll
    for (int i = 0; i < 4; i++) acc[p][i] = 0ull;
  const unsigned long long* wrow = (const unsigned long long*)Wp;
#pragma unroll 2
  for (int cp = 0; cp < CIN / 2; cp += 2) {
    const unsigned long long* wb0 = wrow + (size_t)cp * COUT + c0;
    const unsigned long long* wb1 = wrow + (size_t)(cp + 1) * COUT + c0;
    ulonglong2 wa = *(const ulonglong2*)wb0, wa2 = *(const ulonglong2*)(wb0 + 2);
    ulonglong2 wc = *(const ulonglong2*)wb1, wc2 = *(const ulonglong2*)(wb1 + 2);
#pragma unroll
    for (int p = 0; p < 8; p++) {
      ulonglong2 xv = *(const ulonglong2*)&xs[(p0 + p) * STRIDE + 2 * cp];
      acc[p][0] = fma2(xv.x, wa.x,  acc[p][0]);
      acc[p][1] = fma2(xv.x, wa.y,  acc[p][1]);
      acc[p][2] = fma2(xv.x, wa2.x, acc[p][2]);
      acc[p][3] = fma2(xv.x, wa2.y, acc[p][3]);
      acc[p][0] = fma2(xv.y, wc.x,  acc[p][0]);
      acc[p][1] = fma2(xv.y, wc.y,  acc[p][1]);
      acc[p][2] = fma2(xv.y, wc2.x, acc[p][2]);
      acc[p][3] = fma2(xv.y, wc2.y, acc[p][3]);
    }
  }
#pragma unroll
  for (int p = 0; p < 8; p++) {
    int np = n0 + p0 + p;
    if (np < n) {
      float2 a0 = *(float2*)&acc[p][0], a1 = *(float2*)&acc[p][1];
      float2 a2 = *(float2*)&acc[p][2], a3 = *(float2*)&acc[p][3];
      float4 o = make_float4(a0.x + a0.y, a1.x + a1.y, a2.x + a2.y, a3.x + a3.y);
      *(float4*)&out[(size_t)np * COUT + c0] = o;
    }
  }
}

// ------------------------- BN stats + epilogue -------------------------
__global__ void stats_partial(const float* __restrict__ h,
                              float* __restrict__ part, int n) {
  int c = threadIdx.x, b = blockIdx.x;
  float s = 0.f, q = 0.f;
  for (int r = b; r < n; r += 256) {
    float v = h[(size_t)r * COUT + c];
    s += v;
    q += v * v;
  }
  part[b * COUT + c] = s;
  part[256 * COUT + b * COUT + c] = q;
}

__global__ void stats_final(const float* __restrict__ part,
                            const float* __restrict__ g,
                            const float* __restrict__ bta,
                            float* __restrict__ st, int n) {
  int c = threadIdx.x;
  float s = 0.f, q = 0.f;
  for (int b = 0; b < 256; b++) {
    s += part[b * COUT + c];
    q += part[256 * COUT + b * COUT + c];
  }
  float mu  = s / (float)n;
  float var = q / (float)n - mu * mu;
  float sc  = g[c] * rsqrtf(var + 1e-5f);
  st[c]        = sc;
  st[COUT + c] = bta[c] - mu * sc;
}

__global__ void final_add(const float* __restrict__ h2,
                          const float* __restrict__ res,
                          const float* __restrict__ st2,
                          const float* __restrict__ std_,
                          float* __restrict__ out, int n) {
  int i = blockIdx.x * blockDim.x + threadIdx.x;
  int total = n * (COUT / 4);
  if (i < total) {
    int c0 = (i & (COUT / 4 - 1)) * 4;
    float4 h = ((const float4*)h2)[i];
    float4 r = ((const float4*)res)[i];
    float4 s2 = *(const float4*)&st2[c0];
    float4 t2 = *(const float4*)&st2[COUT + c0];
    float4 sd = *(const float4*)&std_[c0];
    float4 td = *(const float4*)&std_[COUT + c0];
    float4 o;
    o.x = fmaxf(0.f, h.x * s2.x + t2.x) + (r.x * sd.x + td.x);
    o.y = fmaxf(0.f, h.y * s2.y + t2.y) + (r.y * sd.y + td.y);
    o.z = fmaxf(0.f, h.z * s2.z + t2.z) + (r.z * sd.z + td.z);
    o.w = fmaxf(0.f, h.w * s2.w + t2.w) + (r.w * sd.w + td.w);
    ((float4*)out)[i] = o;
  }
}

extern "C" void kernel_launch(void* const* d_in, const int* in_sizes, int n_in,
                              void* d_out, int out_size) {
  const float* x   = (const float*)d_in[0];
  const int*   nbr = (const int*)d_in[1];   // JAX x64 disabled -> int32
  const float* W1  = (const float*)d_in[2];
  const float* g1  = (const float*)d_in[3];
  const float* b1  = (const float*)d_in[4];
  const float* W2  = (const float*)d_in[5];
  const float* g2  = (const float*)d_in[6];
  const float* b2  = (const float*)d_in[7];
  const float* Wd  = (const float*)d_in[8];
  const float* gd  = (const float*)d_in[9];
  const float* bd  = (const float*)d_in[10];
  float*       out = (float*)d_out;
  const int n = in_sizes[0] / CIN1;

  float *h1, *h2, *res, *part, *st;
  float2* Wdp;
  char *B1h, *B1l, *B2h, *B2l;
  cudaGetSymbolAddress((void**)&h1,  g_h1);
  cudaGetSymbolAddress((void**)&h2,  g_h2);
  cudaGetSymbolAddress((void**)&res, g_res);
  cudaGetSymbolAddress((void**)&B1h, g_B1h);
  cudaGetSymbolAddress((void**)&B1l, g_B1l);
  cudaGetSymbolAddress((void**)&B2h, g_B2h);
  cudaGetSymbolAddress((void**)&B2l, g_B2l);
  cudaGetSymbolAddress((void**)&Wdp, g_Wdp);
  cudaGetSymbolAddress((void**)&part, g_part);
  cudaGetSymbolAddress((void**)&st,  g_st);

  const int smem1 = 4 * 128 * CIN1 * 2;   //  65536 B
  const int smem2 = 4 * 128 * COUT * 2;   // 131072 B
  cudaFuncSetAttribute(mma_conv<CIN1, false>,
                       cudaFuncAttributeMaxDynamicSharedMemorySize, smem1);
  cudaFuncSetAttribute(mma_conv<COUT, true>,
                       cudaFuncAttributeMaxDynamicSharedMemorySize, smem2);

  pack_w_mma<<<432, 256>>>(W1, B1h, B1l, KTAPS, CIN1);
  pack_w_mma<<<864, 256>>>(W2, B2h, B2l, KTAPS, COUT);
  pack_w<<<16, 256>>>(Wd, Wdp, 1, CIN1);

  const int nbm = (n + 127) / 128;
  const int nb64 = (n + 63) / 64;

  // conv1 -> h1pre; bn1 stats
  mma_conv<CIN1, false><<<nbm, 256, smem1>>>(x, nbr, B1h, B1l, st, h1, n);
  stats_partial<<<256, 128>>>(h1, part, n);
  stats_final<<<1, 128>>>(part, g1, b1, st + 0, n);

  // downsample branch: respre = x @ Wd; bn_d stats
  dconv_kernel<<<nb64, 256>>>(x, Wdp, res, n);
  stats_partial<<<256, 128>>>(res, part, n);
  stats_final<<<1, 128>>>(part, gd, bd, st + 2 * COUT, n);

  // conv2 (bn1+relu fused into gather) -> h2pre; bn2 stats
  mma_conv<COUT, true><<<nbm, 256, smem2>>>(h1, nbr, B2h, B2l, st + 0, h2, n);
  stats_partial<<<256, 128>>>(h2, part, n);
  stats_final<<<1, 128>>>(part, g2, b2, st + 4 * COUT, n);

  // out = relu(bn2(h2pre)) + bn_d(respre)
  const int tot4 = n * (COUT / 4);
  final_add<<<(tot4 + 255) / 256, 256>>>(h2, res, st + 4 * COUT, st + 2 * COUT,
                                         out, n);
}

// round 7
// speedup vs baseline: 2.9562x; 1.1837x over previous
#include <cuda_runtime.h>
#include <cuda_bf16.h>
#include <cstdint>

#define CIN1  64
#define COUT  128
#define KTAPS 27
#define NMAX  131072
#define TILEB 16384   // one [128 rows x 128B] tile

// ---- scratch (static device globals; no allocation in kernel_launch) ----
__device__ float g_h1[(size_t)NMAX * COUT];
__device__ float g_h2[(size_t)NMAX * COUT];
__device__ float g_res[(size_t)NMAX * COUT];
// pre-swizzled bf16 weight tiles: [step = tap*NC+chunk][128 rows][64 bf16], hi/lo
__device__ __align__(16) char g_B1h[KTAPS * 1 * TILEB];
__device__ __align__(16) char g_B1l[KTAPS * 1 * TILEB];
__device__ __align__(16) char g_B2h[KTAPS * 2 * TILEB];
__device__ __align__(16) char g_B2l[KTAPS * 2 * TILEB];
__device__ float2 g_Wdp[(CIN1 / 2) * COUT];
__device__ float  g_part[2 * 256 * COUT];
__device__ float  g_st[6 * COUT];   // [s1|t1|sd|td|s2|t2]

// ------------------------- helpers -------------------------
__device__ __forceinline__ uint32_t smem_u32(const void* p) {
  uint32_t a;
  asm("{ .reg .u64 t; cvta.to.shared.u64 t, %1; cvt.u32.u64 %0, t; }"
      : "=r"(a) : "l"(p));
  return a;
}
__device__ __forceinline__ unsigned long long fma2(unsigned long long a,
                                                   unsigned long long b,
                                                   unsigned long long c) {
  unsigned long long d;
  asm("fma.rn.f32x2 %0, %1, %2, %3;" : "=l"(d) : "l"(a), "l"(b), "l"(c));
  return d;
}
__device__ __forceinline__ void ldsm4(uint32_t* r, uint32_t addr) {
  asm volatile("ldmatrix.sync.aligned.m8n8.x4.shared.b16 {%0,%1,%2,%3}, [%4];"
               : "=r"(r[0]), "=r"(r[1]), "=r"(r[2]), "=r"(r[3]) : "r"(addr));
}
__device__ __forceinline__ void mma_bf16(float* c, const uint32_t* a,
                                         const uint32_t* b) {
  asm volatile(
      "mma.sync.aligned.m16n8k16.row.col.f32.bf16.bf16.f32 "
      "{%0,%1,%2,%3}, {%4,%5,%6,%7}, {%8,%9}, {%0,%1,%2,%3};"
      : "+f"(c[0]), "+f"(c[1]), "+f"(c[2]), "+f"(c[3])
      : "r"(a[0]), "r"(a[1]), "r"(a[2]), "r"(a[3]), "r"(b[0]), "r"(b[1]));
}
// 16B-chunk XOR swizzle inside a 128B row
__device__ __host__ __forceinline__ uint32_t swz16(uint32_t c, uint32_t r7) {
  return (c & ~7u) | ((c ^ r7) & 7u);
}

// ------------------------- weight packing -------------------------
// W [k][cin][cout] f32 -> per-step tile [cout row][cin-chunk 64 bf16] hi/lo.
__global__ void pack_w_mma(const float* __restrict__ W, char* __restrict__ Bh,
                           char* __restrict__ Bl, int KT, int CIN) {
  int NC = CIN / 64;
  int total = KT * CIN * COUT;
  for (int i = blockIdx.x * blockDim.x + threadIdx.x; i < total;
       i += gridDim.x * blockDim.x) {
    int cout = i % COUT;
    int cin  = (i / COUT) % CIN;
    int k    = i / (COUT * CIN);
    float v = W[((size_t)k * CIN + cin) * COUT + cout];
    __nv_bfloat16 h = __float2bfloat16(v);
    __nv_bfloat16 l = __float2bfloat16(v - __bfloat162float(h));
    int step = k * NC + (cin >> 6);
    uint32_t e = (uint32_t)cin & 63;
    uint32_t off = (uint32_t)cout * 128 + swz16(e >> 3, cout & 7) * 16 +
                   (e & 7) * 2;
    *(__nv_bfloat16*)(Bh + (size_t)step * TILEB + off) = h;
    *(__nv_bfloat16*)(Bl + (size_t)step * TILEB + off) = l;
  }
}

// ------------------------- pipelined mma.sync gathered conv -------------------------
// D[128 pts, 128 couts] = sum over KTAPS*NC steps (K=64 chunk each) of A*B^T,
// 3-term bf16 split (hh + lh + hl), fp32 reg accum. Double-buffered tiles:
// step s+1's gather LDGs + B cp.async overlap step s's MMA.
template <int NC, bool BNIN>
__global__ __launch_bounds__(256, 1)
void mma_conv(const float* __restrict__ X, const int* __restrict__ nbr,
              const char* __restrict__ Bgh, const char* __restrict__ Bgl,
              const float* __restrict__ st, float* __restrict__ out, int n) {
  constexpr int CIN   = NC * 64;
  constexpr int STEPS = KTAPS * NC;
  extern __shared__ char dsm_raw[];
  char* dsm = (char*)(((uintptr_t)dsm_raw + 127) & ~(uintptr_t)127);
  // layout: A buf b: dsm + b*32768 (hi), +16384 (lo); B: dsm+65536 + same
  __shared__ int   idx_s[128 * KTAPS];
  __shared__ float s_s[COUT], s_t[COUT];

  const int t = threadIdx.x, lane = t & 31, wid = t >> 5;
  const int n0 = blockIdx.x * 128;

  if (BNIN && t < COUT) { s_s[t] = st[t]; s_t[t] = st[COUT + t]; }
  for (int i = t; i < 128 * KTAPS; i += 256) {
    int row = n0 + i / KTAPS;
    idx_s[i] = (row < n) ? nbr[(size_t)row * KTAPS + (i % KTAPS)] : 0;
  }
  __syncthreads();

  const int rr = t >> 1, seg = t & 1;        // convert: 2 threads per row
  const int wm = wid & 3, wn = wid >> 2;
  const int aRowL = lane & 15, aKh = lane >> 4;
  const int bRowL = ((lane >> 4) << 3) | (lane & 7);
  const int bKh   = (lane >> 3) & 1;
  const uint32_t Au = smem_u32(dsm);
  const uint32_t Bu = Au + 65536;

  float4 stg[8];
  auto ldA = [&](int sp) {                   // gather LDGs -> regs
    int tap = sp / NC, ch = sp % NC;
    int src = idx_s[rr * KTAPS + tap];
    const float4* rp =
        (const float4*)(X + (size_t)src * CIN + ch * 64 + seg * 32);
#pragma unroll
    for (int j = 0; j < 8; j++) stg[j] = rp[j];
  };
  auto stA = [&](int sp, int b) {            // bn(+relu) + split + STS
    int ch = sp % NC;
    char* hrow = dsm + b * 32768 + rr * 128;
    char* lrow = hrow + TILEB;
    uint32_t r7 = rr & 7;
#pragma unroll
    for (int j = 0; j < 8; j++) {
      float4 v = stg[j];
      if (BNIN) {
        int ci = ch * 64 + seg * 32 + j * 4;
        float4 sc = *(const float4*)&s_s[ci];
        float4 tb = *(const float4*)&s_t[ci];
        v.x = fmaxf(0.f, v.x * sc.x + tb.x);
        v.y = fmaxf(0.f, v.y * sc.y + tb.y);
        v.z = fmaxf(0.f, v.z * sc.z + tb.z);
        v.w = fmaxf(0.f, v.w * sc.w + tb.w);
      }
      __nv_bfloat16 hx = __float2bfloat16(v.x);
      __nv_bfloat16 hy = __float2bfloat16(v.y);
      __nv_bfloat16 hz = __float2bfloat16(v.z);
      __nv_bfloat16 hw = __float2bfloat16(v.w);
      __nv_bfloat162 h01 = __halves2bfloat162(hx, hy);
      __nv_bfloat162 h23 = __halves2bfloat162(hz, hw);
      __nv_bfloat162 l01 = __floats2bfloat162_rn(v.x - __bfloat162float(hx),
                                                 v.y - __bfloat162float(hy));
      __nv_bfloat162 l23 = __floats2bfloat162_rn(v.z - __bfloat162float(hz),
                                                 v.w - __bfloat162float(hw));
      uint32_t e0 = seg * 32 + j * 4;
      uint32_t off = swz16(e0 >> 3, r7) * 16 + (e0 & 7) * 2;
      *(uint2*)(hrow + off) = make_uint2(*(uint32_t*)&h01, *(uint32_t*)&h23);
      *(uint2*)(lrow + off) = make_uint2(*(uint32_t*)&l01, *(uint32_t*)&l23);
    }
  };
  auto cpB = [&](int sp, int b) {            // pre-swizzled B tiles, async
    const char* sh = Bgh + (size_t)sp * TILEB;
    const char* sl = Bgl + (size_t)sp * TILEB;
    uint32_t dh = Bu + b * 32768, dl = dh + TILEB;
#pragma unroll
    for (int i = t * 16; i < TILEB; i += 4096) {
      asm volatile("cp.async.cg.shared.global [%0], [%1], 16;"
                   :: "r"(dh + i), "l"(sh + i));
      asm volatile("cp.async.cg.shared.global [%0], [%1], 16;"
                   :: "r"(dl + i), "l"(sl + i));
    }
    asm volatile("cp.async.commit_group;" ::: "memory");
  };

  float acc[2][8][4];
#pragma unroll
  for (int m = 0; m < 2; m++)
#pragma unroll
    for (int f = 0; f < 8; f++)
#pragma unroll
      for (int q = 0; q < 4; q++) acc[m][f][q] = 0.f;

  // prologue: fill buffer 0
  cpB(0, 0);
  ldA(0);
  stA(0, 0);
  asm volatile("cp.async.wait_group 0;" ::: "memory");
  __syncthreads();

  for (int s = 0; s < STEPS; s++) {
    const int cb = s & 1, nb2 = (s + 1) & 1;
    const bool more = (s + 1 < STEPS);
    if (more) {
      cpB(s + 1, nb2);
      ldA(s + 1);          // LDG latency hides under MMA below
    }
    const uint32_t AHu = Au + cb * 32768, ALu = AHu + TILEB;
    const uint32_t BHu = Bu + cb * 32768, BLu = BHu + TILEB;
#pragma unroll
    for (int ks = 0; ks < 4; ks++) {
      uint32_t ah[2][4], al[2][4], bb[16];
      uint32_t cbase = 2 * ks;
#pragma unroll
      for (int mt = 0; mt < 2; mt++) {
        uint32_t row = wm * 32 + mt * 16 + aRowL;
        uint32_t off = row * 128 + swz16(cbase + aKh, row & 7) * 16;
        ldsm4(ah[mt], AHu + off);
        ldsm4(al[mt], ALu + off);
      }
#pragma unroll
      for (int i = 0; i < 4; i++) {
        uint32_t row = wn * 64 + i * 16 + bRowL;
        uint32_t off = row * 128 + swz16(cbase + bKh, row & 7) * 16;
        ldsm4(&bb[i * 4], BHu + off);
      }
#pragma unroll
      for (int mt = 0; mt < 2; mt++)
#pragma unroll
        for (int f = 0; f < 8; f++) {
          mma_bf16(acc[mt][f], ah[mt], &bb[f * 2]);
          mma_bf16(acc[mt][f], al[mt], &bb[f * 2]);
        }
#pragma unroll
      for (int i = 0; i < 4; i++) {
        uint32_t row = wn * 64 + i * 16 + bRowL;
        uint32_t off = row * 128 + swz16(cbase + bKh, row & 7) * 16;
        ldsm4(&bb[i * 4], BLu + off);
      }
#pragma unroll
      for (int mt = 0; mt < 2; mt++)
#pragma unroll
        for (int f = 0; f < 8; f++)
          mma_bf16(acc[mt][f], ah[mt], &bb[f * 2]);
    }
    if (more) {
      stA(s + 1, nb2);
      asm volatile("cp.async.wait_group 0;" ::: "memory");
    }
    __syncthreads();
  }

  // ---- epilogue: fragment regs -> gmem ----
#pragma unroll
  for (int mt = 0; mt < 2; mt++)
#pragma unroll
    for (int f = 0; f < 8; f++) {
      int row = n0 + wm * 32 + mt * 16 + (lane >> 2);
      int col = wn * 64 + f * 8 + 2 * (lane & 3);
      if (row < n)
        *(float2*)&out[(size_t)row * COUT + col] =
            make_float2(acc[mt][f][0], acc[mt][f][1]);
      if (row + 8 < n)
        *(float2*)&out[(size_t)(row + 8) * COUT + col] =
            make_float2(acc[mt][f][2], acc[mt][f][3]);
    }
}

// ------------------------- downsample (1x1 conv, FFMA2) -------------------------
__global__ void pack_w(const float* __restrict__ W, float2* __restrict__ Wp,
                       int KT, int CIN) {
  int total = KT * (CIN / 2) * COUT;
  for (int i = blockIdx.x * blockDim.x + threadIdx.x; i < total;
       i += gridDim.x * blockDim.x) {
    int c  = i % COUT;
    int cp = (i / COUT) % (CIN / 2);
    int k  = i / (COUT * (CIN / 2));
    Wp[i] = make_float2(W[((size_t)k * CIN + 2 * cp) * COUT + c],
                        W[((size_t)k * CIN + 2 * cp + 1) * COUT + c]);
  }
}

__global__ __launch_bounds__(256, 2)
void dconv_kernel(const float* __restrict__ X, const float2* __restrict__ Wp,
                  float* __restrict__ out, int n) {
  constexpr int CIN = CIN1;
  constexpr int STRIDE = CIN + 8;
  __shared__ float xs[64 * STRIDE];
  const int t = threadIdx.x;
  const int n0 = blockIdx.x * 64;
  const int tcol = t & 31, trow = t >> 5;
  const int c0 = tcol * 4, p0 = trow * 8;
  const int r = t >> 2, seg = t & 3;
  {
    int src = n0 + r;
    if (src >= n) src = n - 1;
    const float4* rp = (const float4*)(X + (size_t)src * CIN);
#pragma unroll
    for (int j = 0; j < CIN / 16; j++)
      *(float4*)&xs[r * STRIDE + (seg + 4 * j) * 4] = rp[seg + 4 * j];
  }
  __syncthreads();
  unsigned long long acc[8][4];
#pragma unroll
  for (int p = 0; p < 8; p++)
#pragma unroll
    for (int i = 0; i < 4; i++) acc[p][i] = 0ull;
  const unsigned long long* wrow = (const unsigned long long*)Wp;
#pragma unroll 2
  for (int cp = 0; cp < CIN / 2; cp += 2) {
    const unsigned long long* wb0 = wrow + (size_t)cp * COUT + c0;
    const unsigned long long* wb1 = wrow + (size_t)(cp + 1) * COUT + c0;
    ulonglong2 wa = *(const ulonglong2*)wb0, wa2 = *(const ulonglong2*)(wb0 + 2);
    ulonglong2 wc = *(const ulonglong2*)wb1, wc2 = *(const ulonglong2*)(wb1 + 2);
#pragma unroll
    for (int p = 0; p < 8; p++) {
      ulonglong2 xv = *(const ulonglong2*)&xs[(p0 + p) * STRIDE + 2 * cp];
      acc[p][0] = fma2(xv.x, wa.x,  acc[p][0]);
      acc[p][1] = fma2(xv.x, wa.y,  acc[p][1]);
      acc[p][2] = fma2(xv.x, wa2.x, acc[p][2]);
      acc[p][3] = fma2(xv.x, wa2.y, acc[p][3]);
      acc[p][0] = fma2(xv.y, wc.x,  acc[p][0]);
      acc[p][1] = fma2(xv.y, wc.y,  acc[p][1]);
      acc[p][2] = fma2(xv.y, wc2.x, acc[p][2]);
      acc[p][3] = fma2(xv.y, wc2.y, acc[p][3]);
    }
  }
#pragma unroll
  for (int p = 0; p < 8; p++) {
    int np = n0 + p0 + p;
    if (np < n) {
      float2 a0 = *(float2*)&acc[p][0], a1 = *(float2*)&acc[p][1];
      float2 a2 = *(float2*)&acc[p][2], a3 = *(float2*)&acc[p][3];
      float4 o = make_float4(a0.x + a0.y, a1.x + a1.y, a2.x + a2.y, a3.x + a3.y);
      *(float4*)&out[(size_t)np * COUT + c0] = o;
    }
  }
}

// ------------------------- BN stats + epilogue -------------------------
__global__ void stats_partial(const float* __restrict__ h,
                              float* __restrict__ part, int n) {
  int c = threadIdx.x, b = blockIdx.x;
  float s = 0.f, q = 0.f;
  for (int r = b; r < n; r += 256) {
    float v = h[(size_t)r * COUT + c];
    s += v;
    q += v * v;
  }
  part[b * COUT + c] = s;
  part[256 * COUT + b * COUT + c] = q;
}

__global__ void stats_final(const float* __restrict__ part,
                            const float* __restrict__ g,
                            const float* __restrict__ bta,
                            float* __restrict__ st, int n) {
  int c = threadIdx.x;
  float s = 0.f, q = 0.f;
  for (int b = 0; b < 256; b++) {
    s += part[b * COUT + c];
    q += part[256 * COUT + b * COUT + c];
  }
  float mu  = s / (float)n;
  float var = q / (float)n - mu * mu;
  float sc  = g[c] * rsqrtf(var + 1e-5f);
  st[c]        = sc;
  st[COUT + c] = bta[c] - mu * sc;
}

__global__ void final_add(const float* __restrict__ h2,
                          const float* __restrict__ res,
                          const float* __restrict__ st2,
                          const float* __restrict__ std_,
                          float* __restrict__ out, int n) {
  int i = blockIdx.x * blockDim.x + threadIdx.x;
  int total = n * (COUT / 4);
  if (i < total) {
    int c0 = (i & (COUT / 4 - 1)) * 4;
    float4 h = ((const float4*)h2)[i];
    float4 r = ((const float4*)res)[i];
    float4 s2 = *(const float4*)&st2[c0];
    float4 t2 = *(const float4*)&st2[COUT + c0];
    float4 sd = *(const float4*)&std_[c0];
    float4 td = *(const float4*)&std_[COUT + c0];
    float4 o;
    o.x = fmaxf(0.f, h.x * s2.x + t2.x) + (r.x * sd.x + td.x);
    o.y = fmaxf(0.f, h.y * s2.y + t2.y) + (r.y * sd.y + td.y);
    o.z = fmaxf(0.f, h.z * s2.z + t2.z) + (r.z * sd.z + td.z);
    o.w = fmaxf(0.f, h.w * s2.w + t2.w) + (r.w * sd.w + td.w);
    ((float4*)out)[i] = o;
  }
}

extern "C" void kernel_launch(void* const* d_in, const int* in_sizes, int n_in,
                              void* d_out, int out_size) {
  const float* x   = (const float*)d_in[0];
  const int*   nbr = (const int*)d_in[1];   // JAX x64 disabled -> int32
  const float* W1  = (const float*)d_in[2];
  const float* g1  = (const float*)d_in[3];
  const float* b1  = (const float*)d_in[4];
  const float* W2  = (const float*)d_in[5];
  const float* g2  = (const float*)d_in[6];
  const float* b2  = (const float*)d_in[7];
  const float* Wd  = (const float*)d_in[8];
  const float* gd  = (const float*)d_in[9];
  const float* bd  = (const float*)d_in[10];
  float*       out = (float*)d_out;
  const int n = in_sizes[0] / CIN1;

  float *h1, *h2, *res, *part, *st;
  float2* Wdp;
  char *B1h, *B1l, *B2h, *B2l;
  cudaGetSymbolAddress((void**)&h1,  g_h1);
  cudaGetSymbolAddress((void**)&h2,  g_h2);
  cudaGetSymbolAddress((void**)&res, g_res);
  cudaGetSymbolAddress((void**)&B1h, g_B1h);
  cudaGetSymbolAddress((void**)&B1l, g_B1l);
  cudaGetSymbolAddress((void**)&B2h, g_B2h);
  cudaGetSymbolAddress((void**)&B2l, g_B2l);
  cudaGetSymbolAddress((void**)&Wdp, g_Wdp);
  cudaGetSymbolAddress((void**)&part, g_part);
  cudaGetSymbolAddress((void**)&st,  g_st);

  const int smem = 4 * 2 * TILEB + 256;   // 131328 B (double-buffered tiles)
  cudaFuncSetAttribute(mma_conv<1, false>,
                       cudaFuncAttributeMaxDynamicSharedMemorySize, smem);
  cudaFuncSetAttribute(mma_conv<2, true>,
                       cudaFuncAttributeMaxDynamicSharedMemorySize, smem);

  pack_w_mma<<<432, 256>>>(W1, B1h, B1l, KTAPS, CIN1);
  pack_w_mma<<<864, 256>>>(W2, B2h, B2l, KTAPS, COUT);
  pack_w<<<16, 256>>>(Wd, Wdp, 1, CIN1);

  const int nbm = (n + 127) / 128;
  const int nb64 = (n + 63) / 64;

  // conv1 -> h1pre; bn1 stats
  mma_conv<1, false><<<nbm, 256, smem>>>(x, nbr, B1h, B1l, st, h1, n);
  stats_partial<<<256, 128>>>(h1, part, n);
  stats_final<<<1, 128>>>(part, g1, b1, st + 0, n);

  // downsample branch: respre = x @ Wd; bn_d stats
  dconv_kernel<<<nb64, 256>>>(x, Wdp, res, n);
  stats_partial<<<256, 128>>>(res, part, n);
  stats_final<<<1, 128>>>(part, gd, bd, st + 2 * COUT, n);

  // conv2 (bn1+relu fused into gather) -> h2pre; bn2 stats
  mma_conv<2, true><<<nbm, 256, smem>>>(h1, nbr, B2h, B2l, st + 0, h2, n);
  stats_partial<<<256, 128>>>(h2, part, n);
  stats_final<<<1, 128>>>(part, g2, b2, st + 4 * COUT, n);

  // out = relu(bn2(h2pre)) + bn_d(respre)
  const int tot4 = n * (COUT / 4);
  final_add<<<(tot4 + 255) / 256, 256>>>(h2, res, st + 4 * COUT, st + 2 * COUT,
                                         out, n);
}

// round 9
// speedup vs baseline: 3.5115x; 1.1878x over previous
#include <cuda_runtime.h>
#include <cuda_bf16.h>
#include <cstdint>

#define CIN1  64
#define COUT  128
#define KTAPS 27
#define NMAX  131072
#define TILEB 16384   // one [128 rows x 128B] tile

// ---- scratch (static device globals; no allocation in kernel_launch) ----
__device__ float g_h1[(size_t)NMAX * COUT];
__device__ float g_h2[(size_t)NMAX * COUT];
__device__ float g_res[(size_t)NMAX * COUT];
// pre-swizzled bf16 weight tiles: [step = tap*NC+chunk][128 rows][64 bf16], hi/lo
__device__ __align__(16) char g_B1h[KTAPS * 1 * TILEB];
__device__ __align__(16) char g_B1l[KTAPS * 1 * TILEB];
__device__ __align__(16) char g_B2h[KTAPS * 2 * TILEB];
__device__ __align__(16) char g_B2l[KTAPS * 2 * TILEB];
__device__ float2 g_Wdp[(CIN1 / 2) * COUT];
__device__ float  g_part[2 * 256 * COUT];
__device__ float  g_st[6 * COUT];   // [s1|t1|sd|td|s2|t2]

// ------------------------- helpers -------------------------
__device__ __forceinline__ uint32_t smem_u32(const void* p) {
  uint32_t a;
  asm("{ .reg .u64 t; cvta.to.shared.u64 t, %1; cvt.u32.u64 %0, t; }"
      : "=r"(a) : "l"(p));
  return a;
}
__device__ __forceinline__ unsigned long long fma2(unsigned long long a,
                                                   unsigned long long b,
                                                   unsigned long long c) {
  unsigned long long d;
  asm("fma.rn.f32x2 %0, %1, %2, %3;" : "=l"(d) : "l"(a), "l"(b), "l"(c));
  return d;
}
__device__ __forceinline__ void ldsm4(uint32_t* r, uint32_t addr) {
  asm volatile("ldmatrix.sync.aligned.m8n8.x4.shared.b16 {%0,%1,%2,%3}, [%4];"
               : "=r"(r[0]), "=r"(r[1]), "=r"(r[2]), "=r"(r[3]) : "r"(addr));
}
__device__ __forceinline__ void mma_bf16(float* c, const uint32_t* a,
                                         const uint32_t* b) {
  asm volatile(
      "mma.sync.aligned.m16n8k16.row.col.f32.bf16.bf16.f32 "
      "{%0,%1,%2,%3}, {%4,%5,%6,%7}, {%8,%9}, {%0,%1,%2,%3};"
      : "+f"(c[0]), "+f"(c[1]), "+f"(c[2]), "+f"(c[3])
      : "r"(a[0]), "r"(a[1]), "r"(a[2]), "r"(a[3]), "r"(b[0]), "r"(b[1]));
}
// 16B-chunk XOR swizzle inside a 128B row
__device__ __host__ __forceinline__ uint32_t swz16(uint32_t c, uint32_t r7) {
  return (c & ~7u) | ((c ^ r7) & 7u);
}
#define BAR_SYNC(id)   asm volatile("bar.sync %0, 384;"   :: "r"(id) : "memory")
#define BAR_ARRIVE(id) asm volatile("bar.arrive %0, 384;" :: "r"(id) : "memory")

// ------------------------- weight packing -------------------------
// W [k][cin][cout] f32 -> per-step tile [cout row][cin-chunk 64 bf16] hi/lo.
__global__ void pack_w_mma(const float* __restrict__ W, char* __restrict__ Bh,
                           char* __restrict__ Bl, int KT, int CIN) {
  int NC = CIN / 64;
  int total = KT * CIN * COUT;
  for (int i = blockIdx.x * blockDim.x + threadIdx.x; i < total;
       i += gridDim.x * blockDim.x) {
    int cout = i % COUT;
    int cin  = (i / COUT) % CIN;
    int k    = i / (COUT * CIN);
    float v = W[((size_t)k * CIN + cin) * COUT + cout];
    __nv_bfloat16 h = __float2bfloat16(v);
    __nv_bfloat16 l = __float2bfloat16(v - __bfloat162float(h));
    int step = k * NC + (cin >> 6);
    uint32_t e = (uint32_t)cin & 63;
    uint32_t off = (uint32_t)cout * 128 + swz16(e >> 3, cout & 7) * 16 +
                   (e & 7) * 2;
    *(__nv_bfloat16*)(Bh + (size_t)step * TILEB + off) = h;
    *(__nv_bfloat16*)(Bl + (size_t)step * TILEB + off) = l;
  }
}

// ------------------------- warp-specialized mma.sync gathered conv -------------
// 384 threads: warps 0-7 = consumers (MMA), warps 8-11 = producers
// (gather + bn + bf16 split + STS + B cp.async). Double-buffered 64KB stages:
// buf b = [A-hi][A-lo][B-hi][B-lo], named-barrier full/free handoff.
template <int NC, bool BNIN>
__global__ __launch_bounds__(384, 1)
void mma_conv(const float* __restrict__ X, const int* __restrict__ nbr,
              const char* __restrict__ Bgh, const char* __restrict__ Bgl,
              const float* __restrict__ st, float* __restrict__ out, int n) {
  constexpr int CIN   = NC * 64;
  constexpr int STEPS = KTAPS * NC;
  extern __shared__ char dsm_raw[];
  char* dsm = (char*)(((uintptr_t)dsm_raw + 127) & ~(uintptr_t)127);
  __shared__ int   idx_s[128 * KTAPS];
  __shared__ float s_s[COUT], s_t[COUT];

  const int t = threadIdx.x, lane = t & 31, wid = t >> 5;
  const int n0 = blockIdx.x * 128;

  if (BNIN && t < COUT) { s_s[t] = st[t]; s_t[t] = st[COUT + t]; }
  for (int i = t; i < 128 * KTAPS; i += 384) {
    int row = n0 + i / KTAPS;
    idx_s[i] = (row < n) ? nbr[(size_t)row * KTAPS + (i % KTAPS)] : 0;
  }
  __syncthreads();

  const uint32_t Du = smem_u32(dsm);
  // barrier ids: FULL(b) = 1+b, FREE(b) = 3+b

  if (wid >= 8) {
    // ======================= producer =======================
    const int pr = t - 256;                 // 0..127, one row each
    const uint32_t r7x = (uint32_t)(pr & 7) * 16;
    for (int s = 0; s < STEPS; s++) {
      const int b = s & 1;
      if (s >= 2) BAR_SYNC(3 + b);
      // B tiles: pre-swizzled, async copy
      {
        const char* sh = Bgh + (size_t)s * TILEB;
        const char* sl = Bgl + (size_t)s * TILEB;
        uint32_t dh = Du + b * 65536 + 32768;
        uint32_t dl = dh + TILEB;
#pragma unroll
        for (int i = pr * 16; i < TILEB; i += 2048) {
          asm volatile("cp.async.cg.shared.global [%0], [%1], 16;"
                       :: "r"(dh + i), "l"(sh + i));
          asm volatile("cp.async.cg.shared.global [%0], [%1], 16;"
                       :: "r"(dl + i), "l"(sl + i));
        }
        asm volatile("cp.async.commit_group;" ::: "memory");
      }
      // A: gather one row (64-cin chunk) + bn(+relu) + hi/lo split + STS
      {
        int tap = s / NC, ch = s % NC;
        int src = idx_s[pr * KTAPS + tap];
        const float4* rp = (const float4*)(X + (size_t)src * CIN + ch * 64);
        char* hrow = dsm + b * 65536 + pr * 128;
        char* lrow = hrow + TILEB;
#pragma unroll
        for (int j = 0; j < 8; j++) {
          float4 a = rp[2 * j], c4 = rp[2 * j + 1];
          if (BNIN) {
            int ci = ch * 64 + j * 8;
            float4 s0 = *(const float4*)&s_s[ci], s1 = *(const float4*)&s_s[ci + 4];
            float4 t0 = *(const float4*)&s_t[ci], t1 = *(const float4*)&s_t[ci + 4];
            a.x = fmaxf(0.f, a.x * s0.x + t0.x);
            a.y = fmaxf(0.f, a.y * s0.y + t0.y);
            a.z = fmaxf(0.f, a.z * s0.z + t0.z);
            a.w = fmaxf(0.f, a.w * s0.w + t0.w);
            c4.x = fmaxf(0.f, c4.x * s1.x + t1.x);
            c4.y = fmaxf(0.f, c4.y * s1.y + t1.y);
            c4.z = fmaxf(0.f, c4.z * s1.z + t1.z);
            c4.w = fmaxf(0.f, c4.w * s1.w + t1.w);
          }
          __nv_bfloat162 h0 = __floats2bfloat162_rn(a.x, a.y);
          __nv_bfloat162 h1 = __floats2bfloat162_rn(a.z, a.w);
          __nv_bfloat162 h2 = __floats2bfloat162_rn(c4.x, c4.y);
          __nv_bfloat162 h3 = __floats2bfloat162_rn(c4.z, c4.w);
          __nv_bfloat162 l0 = __floats2bfloat162_rn(a.x - __bfloat162float(h0.x),
                                                    a.y - __bfloat162float(h0.y));
          __nv_bfloat162 l1 = __floats2bfloat162_rn(a.z - __bfloat162float(h1.x),
                                                    a.w - __bfloat162float(h1.y));
          __nv_bfloat162 l2 = __floats2bfloat162_rn(c4.x - __bfloat162float(h2.x),
                                                    c4.y - __bfloat162float(h2.y));
          __nv_bfloat162 l3 = __floats2bfloat162_rn(c4.z - __bfloat162float(h3.x),
                                                    c4.w - __bfloat162float(h3.y));
          uint32_t off = ((uint32_t)j * 16) ^ r7x;
          *(uint4*)(hrow + off) = make_uint4(
              *(uint32_t*)&h0, *(uint32_t*)&h1, *(uint32_t*)&h2, *(uint32_t*)&h3);
          *(uint4*)(lrow + off) = make_uint4(
              *(uint32_t*)&l0, *(uint32_t*)&l1, *(uint32_t*)&l2, *(uint32_t*)&l3);
        }
      }
      asm volatile("cp.async.wait_group 0;" ::: "memory");
      BAR_ARRIVE(1 + b);
    }
    return;   // producers done
  }

  // ======================= consumer =======================
  const int wm = wid & 3, wn = wid >> 2;
  const int aRowL = lane & 15, aKh = lane >> 4;
  const int bRowL = ((lane >> 4) << 3) | (lane & 7);
  const int bKh   = (lane >> 3) & 1;

  float acc[2][8][4];
#pragma unroll
  for (int m = 0; m < 2; m++)
#pragma unroll
    for (int f = 0; f < 8; f++)
#pragma unroll
      for (int q = 0; q < 4; q++) acc[m][f][q] = 0.f;

  for (int s = 0; s < STEPS; s++) {
    const int b = s & 1;
    BAR_SYNC(1 + b);
    const uint32_t AHu = Du + b * 65536, ALu = AHu + TILEB;
    const uint32_t BHu = AHu + 32768,    BLu = BHu + TILEB;
#pragma unroll
    for (int ks = 0; ks < 4; ks++) {
      uint32_t ah[2][4], al[2][4], bb[16];
      uint32_t cbase = 2 * ks;
#pragma unroll
      for (int mt = 0; mt < 2; mt++) {
        uint32_t row = wm * 32 + mt * 16 + aRowL;
        uint32_t off = row * 128 + swz16(cbase + aKh, row & 7) * 16;
        ldsm4(ah[mt], AHu + off);
        ldsm4(al[mt], ALu + off);
      }
#pragma unroll
      for (int i = 0; i < 4; i++) {
        uint32_t row = wn * 64 + i * 16 + bRowL;
        uint32_t off = row * 128 + swz16(cbase + bKh, row & 7) * 16;
        ldsm4(&bb[i * 4], BHu + off);
      }
#pragma unroll
      for (int mt = 0; mt < 2; mt++)
#pragma unroll
        for (int f = 0; f < 8; f++) {
          mma_bf16(acc[mt][f], ah[mt], &bb[f * 2]);
          mma_bf16(acc[mt][f], al[mt], &bb[f * 2]);
        }
#pragma unroll
      for (int i = 0; i < 4; i++) {
        uint32_t row = wn * 64 + i * 16 + bRowL;
        uint32_t off = row * 128 + swz16(cbase + bKh, row & 7) * 16;
        ldsm4(&bb[i * 4], BLu + off);
      }
#pragma unroll
      for (int mt = 0; mt < 2; mt++)
#pragma unroll
        for (int f = 0; f < 8; f++)
          mma_bf16(acc[mt][f], ah[mt], &bb[f * 2]);
    }
    BAR_ARRIVE(3 + b);
  }

  // ---- epilogue: fragment regs -> gmem ----
#pragma unroll
  for (int mt = 0; mt < 2; mt++)
#pragma unroll
    for (int f = 0; f < 8; f++) {
      int row = n0 + wm * 32 + mt * 16 + (lane >> 2);
      int col = wn * 64 + f * 8 + 2 * (lane & 3);
      if (row < n)
        *(float2*)&out[(size_t)row * COUT + col] =
            make_float2(acc[mt][f][0], acc[mt][f][1]);
      if (row + 8 < n)
        *(float2*)&out[(size_t)(row + 8) * COUT + col] =
            make_float2(acc[mt][f][2], acc[mt][f][3]);
    }
}

// ------------------------- downsample (1x1 conv, FFMA2) -------------------------
__global__ void pack_w(const float* __restrict__ W, float2* __restrict__ Wp,
                       int KT, int CIN) {
  int total = KT * (CIN / 2) * COUT;
  for (int i = blockIdx.x * blockDim.x + threadIdx.x; i < total;
       i += gridDim.x * blockDim.x) {
    int c  = i % COUT;
    int cp = (i / COUT) % (CIN / 2);
    int k  = i / (COUT * (CIN / 2));
    Wp[i] = make_float2(W[((size_t)k * CIN + 2 * cp) * COUT + c],
                        W[((size_t)k * CIN + 2 * cp + 1) * COUT + c]);
  }
}

__global__ __launch_bounds__(256, 2)
void dconv_kernel(const float* __restrict__ X, const float2* __restrict__ Wp,
                  float* __restrict__ out, int n) {
  constexpr int CIN = CIN1;
  constexpr int STRIDE = CIN + 8;
  __shared__ float xs[64 * STRIDE];
  const int t = threadIdx.x;
  const int n0 = blockIdx.x * 64;
  const int tcol = t & 31, trow = t >> 5;
  const int c0 = tcol * 4, p0 = trow * 8;
  const int r = t >> 2, seg = t & 3;
  {
    int src = n0 + r;
    if (src >= n) src = n - 1;
    const float4* rp = (const float4*)(X + (size_t)src * CIN);
#pragma unroll
    for (int j = 0; j < CIN / 16; j++)
      *(float4*)&xs[r * STRIDE + (seg + 4 * j) * 4] = rp[seg + 4 * j];
  }
  __syncthreads();
  unsigned long long acc[8][4];
#pragma unroll
  for (int p = 0; p < 8; p++)
#pragma unroll
    for (int i = 0; i < 4; i++) acc[p][i] = 0ull;
  const unsigned long long* wrow = (const unsigned long long*)Wp;
#pragma unroll 2
  for (int cp = 0; cp < CIN / 2; cp += 2) {
    const unsigned long long* wb0 = wrow + (size_t)cp * COUT + c0;
    const unsigned long long* wb1 = wrow + (size_t)(cp + 1) * COUT + c0;
    ulonglong2 wa = *(const ulonglong2*)wb0, wa2 = *(const ulonglong2*)(wb0 + 2);
    ulonglong2 wc = *(const ulonglong2*)wb1, wc2 = *(const ulonglong2*)(wb1 + 2);
#pragma unroll
    for (int p = 0; p < 8; p++) {
      ulonglong2 xv = *(const ulonglong2*)&xs[(p0 + p) * STRIDE + 2 * cp];
      acc[p][0] = fma2(xv.x, wa.x,  acc[p][0]);
      acc[p][1] = fma2(xv.x, wa.y,  acc[p][1]);
      acc[p][2] = fma2(xv.x, wa2.x, acc[p][2]);
      acc[p][3] = fma2(xv.x, wa2.y, acc[p][3]);
      acc[p][0] = fma2(xv.y, wc.x,  acc[p][0]);
      acc[p][1] = fma2(xv.y, wc.y,  acc[p][1]);
      acc[p][2] = fma2(xv.y, wc2.x, acc[p][2]);
      acc[p][3] = fma2(xv.y, wc2.y, acc[p][3]);
    }
  }
#pragma unroll
  for (int p = 0; p < 8; p++) {
    int np = n0 + p0 + p;
    if (np < n) {
      float2 a0 = *(float2*)&acc[p][0], a1 = *(float2*)&acc[p][1];
      float2 a2 = *(float2*)&acc[p][2], a3 = *(float2*)&acc[p][3];
      float4 o = make_float4(a0.x + a0.y, a1.x + a1.y, a2.x + a2.y, a3.x + a3.y);
      *(float4*)&out[(size_t)np * COUT + c0] = o;
    }
  }
}

// ------------------------- BN stats + epilogue -------------------------
__global__ void stats_partial(const float* __restrict__ h,
                              float* __restrict__ part, int n) {
  int c = threadIdx.x, b = blockIdx.x;
  float s = 0.f, q = 0.f;
  for (int r = b; r < n; r += 256) {
    float v = h[(size_t)r * COUT + c];
    s += v;
    q += v * v;
  }
  part[b * COUT + c] = s;
  part[256 * COUT + b * COUT + c] = q;
}

__global__ void stats_final(const float* __restrict__ part,
                            const float* __restrict__ g,
                            const float* __restrict__ bta,
                            float* __restrict__ st, int n) {
  int c = threadIdx.x;
  float s = 0.f, q = 0.f;
  for (int b = 0; b < 256; b++) {
    s += part[b * COUT + c];
    q += part[256 * COUT + b * COUT + c];
  }
  float mu  = s / (float)n;
  float var = q / (float)n - mu * mu;
  float sc  = g[c] * rsqrtf(var + 1e-5f);
  st[c]        = sc;
  st[COUT + c] = bta[c] - mu * sc;
}

__global__ void final_add(const float* __restrict__ h2,
                          const float* __restrict__ res,
                          const float* __restrict__ st2,
                          const float* __restrict__ std_,
                          float* __restrict__ out, int n) {
  int i = blockIdx.x * blockDim.x + threadIdx.x;
  int total = n * (COUT / 4);
  if (i < total) {
    int c0 = (i & (COUT / 4 - 1)) * 4;
    float4 h = ((const float4*)h2)[i];
    float4 r = ((const float4*)res)[i];
    float4 s2 = *(const float4*)&st2[c0];
    float4 t2 = *(const float4*)&st2[COUT + c0];
    float4 sd = *(const float4*)&std_[c0];
    float4 td = *(const float4*)&std_[COUT + c0];
    float4 o;
    o.x = fmaxf(0.f, h.x * s2.x + t2.x) + (r.x * sd.x + td.x);
    o.y = fmaxf(0.f, h.y * s2.y + t2.y) + (r.y * sd.y + td.y);
    o.z = fmaxf(0.f, h.z * s2.z + t2.z) + (r.z * sd.z + td.z);
    o.w = fmaxf(0.f, h.w * s2.w + t2.w) + (r.w * sd.w + td.w);
    ((float4*)out)[i] = o;
  }
}

extern "C" void kernel_launch(void* const* d_in, const int* in_sizes, int n_in,
                              void* d_out, int out_size) {
  const float* x   = (const float*)d_in[0];
  const int*   nbr = (const int*)d_in[1];   // JAX x64 disabled -> int32
  const float* W1  = (const float*)d_in[2];
  const float* g1  = (const float*)d_in[3];
  const float* b1  = (const float*)d_in[4];
  const float* W2  = (const float*)d_in[5];
  const float* g2  = (const float*)d_in[6];
  const float* b2  = (const float*)d_in[7];
  const float* Wd  = (const float*)d_in[8];
  const float* gd  = (const float*)d_in[9];
  const float* bd  = (const float*)d_in[10];
  float*       out = (float*)d_out;
  const int n = in_sizes[0] / CIN1;

  float *h1, *h2, *res, *part, *st;
  float2* Wdp;
  char *B1h, *B1l, *B2h, *B2l;
  cudaGetSymbolAddress((void**)&h1,  g_h1);
  cudaGetSymbolAddress((void**)&h2,  g_h2);
  cudaGetSymbolAddress((void**)&res, g_res);
  cudaGetSymbolAddress((void**)&B1h, g_B1h);
  cudaGetSymbolAddress((void**)&B1l, g_B1l);
  cudaGetSymbolAddress((void**)&B2h, g_B2h);
  cudaGetSymbolAddress((void**)&B2l, g_B2l);
  cudaGetSymbolAddress((void**)&Wdp, g_Wdp);
  cudaGetSymbolAddress((void**)&part, g_part);
  cudaGetSymbolAddress((void**)&st,  g_st);

  const int smem = 2 * 4 * TILEB + 256;   // 131328 B (two 64KB stages)
  cudaFuncSetAttribute(mma_conv<1, false>,
                       cudaFuncAttributeMaxDynamicSharedMemorySize, smem);
  cudaFuncSetAttribute(mma_conv<2, true>,
                       cudaFuncAttributeMaxDynamicSharedMemorySize, smem);

  pack_w_mma<<<432, 256>>>(W1, B1h, B1l, KTAPS, CIN1);
  pack_w_mma<<<864, 256>>>(W2, B2h, B2l, KTAPS, COUT);
  pack_w<<<16, 256>>>(Wd, Wdp, 1, CIN1);

  const int nbm = (n + 127) / 128;
  const int nb64 = (n + 63) / 64;

  // conv1 -> h1pre; bn1 stats
  mma_conv<1, false><<<nbm, 384, smem>>>(x, nbr, B1h, B1l, st, h1, n);
  stats_partial<<<256, 128>>>(h1, part, n);
  stats_final<<<1, 128>>>(part, g1, b1, st + 0, n);

  // downsample branch: respre = x @ Wd; bn_d stats
  dconv_kernel<<<nb64, 256>>>(x, Wdp, res, n);
  stats_partial<<<256, 128>>>(res, part, n);
  stats_final<<<1, 128>>>(part, gd, bd, st + 2 * COUT, n);

  // conv2 (bn1+relu fused into gather) -> h2pre; bn2 stats
  mma_conv<2, true><<<nbm, 384, smem>>>(h1, nbr, B2h, B2l, st + 0, h2, n);
  stats_partial<<<256, 128>>>(h2, part, n);
  stats_final<<<1, 128>>>(part, g2, b2, st + 4 * COUT, n);

  // out = relu(bn2(h2pre)) + bn_d(respre)
  const int tot4 = n * (COUT / 4);
  final_add<<<(tot4 + 255) / 256, 256>>>(h2, res, st + 4 * COUT, st + 2 * COUT,
                                         out, n);
}

// round 10
// speedup vs baseline: 3.7923x; 1.0800x over previous
#include <cuda_runtime.h>
#include <cuda_fp16.h>
#include <cstdint>

#define CIN1  64
#define COUT  128
#define KTAPS 27
#define NMAX  131072
#define TILEB 16384   // one [128 rows x 128B] tile
#define STAGEB 49152  // A-hi + A-lo + B per stage
#define NSTAGE 3

// ---- scratch (static device globals; no allocation in kernel_launch) ----
__device__ float g_h1[(size_t)NMAX * COUT];
__device__ float g_h2[(size_t)NMAX * COUT];
__device__ float g_res[(size_t)NMAX * COUT];
// pre-swizzled fp16 weight tiles: [step = tap*NC+chunk][128 rows][64 f16]
__device__ __align__(16) char g_B1[KTAPS * 1 * TILEB];
__device__ __align__(16) char g_B2[KTAPS * 2 * TILEB];
__device__ float2 g_Wdp[(CIN1 / 2) * COUT];
__device__ float  g_part[2 * 256 * COUT];
__device__ float  g_st[6 * COUT];   // [s1|t1|sd|td|s2|t2]

// ------------------------- helpers -------------------------
__device__ __forceinline__ uint32_t smem_u32(const void* p) {
  uint32_t a;
  asm("{ .reg .u64 t; cvta.to.shared.u64 t, %1; cvt.u32.u64 %0, t; }"
      : "=r"(a) : "l"(p));
  return a;
}
__device__ __forceinline__ unsigned long long fma2(unsigned long long a,
                                                   unsigned long long b,
                                                   unsigned long long c) {
  unsigned long long d;
  asm("fma.rn.f32x2 %0, %1, %2, %3;" : "=l"(d) : "l"(a), "l"(b), "l"(c));
  return d;
}
__device__ __forceinline__ void ldsm4(uint32_t* r, uint32_t addr) {
  asm volatile("ldmatrix.sync.aligned.m8n8.x4.shared.b16 {%0,%1,%2,%3}, [%4];"
               : "=r"(r[0]), "=r"(r[1]), "=r"(r[2]), "=r"(r[3]) : "r"(addr));
}
__device__ __forceinline__ void mma_f16(float* c, const uint32_t* a,
                                        const uint32_t* b) {
  asm volatile(
      "mma.sync.aligned.m16n8k16.row.col.f32.f16.f16.f32 "
      "{%0,%1,%2,%3}, {%4,%5,%6,%7}, {%8,%9}, {%0,%1,%2,%3};"
      : "+f"(c[0]), "+f"(c[1]), "+f"(c[2]), "+f"(c[3])
      : "r"(a[0]), "r"(a[1]), "r"(a[2]), "r"(a[3]), "r"(b[0]), "r"(b[1]));
}
// 16B-chunk XOR swizzle inside a 128B row
__device__ __host__ __forceinline__ uint32_t swz16(uint32_t c, uint32_t r7) {
  return (c & ~7u) | ((c ^ r7) & 7u);
}
#define BAR_SYNC(id)   asm volatile("bar.sync %0, 512;"   :: "r"(id) : "memory")
#define BAR_ARRIVE(id) asm volatile("bar.arrive %0, 512;" :: "r"(id) : "memory")

// ------------------------- weight packing -------------------------
// W [k][cin][cout] f32 -> per-step fp16 tile [cout row][cin-chunk 64 f16].
__global__ void pack_w_f16(const float* __restrict__ W, char* __restrict__ B,
                           int KT, int CIN) {
  int NC = CIN / 64;
  int total = KT * CIN * COUT;
  for (int i = blockIdx.x * blockDim.x + threadIdx.x; i < total;
       i += gridDim.x * blockDim.x) {
    int cout = i % COUT;
    int cin  = (i / COUT) % CIN;
    int k    = i / (COUT * CIN);
    float v = W[((size_t)k * CIN + cin) * COUT + cout];
    int step = k * NC + (cin >> 6);
    uint32_t e = (uint32_t)cin & 63;
    uint32_t off = (uint32_t)cout * 128 + swz16(e >> 3, cout & 7) * 16 +
                   (e & 7) * 2;
    *(__half*)(B + (size_t)step * TILEB + off) = __float2half_rn(v);
  }
}

// ------------------------- warp-specialized fp16 mma gathered conv -------------
// 512 threads: warps 0-7 = consumers (MMA), warps 8-15 = producers.
// acc += xh*w + xl*w  (x split into two fp16, w single fp16; err ~2^-13).
// 3-stage 48KB pipeline: stage = [A-hi 16K][A-lo 16K][B 16K].
template <int NC, bool BNIN>
__global__ __launch_bounds__(512, 1)
void mma_conv(const float* __restrict__ X, const int* __restrict__ nbr,
              const char* __restrict__ Bg,
              const float* __restrict__ st, float* __restrict__ out, int n) {
  constexpr int CIN   = NC * 64;
  constexpr int STEPS = KTAPS * NC;
  extern __shared__ char dsm_raw[];
  char* dsm = (char*)(((uintptr_t)dsm_raw + 127) & ~(uintptr_t)127);
  __shared__ int   idx_s[128 * KTAPS];
  __shared__ float s_s[COUT], s_t[COUT];

  const int t = threadIdx.x, lane = t & 31, wid = t >> 5;
  const int n0 = blockIdx.x * 128;

  if (BNIN && t < COUT) { s_s[t] = st[t]; s_t[t] = st[COUT + t]; }
  for (int i = t; i < 128 * KTAPS; i += 512) {
    int row = n0 + i / KTAPS;
    idx_s[i] = (row < n) ? nbr[(size_t)row * KTAPS + (i % KTAPS)] : 0;
  }
  __syncthreads();

  const uint32_t Du = smem_u32(dsm);
  // barrier ids: FULL(b) = 1+b, FREE(b) = 4+b

  if (wid >= 8) {
    // ======================= producer =======================
    const int pr  = t - 256;                 // 0..255
    const int row = pr >> 1, seg = pr & 1;   // 2 threads per row, 32 floats each
    const uint32_t r7x = (uint32_t)(row & 7) * 16;
    for (int s = 0; s < STEPS; s++) {
      const int b = s % NSTAGE;
      if (s >= NSTAGE) BAR_SYNC(4 + b);
      // B tile: pre-swizzled fp16, async copy (16KB / 256 threads)
      {
        const char* sb = Bg + (size_t)s * TILEB;
        uint32_t db = Du + b * STAGEB + 32768;
#pragma unroll
        for (int i = pr * 16; i < TILEB; i += 4096) {
          asm volatile("cp.async.cg.shared.global [%0], [%1], 16;"
                       :: "r"(db + i), "l"(sb + i));
        }
        asm volatile("cp.async.commit_group;" ::: "memory");
      }
      // A: gather half-row + bn(+relu) + fp16 hi/lo split + STS
      {
        int tap = s / NC, ch = s % NC;
        int src = idx_s[row * KTAPS + tap];
        const float4* rp =
            (const float4*)(X + (size_t)src * CIN + ch * 64 + seg * 32);
        char* hrow = dsm + b * STAGEB + row * 128;
        char* lrow = hrow + TILEB;
#pragma unroll
        for (int j = 0; j < 4; j++) {
          float4 a = rp[2 * j], c4 = rp[2 * j + 1];
          if (BNIN) {
            int ci = ch * 64 + seg * 32 + j * 8;
            float4 s0 = *(const float4*)&s_s[ci], s1 = *(const float4*)&s_s[ci + 4];
            float4 t0 = *(const float4*)&s_t[ci], t1 = *(const float4*)&s_t[ci + 4];
            a.x = fmaxf(0.f, a.x * s0.x + t0.x);
            a.y = fmaxf(0.f, a.y * s0.y + t0.y);
            a.z = fmaxf(0.f, a.z * s0.z + t0.z);
            a.w = fmaxf(0.f, a.w * s0.w + t0.w);
            c4.x = fmaxf(0.f, c4.x * s1.x + t1.x);
            c4.y = fmaxf(0.f, c4.y * s1.y + t1.y);
            c4.z = fmaxf(0.f, c4.z * s1.z + t1.z);
            c4.w = fmaxf(0.f, c4.w * s1.w + t1.w);
          }
          __half hx = __float2half_rn(a.x),  hy = __float2half_rn(a.y);
          __half hz = __float2half_rn(a.z),  hw = __float2half_rn(a.w);
          __half gx = __float2half_rn(c4.x), gy = __float2half_rn(c4.y);
          __half gz = __float2half_rn(c4.z), gw = __float2half_rn(c4.w);
          __half2 h0 = __halves2half2(hx, hy), h1 = __halves2half2(hz, hw);
          __half2 h2 = __halves2half2(gx, gy), h3 = __halves2half2(gz, gw);
          __half2 l0 = __floats2half2_rn(a.x - __half2float(hx),
                                         a.y - __half2float(hy));
          __half2 l1 = __floats2half2_rn(a.z - __half2float(hz),
                                         a.w - __half2float(hw));
          __half2 l2 = __floats2half2_rn(c4.x - __half2float(gx),
                                         c4.y - __half2float(gy));
          __half2 l3 = __floats2half2_rn(c4.z - __half2float(gz),
                                         c4.w - __half2float(gw));
          uint32_t off = (((uint32_t)(seg * 4 + j)) * 16) ^ r7x;
          *(uint4*)(hrow + off) = make_uint4(
              *(uint32_t*)&h0, *(uint32_t*)&h1, *(uint32_t*)&h2, *(uint32_t*)&h3);
          *(uint4*)(lrow + off) = make_uint4(
              *(uint32_t*)&l0, *(uint32_t*)&l1, *(uint32_t*)&l2, *(uint32_t*)&l3);
        }
      }
      asm volatile("cp.async.wait_group 0;" ::: "memory");
      BAR_ARRIVE(1 + b);
    }
    return;   // producers done
  }

  // ======================= consumer =======================
  const int wm = wid & 3, wn = wid >> 2;
  const int aRowL = lane & 15, aKh = lane >> 4;
  const int bRowL = ((lane >> 4) << 3) | (lane & 7);
  const int bKh   = (lane >> 3) & 1;

  float acc[2][8][4];
#pragma unroll
  for (int m = 0; m < 2; m++)
#pragma unroll
    for (int f = 0; f < 8; f++)
#pragma unroll
      for (int q = 0; q < 4; q++) acc[m][f][q] = 0.f;

  for (int s = 0; s < STEPS; s++) {
    const int b = s % NSTAGE;
    BAR_SYNC(1 + b);
    const uint32_t AHu = Du + b * STAGEB, ALu = AHu + TILEB, Bu = AHu + 32768;
#pragma unroll
    for (int ks = 0; ks < 4; ks++) {
      uint32_t ah[2][4], al[2][4], bb[16];
      uint32_t cbase = 2 * ks;
#pragma unroll
      for (int mt = 0; mt < 2; mt++) {
        uint32_t row = wm * 32 + mt * 16 + aRowL;
        uint32_t off = row * 128 + swz16(cbase + aKh, row & 7) * 16;
        ldsm4(ah[mt], AHu + off);
        ldsm4(al[mt], ALu + off);
      }
#pragma unroll
      for (int i = 0; i < 4; i++) {
        uint32_t row = wn * 64 + i * 16 + bRowL;
        uint32_t off = row * 128 + swz16(cbase + bKh, row & 7) * 16;
        ldsm4(&bb[i * 4], Bu + off);
      }
#pragma unroll
      for (int mt = 0; mt < 2; mt++)
#pragma unroll
        for (int f = 0; f < 8; f++) {
          mma_f16(acc[mt][f], ah[mt], &bb[f * 2]);
          mma_f16(acc[mt][f], al[mt], &bb[f * 2]);
        }
    }
    BAR_ARRIVE(4 + b);
  }

  // ---- epilogue: fragment regs -> gmem ----
#pragma unroll
  for (int mt = 0; mt < 2; mt++)
#pragma unroll
    for (int f = 0; f < 8; f++) {
      int row = n0 + wm * 32 + mt * 16 + (lane >> 2);
      int col = wn * 64 + f * 8 + 2 * (lane & 3);
      if (row < n)
        *(float2*)&out[(size_t)row * COUT + col] =
            make_float2(acc[mt][f][0], acc[mt][f][1]);
      if (row + 8 < n)
        *(float2*)&out[(size_t)(row + 8) * COUT + col] =
            make_float2(acc[mt][f][2], acc[mt][f][3]);
    }
}

// ------------------------- downsample (1x1 conv, FFMA2) -------------------------
__global__ void pack_w(const float* __restrict__ W, float2* __restrict__ Wp,
                       int KT, int CIN) {
  int total = KT * (CIN / 2) * COUT;
  for (int i = blockIdx.x * blockDim.x + threadIdx.x; i < total;
       i += gridDim.x * blockDim.x) {
    int c  = i % COUT;
    int cp = (i / COUT) % (CIN / 2);
    int k  = i / (COUT * (CIN / 2));
    Wp[i] = make_float2(W[((size_t)k * CIN + 2 * cp) * COUT + c],
                        W[((size_t)k * CIN + 2 * cp + 1) * COUT + c]);
  }
}

__global__ __launch_bounds__(256, 2)
void dconv_kernel(const float* __restrict__ X, const float2* __restrict__ Wp,
                  float* __restrict__ out, int n) {
  constexpr int CIN = CIN1;
  constexpr int STRIDE = CIN + 8;
  __shared__ float xs[64 * STRIDE];
  const int t = threadIdx.x;
  const int n0 = blockIdx.x * 64;
  const int tcol = t & 31, trow = t >> 5;
  const int c0 = tcol * 4, p0 = trow * 8;
  const int r = t >> 2, seg = t & 3;
  {
    int src = n0 + r;
    if (src >= n) src = n - 1;
    const float4* rp = (const float4*)(X + (size_t)src * CIN);
#pragma unroll
    for (int j = 0; j < CIN / 16; j++)
      *(float4*)&xs[r * STRIDE + (seg + 4 * j) * 4] = rp[seg + 4 * j];
  }
  __syncthreads();
  unsigned long long acc[8][4];
#pragma unroll
  for (int p = 0; p < 8; p++)
#pragma unroll
    for (int i = 0; i < 4; i++) acc[p][i] = 0ull;
  const unsigned long long* wrow = (const unsigned long long*)Wp;
#pragma unroll 2
  for (int cp = 0; cp < CIN / 2; cp += 2) {
    const unsigned long long* wb0 = wrow + (size_t)cp * COUT + c0;
    const unsigned long long* wb1 = wrow + (size_t)(cp + 1) * COUT + c0;
    ulonglong2 wa = *(const ulonglong2*)wb0, wa2 = *(const ulonglong2*)(wb0 + 2);
    ulonglong2 wc = *(const ulonglong2*)wb1, wc2 = *(const ulonglong2*)(wb1 + 2);
#pragma unroll
    for (int p = 0; p < 8; p++) {
      ulonglong2 xv = *(const ulonglong2*)&xs[(p0 + p) * STRIDE + 2 * cp];
      acc[p][0] = fma2(xv.x, wa.x,  acc[p][0]);
      acc[p][1] = fma2(xv.x, wa.y,  acc[p][1]);
      acc[p][2] = fma2(xv.x, wa2.x, acc[p][2]);
      acc[p][3] = fma2(xv.x, wa2.y, acc[p][3]);
      acc[p][0] = fma2(xv.y, wc.x,  acc[p][0]);
      acc[p][1] = fma2(xv.y, wc.y,  acc[p][1]);
      acc[p][2] = fma2(xv.y, wc2.x, acc[p][2]);
      acc[p][3] = fma2(xv.y, wc2.y, acc[p][3]);
    }
  }
#pragma unroll
  for (int p = 0; p < 8; p++) {
    int np = n0 + p0 + p;
    if (np < n) {
      float2 a0 = *(float2*)&acc[p][0], a1 = *(float2*)&acc[p][1];
      float2 a2 = *(float2*)&acc[p][2], a3 = *(float2*)&acc[p][3];
      float4 o = make_float4(a0.x + a0.y, a1.x + a1.y, a2.x + a2.y, a3.x + a3.y);
      *(float4*)&out[(size_t)np * COUT + c0] = o;
    }
  }
}

// ------------------------- BN stats + epilogue -------------------------
__global__ void stats_partial(const float* __restrict__ h,
                              float* __restrict__ part, int n) {
  int c = threadIdx.x, b = blockIdx.x;
  float s = 0.f, q = 0.f;
  for (int r = b; r < n; r += 256) {
    float v = h[(size_t)r * COUT + c];
    s += v;
    q += v * v;
  }
  part[b * COUT + c] = s;
  part[256 * COUT + b * COUT + c] = q;
}

__global__ void stats_final(const float* __restrict__ part,
                            const float* __restrict__ g,
                            const float* __restrict__ bta,
                            float* __restrict__ st, int n) {
  int c = threadIdx.x;
  float s = 0.f, q = 0.f;
  for (int b = 0; b < 256; b++) {
    s += part[b * COUT + c];
    q += part[256 * COUT + b * COUT + c];
  }
  float mu  = s / (float)n;
  float var = q / (float)n - mu * mu;
  float sc  = g[c] * rsqrtf(var + 1e-5f);
  st[c]        = sc;
  st[COUT + c] = bta[c] - mu * sc;
}

__global__ void final_add(const float* __restrict__ h2,
                          const float* __restrict__ res,
                          const float* __restrict__ st2,
                          const float* __restrict__ std_,
                          float* __restrict__ out, int n) {
  int i = blockIdx.x * blockDim.x + threadIdx.x;
  int total = n * (COUT / 4);
  if (i < total) {
    int c0 = (i & (COUT / 4 - 1)) * 4;
    float4 h = ((const float4*)h2)[i];
    float4 r = ((const float4*)res)[i];
    float4 s2 = *(const float4*)&st2[c0];
    float4 t2 = *(const float4*)&st2[COUT + c0];
    float4 sd = *(const float4*)&std_[c0];
    float4 td = *(const float4*)&std_[COUT + c0];
    float4 o;
    o.x = fmaxf(0.f, h.x * s2.x + t2.x) + (r.x * sd.x + td.x);
    o.y = fmaxf(0.f, h.y * s2.y + t2.y) + (r.y * sd.y + td.y);
    o.z = fmaxf(0.f, h.z * s2.z + t2.z) + (r.z * sd.z + td.z);
    o.w = fmaxf(0.f, h.w * s2.w + t2.w) + (r.w * sd.w + td.w);
    ((float4*)out)[i] = o;
  }
}

extern "C" void kernel_launch(void* const* d_in, const int* in_sizes, int n_in,
                              void* d_out, int out_size) {
  const float* x   = (const float*)d_in[0];
  const int*   nbr = (const int*)d_in[1];   // JAX x64 disabled -> int32
  const float* W1  = (const float*)d_in[2];
  const float* g1  = (const float*)d_in[3];
  const float* b1  = (const float*)d_in[4];
  const float* W2  = (const float*)d_in[5];
  const float* g2  = (const float*)d_in[6];
  const float* b2  = (const float*)d_in[7];
  const float* Wd  = (const float*)d_in[8];
  const float* gd  = (const float*)d_in[9];
  const float* bd  = (const float*)d_in[10];
  float*       out = (float*)d_out;
  const int n = in_sizes[0] / CIN1;

  float *h1, *h2, *res, *part, *st;
  float2* Wdp;
  char *B1, *B2;
  cudaGetSymbolAddress((void**)&h1,  g_h1);
  cudaGetSymbolAddress((void**)&h2,  g_h2);
  cudaGetSymbolAddress((void**)&res, g_res);
  cudaGetSymbolAddress((void**)&B1,  g_B1);
  cudaGetSymbolAddress((void**)&B2,  g_B2);
  cudaGetSymbolAddress((void**)&Wdp, g_Wdp);
  cudaGetSymbolAddress((void**)&part, g_part);
  cudaGetSymbolAddress((void**)&st,  g_st);

  const int smem = NSTAGE * STAGEB + 256;   // 147712 B
  cudaFuncSetAttribute(mma_conv<1, false>,
                       cudaFuncAttributeMaxDynamicSharedMemorySize, smem);
  cudaFuncSetAttribute(mma_conv<2, true>,
                       cudaFuncAttributeMaxDynamicSharedMemorySize, smem);

  pack_w_f16<<<432, 256>>>(W1, B1, KTAPS, CIN1);
  pack_w_f16<<<864, 256>>>(W2, B2, KTAPS, COUT);
  pack_w<<<16, 256>>>(Wd, Wdp, 1, CIN1);

  const int nbm = (n + 127) / 128;
  const int nb64 = (n + 63) / 64;

  // conv1 -> h1pre; bn1 stats
  mma_conv<1, false><<<nbm, 512, smem>>>(x, nbr, B1, st, h1, n);
  stats_partial<<<256, 128>>>(h1, part, n);
  stats_final<<<1, 128>>>(part, g1, b1, st + 0, n);

  // downsample branch: respre = x @ Wd; bn_d stats
  dconv_kernel<<<nb64, 256>>>(x, Wdp, res, n);
  stats_partial<<<256, 128>>>(res, part, n);
  stats_final<<<1, 128>>>(part, gd, bd, st + 2 * COUT, n);

  // conv2 (bn1+relu fused into gather) -> h2pre; bn2 stats
  mma_conv<2, true><<<nbm, 512, smem>>>(h1, nbr, B2, st + 0, h2, n);
  stats_partial<<<256, 128>>>(h2, part, n);
  stats_final<<<1, 128>>>(part, g2, b2, st + 4 * COUT, n);

  // out = relu(bn2(h2pre)) + bn_d(respre)
  const int tot4 = n * (COUT / 4);
  final_add<<<(tot4 + 255) / 256, 256>>>(h2, res, st + 4 * COUT, st + 2 * COUT,
                                         out, n);
}

// round 11
// speedup vs baseline: 3.8046x; 1.0032x over previous
#include <cuda_runtime.h>
#include <cuda_fp16.h>
#include <cstdint>

#define CIN1  64
#define COUT  128
#define KTAPS 27
#define NMAX  131072
#define TILEB 16384   // one [128 rows x 128B] tile
#define STAGEB 49152  // A-hi + A-lo + B per stage
#define NSTAGE 3

// ---- scratch (static device globals; no allocation in kernel_launch) ----
__device__ float g_h1[(size_t)NMAX * COUT];
__device__ float g_h2[(size_t)NMAX * COUT];
__device__ float g_res[(size_t)NMAX * COUT];
__device__ __half g_X1h[(size_t)NMAX * CIN1];
__device__ __half g_X1l[(size_t)NMAX * CIN1];
__device__ __half g_X2h[(size_t)NMAX * COUT];
__device__ __half g_X2l[(size_t)NMAX * COUT];
// pre-swizzled fp16 weight tiles: [step = tap*NC+chunk][128 rows][64 f16]
__device__ __align__(16) char g_B1[KTAPS * 1 * TILEB];
__device__ __align__(16) char g_B2[KTAPS * 2 * TILEB];
__device__ float2 g_Wdp[(CIN1 / 2) * COUT];
__device__ float  g_part[1024 * 256];   // conv block partials / res 2-stage
__device__ float  g_st[6 * COUT];       // [s1|t1|sd|td|s2|t2]

// ------------------------- helpers -------------------------
__device__ __forceinline__ uint32_t smem_u32(const void* p) {
  uint32_t a;
  asm("{ .reg .u64 t; cvta.to.shared.u64 t, %1; cvt.u32.u64 %0, t; }"
      : "=r"(a) : "l"(p));
  return a;
}
__device__ __forceinline__ unsigned long long fma2(unsigned long long a,
                                                   unsigned long long b,
                                                   unsigned long long c) {
  unsigned long long d;
  asm("fma.rn.f32x2 %0, %1, %2, %3;" : "=l"(d) : "l"(a), "l"(b), "l"(c));
  return d;
}
__device__ __forceinline__ void ldsm4(uint32_t* r, uint32_t addr) {
  asm volatile("ldmatrix.sync.aligned.m8n8.x4.shared.b16 {%0,%1,%2,%3}, [%4];"
               : "=r"(r[0]), "=r"(r[1]), "=r"(r[2]), "=r"(r[3]) : "r"(addr));
}
__device__ __forceinline__ void mma_f16(float* c, const uint32_t* a,
                                        const uint32_t* b) {
  asm volatile(
      "mma.sync.aligned.m16n8k16.row.col.f32.f16.f16.f32 "
      "{%0,%1,%2,%3}, {%4,%5,%6,%7}, {%8,%9}, {%0,%1,%2,%3};"
      : "+f"(c[0]), "+f"(c[1]), "+f"(c[2]), "+f"(c[3])
      : "r"(a[0]), "r"(a[1]), "r"(a[2]), "r"(a[3]), "r"(b[0]), "r"(b[1]));
}
// 16B-chunk XOR swizzle inside a 128B row
__device__ __host__ __forceinline__ uint32_t swz16(uint32_t c, uint32_t r7) {
  return (c & ~7u) | ((c ^ r7) & 7u);
}
#define BAR_SYNC(id)   asm volatile("bar.sync %0, 384;"   :: "r"(id) : "memory")
#define BAR_ARRIVE(id) asm volatile("bar.arrive %0, 384;" :: "r"(id) : "memory")
#define CP16(dst, src) \
  asm volatile("cp.async.cg.shared.global [%0], [%1], 16;" \
               :: "r"(dst), "l"(src))

// ------------------------- weight packing -------------------------
__global__ void pack_w_f16(const float* __restrict__ W, char* __restrict__ B,
                           int KT, int CIN) {
  int NC = CIN / 64;
  int total = KT * CIN * COUT;
  for (int i = blockIdx.x * blockDim.x + threadIdx.x; i < total;
       i += gridDim.x * blockDim.x) {
    int cout = i % COUT;
    int cin  = (i / COUT) % CIN;
    int k    = i / (COUT * CIN);
    float v = W[((size_t)k * CIN + cin) * COUT + cout];
    int step = k * NC + (cin >> 6);
    uint32_t e = (uint32_t)cin & 63;
    uint32_t off = (uint32_t)cout * 128 + swz16(e >> 3, cout & 7) * 16 +
                   (e & 7) * 2;
    *(__half*)(B + (size_t)step * TILEB + off) = __float2half_rn(v);
  }
}

// ------------------------- fp16 hi/lo split passes -------------------------
// x fp32 -> Xh + Xl fp16 (value = hi + lo to ~2^-24)
__global__ void split_plain(const float* __restrict__ X, __half* __restrict__ Xh,
                            __half* __restrict__ Xl, int total4) {
  int i = blockIdx.x * blockDim.x + threadIdx.x;
  if (i < total4) {
    float4 v = ((const float4*)X)[i];
    __half hx = __float2half_rn(v.x), hy = __float2half_rn(v.y);
    __half hz = __float2half_rn(v.z), hw = __float2half_rn(v.w);
    __half2 h0 = __halves2half2(hx, hy), h1 = __halves2half2(hz, hw);
    __half2 l0 = __floats2half2_rn(v.x - __half2float(hx), v.y - __half2float(hy));
    __half2 l1 = __floats2half2_rn(v.z - __half2float(hz), v.w - __half2float(hw));
    ((uint2*)Xh)[i] = make_uint2(*(uint32_t*)&h0, *(uint32_t*)&h1);
    ((uint2*)Xl)[i] = make_uint2(*(uint32_t*)&l0, *(uint32_t*)&l1);
  }
}

// h1 fp32 -> relu(bn1(h1)) -> Xh + Xl fp16
__global__ void split_bn(const float* __restrict__ H, const float* __restrict__ st,
                         __half* __restrict__ Xh, __half* __restrict__ Xl,
                         int total4) {
  int i = blockIdx.x * blockDim.x + threadIdx.x;
  if (i < total4) {
    int c0 = (i & 31) * 4;   // channel of first element (COUT=128)
    float4 v = ((const float4*)H)[i];
    float4 sc = *(const float4*)&st[c0];
    float4 tb = *(const float4*)&st[COUT + c0];
    v.x = fmaxf(0.f, v.x * sc.x + tb.x);
    v.y = fmaxf(0.f, v.y * sc.y + tb.y);
    v.z = fmaxf(0.f, v.z * sc.z + tb.z);
    v.w = fmaxf(0.f, v.w * sc.w + tb.w);
    __half hx = __float2half_rn(v.x), hy = __float2half_rn(v.y);
    __half hz = __float2half_rn(v.z), hw = __float2half_rn(v.w);
    __half2 h0 = __halves2half2(hx, hy), h1 = __halves2half2(hz, hw);
    __half2 l0 = __floats2half2_rn(v.x - __half2float(hx), v.y - __half2float(hy));
    __half2 l1 = __floats2half2_rn(v.z - __half2float(hz), v.w - __half2float(hw));
    ((uint2*)Xh)[i] = make_uint2(*(uint32_t*)&h0, *(uint32_t*)&h1);
    ((uint2*)Xl)[i] = make_uint2(*(uint32_t*)&l0, *(uint32_t*)&l1);
  }
}

// ------------------------- warp-specialized fp16 mma gathered conv -------------
// 384 threads: warps 0-7 = consumers (MMA + fused BN-stat partials),
// warps 8-11 = producers (pure cp.async from pre-split fp16 inputs).
// acc += xh*w + xl*w. 3-stage 48KB pipeline: [A-hi 16K][A-lo 16K][B 16K].
template <int NC>
__global__ __launch_bounds__(384, 1)
void mma_conv(const __half* __restrict__ Xh, const __half* __restrict__ Xl,
              const int* __restrict__ nbr, const char* __restrict__ Bg,
              float* __restrict__ out, float* __restrict__ part, int n) {
  constexpr int CIN   = NC * 64;
  constexpr int STEPS = KTAPS * NC;
  extern __shared__ char dsm_raw[];
  char* dsm = (char*)(((uintptr_t)dsm_raw + 127) & ~(uintptr_t)127);
  __shared__ int idx_s[128 * KTAPS];

  const int t = threadIdx.x, lane = t & 31, wid = t >> 5;
  const int n0 = blockIdx.x * 128;

  for (int i = t; i < 128 * KTAPS; i += 384) {
    int row = n0 + i / KTAPS;
    idx_s[i] = (row < n) ? nbr[(size_t)row * KTAPS + (i % KTAPS)] : 0;
  }
  __syncthreads();

  const uint32_t Du = smem_u32(dsm);
  // barrier ids: FULL(b) = 1+b, FREE(b) = 4+b, epilogue = 7

  if (wid >= 8) {
    // ======================= producer: pure cp.async =======================
    const int row = t - 256;                 // 0..127, one row each
    const uint32_t r7 = (uint32_t)(row & 7);
    for (int s = 0; s < STEPS; s++) {
      const int b = s % NSTAGE;
      if (s >= NSTAGE) BAR_SYNC(4 + b);
      int tap = s / NC, ch = s % NC;
      int src = idx_s[row * KTAPS + tap];
      const char* sh = (const char*)(Xh + (size_t)src * CIN + ch * 64);
      const char* sl = (const char*)(Xl + (size_t)src * CIN + ch * 64);
      const char* sb = Bg + (size_t)s * TILEB + row * 128;
      uint32_t dh = Du + b * STAGEB + row * 128;
      uint32_t dl = dh + TILEB;
      uint32_t db = Du + b * STAGEB + 32768 + row * 128;
#pragma unroll
      for (uint32_t d = 0; d < 8; d++) {
        uint32_t scn = d ^ r7;               // source chunk for dst chunk d
        CP16(dh + d * 16, sh + scn * 16);
        CP16(dl + d * 16, sl + scn * 16);
        CP16(db + d * 16, sb + d * 16);      // B pre-swizzled: verbatim
      }
      asm volatile("cp.async.commit_group;" ::: "memory");
      asm volatile("cp.async.wait_group 0;" ::: "memory");
      BAR_ARRIVE(1 + b);
    }
    return;   // producers done
  }

  // ======================= consumer =======================
  const int wm = wid & 3, wn = wid >> 2;
  const int aRowL = lane & 15, aKh = lane >> 4;
  const int bRowL = ((lane >> 4) << 3) | (lane & 7);
  const int bKh   = (lane >> 3) & 1;

  float acc[2][8][4];
#pragma unroll
  for (int m = 0; m < 2; m++)
#pragma unroll
    for (int f = 0; f < 8; f++)
#pragma unroll
      for (int q = 0; q < 4; q++) acc[m][f][q] = 0.f;

  for (int s = 0; s < STEPS; s++) {
    const int b = s % NSTAGE;
    BAR_SYNC(1 + b);
    const uint32_t AHu = Du + b * STAGEB, ALu = AHu + TILEB, Bu = AHu + 32768;
#pragma unroll
    for (int ks = 0; ks < 4; ks++) {
      uint32_t ah[2][4], al[2][4], bb[16];
      uint32_t cbase = 2 * ks;
#pragma unroll
      for (int mt = 0; mt < 2; mt++) {
        uint32_t row = wm * 32 + mt * 16 + aRowL;
        uint32_t off = row * 128 + swz16(cbase + aKh, row & 7) * 16;
        ldsm4(ah[mt], AHu + off);
        ldsm4(al[mt], ALu + off);
      }
#pragma unroll
      for (int i = 0; i < 4; i++) {
        uint32_t row = wn * 64 + i * 16 + bRowL;
        uint32_t off = row * 128 + swz16(cbase + bKh, row & 7) * 16;
        ldsm4(&bb[i * 4], Bu + off);
      }
#pragma unroll
      for (int mt = 0; mt < 2; mt++)
#pragma unroll
        for (int f = 0; f < 8; f++) {
          mma_f16(acc[mt][f], ah[mt], &bb[f * 2]);
          mma_f16(acc[mt][f], al[mt], &bb[f * 2]);
        }
    }
    BAR_ARRIVE(4 + b);
  }

  // ---- epilogue 1: fragment regs -> gmem ----
#pragma unroll
  for (int mt = 0; mt < 2; mt++)
#pragma unroll
    for (int f = 0; f < 8; f++) {
      int row = n0 + wm * 32 + mt * 16 + (lane >> 2);
      int col = wn * 64 + f * 8 + 2 * (lane & 3);
      if (row < n)
        *(float2*)&out[(size_t)row * COUT + col] =
            make_float2(acc[mt][f][0], acc[mt][f][1]);
      if (row + 8 < n)
        *(float2*)&out[(size_t)(row + 8) * COUT + col] =
            make_float2(acc[mt][f][2], acc[mt][f][3]);
    }

  // ---- epilogue 2: fused BN-stat partials (masked, deterministic) ----
  {
    int r0 = n0 + wm * 32 + (lane >> 2);
    bool vA0 = r0 < n, vA1 = r0 + 8 < n;        // mt = 0
    bool vB0 = r0 + 16 < n, vB1 = r0 + 24 < n;  // mt = 1
    float sums[8][2], sqs[8][2];
#pragma unroll
    for (int f = 0; f < 8; f++)
#pragma unroll
      for (int e = 0; e < 2; e++) {
        float a0 = vA0 ? acc[0][f][e] : 0.f;
        float a1 = vA1 ? acc[0][f][e + 2] : 0.f;
        float b0 = vB0 ? acc[1][f][e] : 0.f;
        float b1 = vB1 ? acc[1][f][e + 2] : 0.f;
        sums[f][e] = a0 + a1 + b0 + b1;
        sqs[f][e]  = a0 * a0 + a1 * a1 + b0 * b0 + b1 * b1;
      }
#pragma unroll
    for (int off = 4; off < 32; off <<= 1)
#pragma unroll
      for (int f = 0; f < 8; f++)
#pragma unroll
        for (int e = 0; e < 2; e++) {
          sums[f][e] += __shfl_down_sync(0xffffffffu, sums[f][e], off);
          sqs[f][e]  += __shfl_down_sync(0xffffffffu, sqs[f][e],  off);
        }
    float* S = (float*)dsm;          // [4][128]
    float* Q = S + 512;              // [4][128]
    if (lane < 4) {
#pragma unroll
      for (int f = 0; f < 8; f++)
#pragma unroll
        for (int e = 0; e < 2; e++) {
          int col = wn * 64 + f * 8 + 2 * lane + e;
          S[wm * 128 + col] = sums[f][e];
          Q[wm * 128 + col] = sqs[f][e];
        }
    }
    asm volatile("bar.sync 7, 256;" ::: "memory");
    if (t < 128) {
      float s = S[t] + S[128 + t] + S[256 + t] + S[384 + t];
      float q = Q[t] + Q[128 + t] + Q[256 + t] + Q[384 + t];
      part[(size_t)blockIdx.x * 256 + t] = s;
      part[(size_t)blockIdx.x * 256 + 128 + t] = q;
    }
  }
}

// single-block finalize over conv block partials (deterministic)
__global__ void stats_final_conv(const float* __restrict__ part, int nb,
                                 const float* __restrict__ g,
                                 const float* __restrict__ bta,
                                 float* __restrict__ st, int n) {
  int c = threadIdx.x;   // 128
  float s = 0.f, q = 0.f;
  for (int b = 0; b < nb; b++) {
    s += part[(size_t)b * 256 + c];
    q += part[(size_t)b * 256 + 128 + c];
  }
  float mu  = s / (float)n;
  float var = q / (float)n - mu * mu;
  float sc  = g[c] * rsqrtf(var + 1e-5f);
  st[c]        = sc;
  st[COUT + c] = bta[c] - mu * sc;
}

// ------------------------- downsample (1x1 conv, FFMA2) -------------------------
__global__ void pack_w(const float* __restrict__ W, float2* __restrict__ Wp,
                       int KT, int CIN) {
  int total = KT * (CIN / 2) * COUT;
  for (int i = blockIdx.x * blockDim.x + threadIdx.x; i < total;
       i += gridDim.x * blockDim.x) {
    int c  = i % COUT;
    int cp = (i / COUT) % (CIN / 2);
    int k  = i / (COUT * (CIN / 2));
    Wp[i] = make_float2(W[((size_t)k * CIN + 2 * cp) * COUT + c],
                        W[((size_t)k * CIN + 2 * cp + 1) * COUT + c]);
  }
}

__global__ __launch_bounds__(256, 2)
void dconv_kernel(const float* __restrict__ X, const float2* __restrict__ Wp,
                  float* __restrict__ out, int n) {
  constexpr int CIN = CIN1;
  constexpr int STRIDE = CIN + 8;
  __shared__ float xs[64 * STRIDE];
  const int t = threadIdx.x;
  const int n0 = blockIdx.x * 64;
  const int tcol = t & 31, trow = t >> 5;
  const int c0 = tcol * 4, p0 = trow * 8;
  const int r = t >> 2, seg = t & 3;
  {
    int src = n0 + r;
    if (src >= n) src = n - 1;
    const float4* rp = (const float4*)(X + (size_t)src * CIN);
#pragma unroll
    for (int j = 0; j < CIN / 16; j++)
      *(float4*)&xs[r * STRIDE + (seg + 4 * j) * 4] = rp[seg + 4 * j];
  }
  __syncthreads();
  unsigned long long acc[8][4];
#pragma unroll
  for (int p = 0; p < 8; p++)
#pragma unroll
    for (int i = 0; i < 4; i++) acc[p][i] = 0ull;
  const unsigned long long* wrow = (const unsigned long long*)Wp;
#pragma unroll 2
  for (int cp = 0; cp < CIN / 2; cp += 2) {
    const unsigned long long* wb0 = wrow + (size_t)cp * COUT + c0;
    const unsigned long long* wb1 = wrow + (size_t)(cp + 1) * COUT + c0;
    ulonglong2 wa = *(const ulonglong2*)wb0, wa2 = *(const ulonglong2*)(wb0 + 2);
    ulonglong2 wc = *(const ulonglong2*)wb1, wc2 = *(const ulonglong2*)(wb1 + 2);
#pragma unroll
    for (int p = 0; p < 8; p++) {
      ulonglong2 xv = *(const ulonglong2*)&xs[(p0 + p) * STRIDE + 2 * cp];
      acc[p][0] = fma2(xv.x, wa.x,  acc[p][0]);
      acc[p][1] = fma2(xv.x, wa.y,  acc[p][1]);
      acc[p][2] = fma2(xv.x, wa2.x, acc[p][2]);
      acc[p][3] = fma2(xv.x, wa2.y, acc[p][3]);
      acc[p][0] = fma2(xv.y, wc.x,  acc[p][0]);
      acc[p][1] = fma2(xv.y, wc.y,  acc[p][1]);
      acc[p][2] = fma2(xv.y, wc2.x, acc[p][2]);
      acc[p][3] = fma2(xv.y, wc2.y, acc[p][3]);
    }
  }
#pragma unroll
  for (int p = 0; p < 8; p++) {
    int np = n0 + p0 + p;
    if (np < n) {
      float2 a0 = *(float2*)&acc[p][0], a1 = *(float2*)&acc[p][1];
      float2 a2 = *(float2*)&acc[p][2], a3 = *(float2*)&acc[p][3];
      float4 o = make_float4(a0.x + a0.y, a1.x + a1.y, a2.x + a2.y, a3.x + a3.y);
      *(float4*)&out[(size_t)np * COUT + c0] = o;
    }
  }
}

// ------------------------- res BN stats (two-stage) + final -------------------------
__global__ void stats_partial(const float* __restrict__ h,
                              float* __restrict__ part, int n) {
  int c = threadIdx.x, b = blockIdx.x;
  float s = 0.f, q = 0.f;
  for (int r = b; r < n; r += 256) {
    float v = h[(size_t)r * COUT + c];
    s += v;
    q += v * v;
  }
  part[b * COUT + c] = s;
  part[256 * COUT + b * COUT + c] = q;
}

__global__ void stats_final(const float* __restrict__ part,
                            const float* __restrict__ g,
                            const float* __restrict__ bta,
                            float* __restrict__ st, int n) {
  int c = threadIdx.x;
  float s = 0.f, q = 0.f;
  for (int b = 0; b < 256; b++) {
    s += part[b * COUT + c];
    q += part[256 * COUT + b * COUT + c];
  }
  float mu  = s / (float)n;
  float var = q / (float)n - mu * mu;
  float sc  = g[c] * rsqrtf(var + 1e-5f);
  st[c]        = sc;
  st[COUT + c] = bta[c] - mu * sc;
}

__global__ void final_add(const float* __restrict__ h2,
                          const float* __restrict__ res,
                          const float* __restrict__ st2,
                          const float* __restrict__ std_,
                          float* __restrict__ out, int n) {
  int i = blockIdx.x * blockDim.x + threadIdx.x;
  int total = n * (COUT / 4);
  if (i < total) {
    int c0 = (i & (COUT / 4 - 1)) * 4;
    float4 h = ((const float4*)h2)[i];
    float4 r = ((const float4*)res)[i];
    float4 s2 = *(const float4*)&st2[c0];
    float4 t2 = *(const float4*)&st2[COUT + c0];
    float4 sd = *(const float4*)&std_[c0];
    float4 td = *(const float4*)&std_[COUT + c0];
    float4 o;
    o.x = fmaxf(0.f, h.x * s2.x + t2.x) + (r.x * sd.x + td.x);
    o.y = fmaxf(0.f, h.y * s2.y + t2.y) + (r.y * sd.y + td.y);
    o.z = fmaxf(0.f, h.z * s2.z + t2.z) + (r.z * sd.z + td.z);
    o.w = fmaxf(0.f, h.w * s2.w + t2.w) + (r.w * sd.w + td.w);
    ((float4*)out)[i] = o;
  }
}

extern "C" void kernel_launch(void* const* d_in, const int* in_sizes, int n_in,
                              void* d_out, int out_size) {
  const float* x   = (const float*)d_in[0];
  const int*   nbr = (const int*)d_in[1];   // JAX x64 disabled -> int32
  const float* W1  = (const float*)d_in[2];
  const float* g1  = (const float*)d_in[3];
  const float* b1  = (const float*)d_in[4];
  const float* W2  = (const float*)d_in[5];
  const float* g2  = (const float*)d_in[6];
  const float* b2  = (const float*)d_in[7];
  const float* Wd  = (const float*)d_in[8];
  const float* gd  = (const float*)d_in[9];
  const float* bd  = (const float*)d_in[10];
  float*       out = (float*)d_out;
  const int n = in_sizes[0] / CIN1;

  float *h1, *h2, *res, *part, *st;
  float2* Wdp;
  char *B1, *B2;
  __half *X1h, *X1l, *X2h, *X2l;
  cudaGetSymbolAddress((void**)&h1,  g_h1);
  cudaGetSymbolAddress((void**)&h2,  g_h2);
  cudaGetSymbolAddress((void**)&res, g_res);
  cudaGetSymbolAddress((void**)&B1,  g_B1);
  cudaGetSymbolAddress((void**)&B2,  g_B2);
  cudaGetSymbolAddress((void**)&X1h, g_X1h);
  cudaGetSymbolAddress((void**)&X1l, g_X1l);
  cudaGetSymbolAddress((void**)&X2h, g_X2h);
  cudaGetSymbolAddress((void**)&X2l, g_X2l);
  cudaGetSymbolAddress((void**)&Wdp, g_Wdp);
  cudaGetSymbolAddress((void**)&part, g_part);
  cudaGetSymbolAddress((void**)&st,  g_st);

  const int smem = NSTAGE * STAGEB + 256;   // 147712 B
  cudaFuncSetAttribute(mma_conv<1>,
                       cudaFuncAttributeMaxDynamicSharedMemorySize, smem);
  cudaFuncSetAttribute(mma_conv<2>,
                       cudaFuncAttributeMaxDynamicSharedMemorySize, smem);

  pack_w_f16<<<432, 256>>>(W1, B1, KTAPS, CIN1);
  pack_w_f16<<<864, 256>>>(W2, B2, KTAPS, COUT);
  pack_w<<<16, 256>>>(Wd, Wdp, 1, CIN1);

  const int nbm = (n + 127) / 128;
  const int nb64 = (n + 63) / 64;

  // pre-split x -> fp16 hi/lo
  const int t41 = n * CIN1 / 4;
  split_plain<<<(t41 + 255) / 256, 256>>>(x, X1h, X1l, t41);

  // conv1 -> h1pre + fused bn1 partials; finalize bn1
  mma_conv<1><<<nbm, 384, smem>>>(X1h, X1l, nbr, B1, h1, part, n);
  stats_final_conv<<<1, 128>>>(part, nbm, g1, b1, st + 0, n);

  // downsample branch: respre = x @ Wd; bn_d stats
  dconv_kernel<<<nb64, 256>>>(x, Wdp, res, n);
  stats_partial<<<256, 128>>>(res, part, n);
  stats_final<<<1, 128>>>(part, gd, bd, st + 2 * COUT, n);

  // h1 -> relu(bn1(h1)) -> fp16 hi/lo
  const int t42 = n * COUT / 4;
  split_bn<<<(t42 + 255) / 256, 256>>>(h1, st + 0, X2h, X2l, t42);

  // conv2 -> h2pre + fused bn2 partials; finalize bn2
  mma_conv<2><<<nbm, 384, smem>>>(X2h, X2l, nbr, B2, h2, part, n);
  stats_final_conv<<<1, 128>>>(part, nbm, g2, b2, st + 4 * COUT, n);

  // out = relu(bn2(h2pre)) + bn_d(respre)
  final_add<<<(t42 + 255) / 256, 256>>>(h2, res, st + 4 * COUT, st + 2 * COUT,
                                        out, n);
}

// round 12
// speedup vs baseline: 4.2099x; 1.1065x over previous
#include <cuda_runtime.h>
#include <cuda_fp16.h>
#include <cstdint>

#define CIN1  64
#define COUT  128
#define KTAPS 27
#define NMAX  131072
#define TILEB 16384   // one [128 rows x 128B] tile
#define NSTAGE 3

// ---- scratch (static device globals; no allocation in kernel_launch) ----
__device__ float g_h1[(size_t)NMAX * COUT];
__device__ float g_h2[(size_t)NMAX * COUT];
__device__ float g_res[(size_t)NMAX * COUT];
__device__ __half g_X1h[(size_t)NMAX * CIN1];
__device__ __half g_X1l[(size_t)NMAX * CIN1];
__device__ __half g_X2h[(size_t)NMAX * COUT];
__device__ __half g_X2l[(size_t)NMAX * COUT];
// pre-swizzled fp16 weight tiles: [step = tap*NC+chunk][128 rows][64 f16]
__device__ __align__(16) char g_B1[KTAPS * 1 * TILEB];
__device__ __align__(16) char g_B2[KTAPS * 2 * TILEB];
__device__ float2 g_Wdp[(CIN1 / 2) * COUT];
__device__ float  g_part[1024 * 256];
__device__ float  g_st[6 * COUT];   // [s1|t1|sd|td|s2|t2]

// ------------------------- helpers -------------------------
__device__ __forceinline__ uint32_t smem_u32(const void* p) {
  uint32_t a;
  asm("{ .reg .u64 t; cvta.to.shared.u64 t, %1; cvt.u32.u64 %0, t; }"
      : "=r"(a) : "l"(p));
  return a;
}
__device__ __forceinline__ unsigned long long fma2(unsigned long long a,
                                                   unsigned long long b,
                                                   unsigned long long c) {
  unsigned long long d;
  asm("fma.rn.f32x2 %0, %1, %2, %3;" : "=l"(d) : "l"(a), "l"(b), "l"(c));
  return d;
}
__device__ __forceinline__ void ldsm4(uint32_t* r, uint32_t addr) {
  asm volatile("ldmatrix.sync.aligned.m8n8.x4.shared.b16 {%0,%1,%2,%3}, [%4];"
               : "=r"(r[0]), "=r"(r[1]), "=r"(r[2]), "=r"(r[3]) : "r"(addr));
}
__device__ __forceinline__ void mma_f16(float* c, const uint32_t* a,
                                        const uint32_t* b) {
  asm volatile(
      "mma.sync.aligned.m16n8k16.row.col.f32.f16.f16.f32 "
      "{%0,%1,%2,%3}, {%4,%5,%6,%7}, {%8,%9}, {%0,%1,%2,%3};"
      : "+f"(c[0]), "+f"(c[1]), "+f"(c[2]), "+f"(c[3])
      : "r"(a[0]), "r"(a[1]), "r"(a[2]), "r"(a[3]), "r"(b[0]), "r"(b[1]));
}
// 16B-chunk XOR swizzle inside a 128B row
__device__ __host__ __forceinline__ uint32_t swz16(uint32_t c, uint32_t r7) {
  return (c & ~7u) | ((c ^ r7) & 7u);
}
#define BAR_SYNC(id)   asm volatile("bar.sync %0, 384;"   :: "r"(id) : "memory")
#define BAR_ARRIVE(id) asm volatile("bar.arrive %0, 384;" :: "r"(id) : "memory")
#define CP16(dst, src) \
  asm volatile("cp.async.cg.shared.global [%0], [%1], 16;" \
               :: "r"(dst), "l"(src))

// ------------------------- weight packing -------------------------
__global__ void pack_w_f16(const float* __restrict__ W, char* __restrict__ B,
                           int KT, int CIN) {
  int NC = CIN / 64;
  int total = KT * CIN * COUT;
  for (int i = blockIdx.x * blockDim.x + threadIdx.x; i < total;
       i += gridDim.x * blockDim.x) {
    int cout = i % COUT;
    int cin  = (i / COUT) % CIN;
    int k    = i / (COUT * CIN);
    float v = W[((size_t)k * CIN + cin) * COUT + cout];
    int step = k * NC + (cin >> 6);
    uint32_t e = (uint32_t)cin & 63;
    uint32_t off = (uint32_t)cout * 128 + swz16(e >> 3, cout & 7) * 16 +
                   (e & 7) * 2;
    *(__half*)(B + (size_t)step * TILEB + off) = __float2half_rn(v);
  }
}

// ------------------------- fp16 hi/lo split passes -------------------------
__global__ void split_plain(const float* __restrict__ X, __half* __restrict__ Xh,
                            __half* __restrict__ Xl, int total4) {
  int i = blockIdx.x * blockDim.x + threadIdx.x;
  if (i < total4) {
    float4 v = ((const float4*)X)[i];
    __half hx = __float2half_rn(v.x), hy = __float2half_rn(v.y);
    __half hz = __float2half_rn(v.z), hw = __float2half_rn(v.w);
    __half2 h0 = __halves2half2(hx, hy), h1 = __halves2half2(hz, hw);
    __half2 l0 = __floats2half2_rn(v.x - __half2float(hx), v.y - __half2float(hy));
    __half2 l1 = __floats2half2_rn(v.z - __half2float(hz), v.w - __half2float(hw));
    ((uint2*)Xh)[i] = make_uint2(*(uint32_t*)&h0, *(uint32_t*)&h1);
    ((uint2*)Xl)[i] = make_uint2(*(uint32_t*)&l0, *(uint32_t*)&l1);
  }
}

__global__ void split_bn(const float* __restrict__ H, const float* __restrict__ st,
                         __half* __restrict__ Xh, __half* __restrict__ Xl,
                         int total4) {
  int i = blockIdx.x * blockDim.x + threadIdx.x;
  if (i < total4) {
    int c0 = (i & 31) * 4;   // channel of first element (COUT=128)
    float4 v = ((const float4*)H)[i];
    float4 sc = *(const float4*)&st[c0];
    float4 tb = *(const float4*)&st[COUT + c0];
    v.x = fmaxf(0.f, v.x * sc.x + tb.x);
    v.y = fmaxf(0.f, v.y * sc.y + tb.y);
    v.z = fmaxf(0.f, v.z * sc.z + tb.z);
    v.w = fmaxf(0.f, v.w * sc.w + tb.w);
    __half hx = __float2half_rn(v.x), hy = __float2half_rn(v.y);
    __half hz = __float2half_rn(v.z), hw = __float2half_rn(v.w);
    __half2 h0 = __halves2half2(hx, hy), h1 = __halves2half2(hz, hw);
    __half2 l0 = __floats2half2_rn(v.x - __half2float(hx), v.y - __half2float(hy));
    __half2 l1 = __floats2half2_rn(v.z - __half2float(hz), v.w - __half2float(hw));
    ((uint2*)Xh)[i] = make_uint2(*(uint32_t*)&h0, *(uint32_t*)&h1);
    ((uint2*)Xl)[i] = make_uint2(*(uint32_t*)&l0, *(uint32_t*)&l1);
  }
}

// ------------------------- warp-specialized fp16 mma gathered conv -------------
// 384 threads: warps 0-7 = consumers (MMA + fused BN-stat partials),
// warps 8-11 = producers (pure cp.async from pre-split fp16 inputs).
// TERMS=2: acc += xh*w + xl*w; TERMS=1: acc += xh*w.
// NSTAGE-deep pipeline; stage = [A-hi][A-lo if TERMS=2][B], 16KB tiles.
// Consumer double-buffers LDSM fragments across k-steps and releases the
// stage (bar.arrive) right after the LAST LDSM so producers refill early.
template <int NC, int TERMS>
__global__ __launch_bounds__(384, 1)
void mma_conv(const __half* __restrict__ Xh, const __half* __restrict__ Xl,
              const int* __restrict__ nbr, const char* __restrict__ Bg,
              float* __restrict__ out, float* __restrict__ part, int n) {
  constexpr int CIN    = NC * 64;
  constexpr int STEPS  = KTAPS * NC;
  constexpr int STAGE  = (TERMS + 1) * TILEB;
  constexpr uint32_t BOFF = TERMS * TILEB;
  extern __shared__ char dsm_raw[];
  char* dsm = (char*)(((uintptr_t)dsm_raw + 127) & ~(uintptr_t)127);
  __shared__ int idx_s[128 * KTAPS];

  const int t = threadIdx.x, lane = t & 31, wid = t >> 5;
  const int n0 = blockIdx.x * 128;

  for (int i = t; i < 128 * KTAPS; i += 384) {
    int row = n0 + i / KTAPS;
    idx_s[i] = (row < n) ? nbr[(size_t)row * KTAPS + (i % KTAPS)] : 0;
  }
  __syncthreads();

  const uint32_t Du = smem_u32(dsm);
  // barrier ids: FULL(b) = 1+b, FREE(b) = 4+b, epilogue = 7

  if (wid >= 8) {
    // ======================= producer: pure cp.async =======================
    const int row = t - 256;                 // 0..127, one row each
    const uint32_t r7 = (uint32_t)(row & 7);
    for (int s = 0; s < STEPS; s++) {
      const int b = s % NSTAGE;
      if (s >= NSTAGE) BAR_SYNC(4 + b);
      int tap = s / NC, ch = s % NC;
      int src = idx_s[row * KTAPS + tap];
      const char* sh = (const char*)(Xh + (size_t)src * CIN + ch * 64);
      const char* sl = (const char*)(Xl + (size_t)src * CIN + ch * 64);
      const char* sb = Bg + (size_t)s * TILEB + row * 128;
      uint32_t dh = Du + b * STAGE + row * 128;
      uint32_t db = Du + b * STAGE + BOFF + row * 128;
#pragma unroll
      for (uint32_t d = 0; d < 8; d++) {
        uint32_t scn = d ^ r7;               // source chunk for dst chunk d
        CP16(dh + d * 16, sh + scn * 16);
        if (TERMS == 2) CP16(dh + TILEB + d * 16, sl + scn * 16);
        CP16(db + d * 16, sb + d * 16);      // B pre-swizzled: verbatim
      }
      asm volatile("cp.async.commit_group;" ::: "memory");
      asm volatile("cp.async.wait_group 0;" ::: "memory");
      BAR_ARRIVE(1 + b);
    }
    return;   // producers done
  }

  // ======================= consumer =======================
  const int wm = wid & 3, wn = wid >> 2;
  const int aRowL = lane & 15, aKh = lane >> 4;
  const int bRowL = ((lane >> 4) << 3) | (lane & 7);
  const int bKh   = (lane >> 3) & 1;

  float acc[2][8][4];
#pragma unroll
  for (int m = 0; m < 2; m++)
#pragma unroll
    for (int f = 0; f < 8; f++)
#pragma unroll
      for (int q = 0; q < 4; q++) acc[m][f][q] = 0.f;

  uint32_t ah[2][2][4], al[2][2][4], bb[2][16];

  for (int s = 0; s < STEPS; s++) {
    const int b = s % NSTAGE;
    const uint32_t AHu = Du + b * STAGE, ALu = AHu + TILEB, Bu = AHu + BOFF;
    BAR_SYNC(1 + b);

    // fragment loader for k-step ks into buffer pb
#define LDFRAG(ks, pb)                                                      \
    {                                                                       \
      uint32_t cbase = 2 * (ks);                                            \
      _Pragma("unroll")                                                     \
      for (int mt = 0; mt < 2; mt++) {                                      \
        uint32_t row = wm * 32 + mt * 16 + aRowL;                           \
        uint32_t off = row * 128 + swz16(cbase + aKh, row & 7) * 16;        \
        ldsm4(ah[pb][mt], AHu + off);                                       \
        if (TERMS == 2) ldsm4(al[pb][mt], ALu + off);                       \
      }                                                                     \
      _Pragma("unroll")                                                     \
      for (int i = 0; i < 4; i++) {                                         \
        uint32_t row = wn * 64 + i * 16 + bRowL;                            \
        uint32_t off = row * 128 + swz16(cbase + bKh, row & 7) * 16;        \
        ldsm4(&bb[pb][i * 4], Bu + off);                                    \
      }                                                                     \
    }

    LDFRAG(0, 0);
#pragma unroll
    for (int ks = 0; ks < 4; ks++) {
      const int cur = ks & 1;
      if (ks < 3) {
        LDFRAG(ks + 1, cur ^ 1);
      } else {
        BAR_ARRIVE(4 + b);   // all stage data now in registers
      }
#pragma unroll
      for (int mt = 0; mt < 2; mt++)
#pragma unroll
        for (int f = 0; f < 8; f++) {
          mma_f16(acc[mt][f], ah[cur][mt], &bb[cur][f * 2]);
          if (TERMS == 2) mma_f16(acc[mt][f], al[cur][mt], &bb[cur][f * 2]);
        }
    }
#undef LDFRAG
  }

  // ---- epilogue 1: fragment regs -> gmem ----
#pragma unroll
  for (int mt = 0; mt < 2; mt++)
#pragma unroll
    for (int f = 0; f < 8; f++) {
      int row = n0 + wm * 32 + mt * 16 + (lane >> 2);
      int col = wn * 64 + f * 8 + 2 * (lane & 3);
      if (row < n)
        *(float2*)&out[(size_t)row * COUT + col] =
            make_float2(acc[mt][f][0], acc[mt][f][1]);
      if (row + 8 < n)
        *(float2*)&out[(size_t)(row + 8) * COUT + col] =
            make_float2(acc[mt][f][2], acc[mt][f][3]);
    }

  // ---- epilogue 2: fused BN-stat partials (masked, deterministic) ----
  {
    int r0 = n0 + wm * 32 + (lane >> 2);
    bool vA0 = r0 < n, vA1 = r0 + 8 < n;        // mt = 0
    bool vB0 = r0 + 16 < n, vB1 = r0 + 24 < n;  // mt = 1
    float sums[8][2], sqs[8][2];
#pragma unroll
    for (int f = 0; f < 8; f++)
#pragma unroll
      for (int e = 0; e < 2; e++) {
        float a0 = vA0 ? acc[0][f][e] : 0.f;
        float a1 = vA1 ? acc[0][f][e + 2] : 0.f;
        float b0 = vB0 ? acc[1][f][e] : 0.f;
        float b1 = vB1 ? acc[1][f][e + 2] : 0.f;
        sums[f][e] = a0 + a1 + b0 + b1;
        sqs[f][e]  = a0 * a0 + a1 * a1 + b0 * b0 + b1 * b1;
      }
#pragma unroll
    for (int off = 4; off < 32; off <<= 1)
#pragma unroll
      for (int f = 0; f < 8; f++)
#pragma unroll
        for (int e = 0; e < 2; e++) {
          sums[f][e] += __shfl_down_sync(0xffffffffu, sums[f][e], off);
          sqs[f][e]  += __shfl_down_sync(0xffffffffu, sqs[f][e],  off);
        }
    float* S = (float*)dsm;          // [4][128]
    float* Q = S + 512;              // [4][128]
    if (lane < 4) {
#pragma unroll
      for (int f = 0; f < 8; f++)
#pragma unroll
        for (int e = 0; e < 2; e++) {
          int col = wn * 64 + f * 8 + 2 * lane + e;
          S[wm * 128 + col] = sums[f][e];
          Q[wm * 128 + col] = sqs[f][e];
        }
    }
    asm volatile("bar.sync 7, 256;" ::: "memory");
    if (t < 128) {
      float s = S[t] + S[128 + t] + S[256 + t] + S[384 + t];
      float q = Q[t] + Q[128 + t] + Q[256 + t] + Q[384 + t];
      part[(size_t)blockIdx.x * 256 + t] = s;
      part[(size_t)blockIdx.x * 256 + 128 + t] = q;
    }
  }
}

// single-block finalize over conv block partials (deterministic)
__global__ void stats_final_conv(const float* __restrict__ part, int nb,
                                 const float* __restrict__ g,
                                 const float* __restrict__ bta,
                                 float* __restrict__ st, int n) {
  int c = threadIdx.x;   // 128
  float s = 0.f, q = 0.f;
  for (int b = 0; b < nb; b++) {
    s += part[(size_t)b * 256 + c];
    q += part[(size_t)b * 256 + 128 + c];
  }
  float mu  = s / (float)n;
  float var = q / (float)n - mu * mu;
  float sc  = g[c] * rsqrtf(var + 1e-5f);
  st[c]        = sc;
  st[COUT + c] = bta[c] - mu * sc;
}

// ------------------------- downsample (1x1 conv, FFMA2) -------------------------
__global__ void pack_w(const float* __restrict__ W, float2* __restrict__ Wp,
                       int KT, int CIN) {
  int total = KT * (CIN / 2) * COUT;
  for (int i = blockIdx.x * blockDim.x + threadIdx.x; i < total;
       i += gridDim.x * blockDim.x) {
    int c  = i % COUT;
    int cp = (i / COUT) % (CIN / 2);
    int k  = i / (COUT * (CIN / 2));
    Wp[i] = make_float2(W[((size_t)k * CIN + 2 * cp) * COUT + c],
                        W[((size_t)k * CIN + 2 * cp + 1) * COUT + c]);
  }
}

__global__ __launch_bounds__(256, 2)
void dconv_kernel(const float* __restrict__ X, const float2* __restrict__ Wp,
                  float* __restrict__ out, int n) {
  constexpr int CIN = CIN1;
  constexpr int STRIDE = CIN + 8;
  __shared__ float xs[64 * STRIDE];
  const int t = threadIdx.x;
  const int n0 = blockIdx.x * 64;
  const int tcol = t & 31, trow = t >> 5;
  const int c0 = tcol * 4, p0 = trow * 8;
  const int r = t >> 2, seg = t & 3;
  {
    int src = n0 + r;
    if (src >= n) src = n - 1;
    const float4* rp = (const float4*)(X + (size_t)src * CIN);
#pragma unroll
    for (int j = 0; j < CIN / 16; j++)
      *(float4*)&xs[r * STRIDE + (seg + 4 * j) * 4] = rp[seg + 4 * j];
  }
  __syncthreads();
  unsigned long long acc[8][4];
#pragma unroll
  for (int p = 0; p < 8; p++)
#pragma unroll
    for (int i = 0; i < 4; i++) acc[p][i] = 0ull;
  const unsigned long long* wrow = (const unsigned long long*)Wp;
#pragma unroll 2
  for (int cp = 0; cp < CIN / 2; cp += 2) {
    const unsigned long long* wb0 = wrow + (size_t)cp * COUT + c0;
    const unsigned long long* wb1 = wrow + (size_t)(cp + 1) * COUT + c0;
    ulonglong2 wa = *(const ulonglong2*)wb0, wa2 = *(const ulonglong2*)(wb0 + 2);
    ulonglong2 wc = *(const ulonglong2*)wb1, wc2 = *(const ulonglong2*)(wb1 + 2);
#pragma unroll
    for (int p = 0; p < 8; p++) {
      ulonglong2 xv = *(const ulonglong2*)&xs[(p0 + p) * STRIDE + 2 * cp];
      acc[p][0] = fma2(xv.x, wa.x,  acc[p][0]);
      acc[p][1] = fma2(xv.x, wa.y,  acc[p][1]);
      acc[p][2] = fma2(xv.x, wa2.x, acc[p][2]);
      acc[p][3] = fma2(xv.x, wa2.y, acc[p][3]);
      acc[p][0] = fma2(xv.y, wc.x,  acc[p][0]);
      acc[p][1] = fma2(xv.y, wc.y,  acc[p][1]);
      acc[p][2] = fma2(xv.y, wc2.x, acc[p][2]);
      acc[p][3] = fma2(xv.y, wc2.y, acc[p][3]);
    }
  }
#pragma unroll
  for (int p = 0; p < 8; p++) {
    int np = n0 + p0 + p;
    if (np < n) {
      float2 a0 = *(float2*)&acc[p][0], a1 = *(float2*)&acc[p][1];
      float2 a2 = *(float2*)&acc[p][2], a3 = *(float2*)&acc[p][3];
      float4 o = make_float4(a0.x + a0.y, a1.x + a1.y, a2.x + a2.y, a3.x + a3.y);
      *(float4*)&out[(size_t)np * COUT + c0] = o;
    }
  }
}

// ------------------------- res BN stats (two-stage) + final -------------------------
__global__ void stats_partial(const float* __restrict__ h,
                              float* __restrict__ part, int n) {
  int c = threadIdx.x, b = blockIdx.x;
  float s = 0.f, q = 0.f;
  for (int r = b; r < n; r += 256) {
    float v = h[(size_t)r * COUT + c];
    s += v;
    q += v * v;
  }
  part[b * COUT + c] = s;
  part[256 * COUT + b * COUT + c] = q;
}

__global__ void stats_final(const float* __restrict__ part,
                            const float* __restrict__ g,
                            const float* __restrict__ bta,
                            float* __restrict__ st, int n) {
  int c = threadIdx.x;
  float s = 0.f, q = 0.f;
  for (int b = 0; b < 256; b++) {
    s += part[b * COUT + c];
    q += part[256 * COUT + b * COUT + c];
  }
  float mu  = s / (float)n;
  float var = q / (float)n - mu * mu;
  float sc  = g[c] * rsqrtf(var + 1e-5f);
  st[c]        = sc;
  st[COUT + c] = bta[c] - mu * sc;
}

__global__ void final_add(const float* __restrict__ h2,
                          const float* __restrict__ res,
                          const float* __restrict__ st2,
                          const float* __restrict__ std_,
                          float* __restrict__ out, int n) {
  int i = blockIdx.x * blockDim.x + threadIdx.x;
  int total = n * (COUT / 4);
  if (i < total) {
    int c0 = (i & (COUT / 4 - 1)) * 4;
    float4 h = ((const float4*)h2)[i];
    float4 r = ((const float4*)res)[i];
    float4 s2 = *(const float4*)&st2[c0];
    float4 t2 = *(const float4*)&st2[COUT + c0];
    float4 sd = *(const float4*)&std_[c0];
    float4 td = *(const float4*)&std_[COUT + c0];
    float4 o;
    o.x = fmaxf(0.f, h.x * s2.x + t2.x) + (r.x * sd.x + td.x);
    o.y = fmaxf(0.f, h.y * s2.y + t2.y) + (r.y * sd.y + td.y);
    o.z = fmaxf(0.f, h.z * s2.z + t2.z) + (r.z * sd.z + td.z);
    o.w = fmaxf(0.f, h.w * s2.w + t2.w) + (r.w * sd.w + td.w);
    ((float4*)out)[i] = o;
  }
}

extern "C" void kernel_launch(void* const* d_in, const int* in_sizes, int n_in,
                              void* d_out, int out_size) {
  const float* x   = (const float*)d_in[0];
  const int*   nbr = (const int*)d_in[1];   // JAX x64 disabled -> int32
  const float* W1  = (const float*)d_in[2];
  const float* g1  = (const float*)d_in[3];
  const float* b1  = (const float*)d_in[4];
  const float* W2  = (const float*)d_in[5];
  const float* g2  = (const float*)d_in[6];
  const float* b2  = (const float*)d_in[7];
  const float* Wd  = (const float*)d_in[8];
  const float* gd  = (const float*)d_in[9];
  const float* bd  = (const float*)d_in[10];
  float*       out = (float*)d_out;
  const int n = in_sizes[0] / CIN1;

  float *h1, *h2, *res, *part, *st;
  float2* Wdp;
  char *B1, *B2;
  __half *X1h, *X1l, *X2h, *X2l;
  cudaGetSymbolAddress((void**)&h1,  g_h1);
  cudaGetSymbolAddress((void**)&h2,  g_h2);
  cudaGetSymbolAddress((void**)&res, g_res);
  cudaGetSymbolAddress((void**)&B1,  g_B1);
  cudaGetSymbolAddress((void**)&B2,  g_B2);
  cudaGetSymbolAddress((void**)&X1h, g_X1h);
  cudaGetSymbolAddress((void**)&X1l, g_X1l);
  cudaGetSymbolAddress((void**)&X2h, g_X2h);
  cudaGetSymbolAddress((void**)&X2l, g_X2l);
  cudaGetSymbolAddress((void**)&Wdp, g_Wdp);
  cudaGetSymbolAddress((void**)&part, g_part);
  cudaGetSymbolAddress((void**)&st,  g_st);

  const int smem1 = NSTAGE * 2 * TILEB + 256;   //  98560 B (TERMS=1)
  const int smem2 = NSTAGE * 3 * TILEB + 256;   // 147712 B (TERMS=2)
  cudaFuncSetAttribute(mma_conv<1, 1>,
                       cudaFuncAttributeMaxDynamicSharedMemorySize, smem1);
  cudaFuncSetAttribute(mma_conv<2, 2>,
                       cudaFuncAttributeMaxDynamicSharedMemorySize, smem2);

  pack_w_f16<<<432, 256>>>(W1, B1, KTAPS, CIN1);
  pack_w_f16<<<864, 256>>>(W2, B2, KTAPS, COUT);
  pack_w<<<16, 256>>>(Wd, Wdp, 1, CIN1);

  const int nbm = (n + 127) / 128;
  const int nb64 = (n + 63) / 64;

  // pre-split x -> fp16 hi/lo (conv1 uses only hi; lo write is cheap)
  const int t41 = n * CIN1 / 4;
  split_plain<<<(t41 + 255) / 256, 256>>>(x, X1h, X1l, t41);

  // conv1 (1-term fp16) -> h1pre + fused bn1 partials; finalize bn1
  mma_conv<1, 1><<<nbm, 384, smem1>>>(X1h, X1l, nbr, B1, h1, part, n);
  stats_final_conv<<<1, 128>>>(part, nbm, g1, b1, st + 0, n);

  // downsample branch: respre = x @ Wd; bn_d stats
  dconv_kernel<<<nb64, 256>>>(x, Wdp, res, n);
  stats_partial<<<256, 128>>>(res, part, n);
  stats_final<<<1, 128>>>(part, gd, bd, st + 2 * COUT, n);

  // h1 -> relu(bn1(h1)) -> fp16 hi/lo
  const int t42 = n * COUT / 4;
  split_bn<<<(t42 + 255) / 256, 256>>>(h1, st + 0, X2h, X2l, t42);

  // conv2 (2-term fp16) -> h2pre + fused bn2 partials; finalize bn2
  mma_conv<2, 2><<<nbm, 384, smem2>>>(X2h, X2l, nbr, B2, h2, part, n);
  stats_final_conv<<<1, 128>>>(part, nbm, g2, b2, st + 4 * COUT, n);

  // out = relu(bn2(h2pre)) + bn_d(respre)
  final_add<<<(t42 + 255) / 256, 256>>>(h2, res, st + 4 * COUT, st + 2 * COUT,
                                        out, n);
}

// round 13
// speedup vs baseline: 5.1914x; 1.2331x over previous
#include <cuda_runtime.h>
#include <cuda_fp16.h>
#include <cstdint>

#define CIN1  64
#define COUT  128
#define KTAPS 27
#define NMAX  131072
#define TILEB 16384   // one [128 rows x 128B] tile
#define NSTAGE 4

// ---- scratch (static device globals; no allocation in kernel_launch) ----
__device__ float g_h1[(size_t)NMAX * COUT];
__device__ float g_h2[(size_t)NMAX * COUT];
__device__ float g_res[(size_t)NMAX * COUT];
__device__ __half g_X1h[(size_t)NMAX * CIN1];
__device__ __half g_X2h[(size_t)NMAX * COUT];
// pre-swizzled fp16 weight tiles: [step = tap*NC+chunk][128 rows][64 f16]
__device__ __align__(16) char g_B1[KTAPS * 1 * TILEB];
__device__ __align__(16) char g_B2[KTAPS * 2 * TILEB];
__device__ float2 g_Wdp[(CIN1 / 2) * COUT];
__device__ float  g_part[1024 * 256];
__device__ float  g_st[6 * COUT];   // [s1|t1|sd|td|s2|t2]

// ------------------------- helpers -------------------------
__device__ __forceinline__ uint32_t smem_u32(const void* p) {
  uint32_t a;
  asm("{ .reg .u64 t; cvta.to.shared.u64 t, %1; cvt.u32.u64 %0, t; }"
      : "=r"(a) : "l"(p));
  return a;
}
__device__ __forceinline__ unsigned long long fma2(unsigned long long a,
                                                   unsigned long long b,
                                                   unsigned long long c) {
  unsigned long long d;
  asm("fma.rn.f32x2 %0, %1, %2, %3;" : "=l"(d) : "l"(a), "l"(b), "l"(c));
  return d;
}
__device__ __forceinline__ void ldsm4(uint32_t* r, uint32_t addr) {
  asm volatile("ldmatrix.sync.aligned.m8n8.x4.shared.b16 {%0,%1,%2,%3}, [%4];"
               : "=r"(r[0]), "=r"(r[1]), "=r"(r[2]), "=r"(r[3]) : "r"(addr));
}
__device__ __forceinline__ void mma_f16(float* c, const uint32_t* a,
                                        const uint32_t* b) {
  asm volatile(
      "mma.sync.aligned.m16n8k16.row.col.f32.f16.f16.f32 "
      "{%0,%1,%2,%3}, {%4,%5,%6,%7}, {%8,%9}, {%0,%1,%2,%3};"
      : "+f"(c[0]), "+f"(c[1]), "+f"(c[2]), "+f"(c[3])
      : "r"(a[0]), "r"(a[1]), "r"(a[2]), "r"(a[3]), "r"(b[0]), "r"(b[1]));
}
// 16B-chunk XOR swizzle inside a 128B row
__device__ __host__ __forceinline__ uint32_t swz16(uint32_t c, uint32_t r7) {
  return (c & ~7u) | ((c ^ r7) & 7u);
}
#define BAR_SYNC(id)   asm volatile("bar.sync %0, 384;"   :: "r"(id) : "memory")
#define BAR_ARRIVE(id) asm volatile("bar.arrive %0, 384;" :: "r"(id) : "memory")
#define CP16(dst, src) \
  asm volatile("cp.async.cg.shared.global [%0], [%1], 16;" \
               :: "r"(dst), "l"(src))

// ------------------------- weight packing -------------------------
__global__ void pack_w_f16(const float* __restrict__ W, char* __restrict__ B,
                           int KT, int CIN) {
  int NC = CIN / 64;
  int total = KT * CIN * COUT;
  for (int i = blockIdx.x * blockDim.x + threadIdx.x; i < total;
       i += gridDim.x * blockDim.x) {
    int cout = i % COUT;
    int cin  = (i / COUT) % CIN;
    int k    = i / (COUT * CIN);
    float v = W[((size_t)k * CIN + cin) * COUT + cout];
    int step = k * NC + (cin >> 6);
    uint32_t e = (uint32_t)cin & 63;
    uint32_t off = (uint32_t)cout * 128 + swz16(e >> 3, cout & 7) * 16 +
                   (e & 7) * 2;
    *(__half*)(B + (size_t)step * TILEB + off) = __float2half_rn(v);
  }
}

// ------------------------- fp16 convert passes -------------------------
__global__ void conv_f16(const float* __restrict__ X, __half* __restrict__ Xh,
                         int total4) {
  int i = blockIdx.x * blockDim.x + threadIdx.x;
  if (i < total4) {
    float4 v = ((const float4*)X)[i];
    __half2 h0 = __floats2half2_rn(v.x, v.y);
    __half2 h1 = __floats2half2_rn(v.z, v.w);
    ((uint2*)Xh)[i] = make_uint2(*(uint32_t*)&h0, *(uint32_t*)&h1);
  }
}

// h1 fp32 -> relu(bn1(h1)) -> fp16
__global__ void conv_bn_f16(const float* __restrict__ H,
                            const float* __restrict__ st,
                            __half* __restrict__ Xh, int total4) {
  int i = blockIdx.x * blockDim.x + threadIdx.x;
  if (i < total4) {
    int c0 = (i & 31) * 4;   // channel of first element (COUT=128)
    float4 v = ((const float4*)H)[i];
    float4 sc = *(const float4*)&st[c0];
    float4 tb = *(const float4*)&st[COUT + c0];
    v.x = fmaxf(0.f, v.x * sc.x + tb.x);
    v.y = fmaxf(0.f, v.y * sc.y + tb.y);
    v.z = fmaxf(0.f, v.z * sc.z + tb.z);
    v.w = fmaxf(0.f, v.w * sc.w + tb.w);
    __half2 h0 = __floats2half2_rn(v.x, v.y);
    __half2 h1 = __floats2half2_rn(v.z, v.w);
    ((uint2*)Xh)[i] = make_uint2(*(uint32_t*)&h0, *(uint32_t*)&h1);
  }
}

// ------------------------- warp-specialized fp16 mma gathered conv -------------
// 384 threads: warps 0-7 = consumers (MMA + fused BN-stat partials),
// warps 8-11 = producers (pure cp.async from pre-converted fp16 inputs).
// acc += x*w (single fp16 term). NSTAGE-deep pipeline; stage = [A 16K][B 16K].
// Consumer double-buffers LDSM fragments across k-steps and releases the
// stage (bar.arrive) right after the LAST LDSM so producers refill early.
template <int NC>
__global__ __launch_bounds__(384, 1)
void mma_conv(const __half* __restrict__ Xh, const int* __restrict__ nbr,
              const char* __restrict__ Bg,
              float* __restrict__ out, float* __restrict__ part, int n) {
  constexpr int CIN    = NC * 64;
  constexpr int STEPS  = KTAPS * NC;
  constexpr int STAGE  = 2 * TILEB;
  extern __shared__ char dsm_raw[];
  char* dsm = (char*)(((uintptr_t)dsm_raw + 127) & ~(uintptr_t)127);
  __shared__ int idx_s[128 * KTAPS];

  const int t = threadIdx.x, lane = t & 31, wid = t >> 5;
  const int n0 = blockIdx.x * 128;

  for (int i = t; i < 128 * KTAPS; i += 384) {
    int row = n0 + i / KTAPS;
    idx_s[i] = (row < n) ? nbr[(size_t)row * KTAPS + (i % KTAPS)] : 0;
  }
  __syncthreads();

  const uint32_t Du = smem_u32(dsm);
  // barrier ids: FULL(b) = 1+b (1..4), FREE(b) = 5+b (5..8), epilogue = 9

  if (wid >= 8) {
    // ======================= producer: pure cp.async =======================
    const int row = t - 256;                 // 0..127, one row each
    const uint32_t r7 = (uint32_t)(row & 7);
    for (int s = 0; s < STEPS; s++) {
      const int b = s % NSTAGE;
      if (s >= NSTAGE) BAR_SYNC(5 + b);
      int tap = s / NC, ch = s % NC;
      int src = idx_s[row * KTAPS + tap];
      const char* sh = (const char*)(Xh + (size_t)src * CIN + ch * 64);
      const char* sb = Bg + (size_t)s * TILEB + row * 128;
      uint32_t dh = Du + b * STAGE + row * 128;
      uint32_t db = dh + TILEB;
#pragma unroll
      for (uint32_t d = 0; d < 8; d++) {
        uint32_t scn = d ^ r7;               // source chunk for dst chunk d
        CP16(dh + d * 16, sh + scn * 16);
        CP16(db + d * 16, sb + d * 16);      // B pre-swizzled: verbatim
      }
      asm volatile("cp.async.commit_group;" ::: "memory");
      asm volatile("cp.async.wait_group 0;" ::: "memory");
      BAR_ARRIVE(1 + b);
    }
    return;   // producers done
  }

  // ======================= consumer =======================
  const int wm = wid & 3, wn = wid >> 2;
  const int aRowL = lane & 15, aKh = lane >> 4;
  const int bRowL = ((lane >> 4) << 3) | (lane & 7);
  const int bKh   = (lane >> 3) & 1;

  float acc[2][8][4];
#pragma unroll
  for (int m = 0; m < 2; m++)
#pragma unroll
    for (int f = 0; f < 8; f++)
#pragma unroll
      for (int q = 0; q < 4; q++) acc[m][f][q] = 0.f;

  uint32_t ah[2][2][4], bb[2][16];

  for (int s = 0; s < STEPS; s++) {
    const int b = s % NSTAGE;
    const uint32_t AHu = Du + b * STAGE, Bu = AHu + TILEB;
    BAR_SYNC(1 + b);

#define LDFRAG(ks, pb)                                                      \
    {                                                                       \
      uint32_t cbase = 2 * (ks);                                            \
      _Pragma("unroll")                                                     \
      for (int mt = 0; mt < 2; mt++) {                                      \
        uint32_t row = wm * 32 + mt * 16 + aRowL;                           \
        uint32_t off = row * 128 + swz16(cbase + aKh, row & 7) * 16;        \
        ldsm4(ah[pb][mt], AHu + off);                                       \
      }                                                                     \
      _Pragma("unroll")                                                     \
      for (int i = 0; i < 4; i++) {                                         \
        uint32_t row = wn * 64 + i * 16 + bRowL;                            \
        uint32_t off = row * 128 + swz16(cbase + bKh, row & 7) * 16;        \
        ldsm4(&bb[pb][i * 4], Bu + off);                                    \
      }                                                                     \
    }

    LDFRAG(0, 0);
#pragma unroll
    for (int ks = 0; ks < 4; ks++) {
      const int cur = ks & 1;
      if (ks < 3) {
        LDFRAG(ks + 1, cur ^ 1);
      } else {
        BAR_ARRIVE(5 + b);   // all stage data now in registers
      }
#pragma unroll
      for (int mt = 0; mt < 2; mt++)
#pragma unroll
        for (int f = 0; f < 8; f++)
          mma_f16(acc[mt][f], ah[cur][mt], &bb[cur][f * 2]);
    }
#undef LDFRAG
  }

  // ---- epilogue 1: fragment regs -> gmem ----
#pragma unroll
  for (int mt = 0; mt < 2; mt++)
#pragma unroll
    for (int f = 0; f < 8; f++) {
      int row = n0 + wm * 32 + mt * 16 + (lane >> 2);
      int col = wn * 64 + f * 8 + 2 * (lane & 3);
      if (row < n)
        *(float2*)&out[(size_t)row * COUT + col] =
            make_float2(acc[mt][f][0], acc[mt][f][1]);
      if (row + 8 < n)
        *(float2*)&out[(size_t)(row + 8) * COUT + col] =
            make_float2(acc[mt][f][2], acc[mt][f][3]);
    }

  // ---- epilogue 2: fused BN-stat partials (masked, deterministic) ----
  {
    int r0 = n0 + wm * 32 + (lane >> 2);
    bool vA0 = r0 < n, vA1 = r0 + 8 < n;        // mt = 0
    bool vB0 = r0 + 16 < n, vB1 = r0 + 24 < n;  // mt = 1
    float sums[8][2], sqs[8][2];
#pragma unroll
    for (int f = 0; f < 8; f++)
#pragma unroll
      for (int e = 0; e < 2; e++) {
        float a0 = vA0 ? acc[0][f][e] : 0.f;
        float a1 = vA1 ? acc[0][f][e + 2] : 0.f;
        float b0 = vB0 ? acc[1][f][e] : 0.f;
        float b1 = vB1 ? acc[1][f][e + 2] : 0.f;
        sums[f][e] = a0 + a1 + b0 + b1;
        sqs[f][e]  = a0 * a0 + a1 * a1 + b0 * b0 + b1 * b1;
      }
#pragma unroll
    for (int off = 4; off < 32; off <<= 1)
#pragma unroll
      for (int f = 0; f < 8; f++)
#pragma unroll
        for (int e = 0; e < 2; e++) {
          sums[f][e] += __shfl_down_sync(0xffffffffu, sums[f][e], off);
          sqs[f][e]  += __shfl_down_sync(0xffffffffu, sqs[f][e],  off);
        }
    float* S = (float*)dsm;          // [4][128]
    float* Q = S + 512;              // [4][128]
    if (lane < 4) {
#pragma unroll
      for (int f = 0; f < 8; f++)
#pragma unroll
        for (int e = 0; e < 2; e++) {
          int col = wn * 64 + f * 8 + 2 * lane + e;
          S[wm * 128 + col] = sums[f][e];
          Q[wm * 128 + col] = sqs[f][e];
        }
    }
    asm volatile("bar.sync 9, 256;" ::: "memory");
    if (t < 128) {
      float s = S[t] + S[128 + t] + S[256 + t] + S[384 + t];
      float q = Q[t] + Q[128 + t] + Q[256 + t] + Q[384 + t];
      part[(size_t)blockIdx.x * 256 + t] = s;
      part[(size_t)blockIdx.x * 256 + 128 + t] = q;
    }
  }
}

// single-block finalize over conv block partials (deterministic)
__global__ void stats_final_conv(const float* __restrict__ part, int nb,
                                 const float* __restrict__ g,
                                 const float* __restrict__ bta,
                                 float* __restrict__ st, int n) {
  int c = threadIdx.x;   // 128
  float s = 0.f, q = 0.f;
  for (int b = 0; b < nb; b++) {
    s += part[(size_t)b * 256 + c];
    q += part[(size_t)b * 256 + 128 + c];
  }
  float mu  = s / (float)n;
  float var = q / (float)n - mu * mu;
  float sc  = g[c] * rsqrtf(var + 1e-5f);
  st[c]        = sc;
  st[COUT + c] = bta[c] - mu * sc;
}

// ------------------------- downsample (1x1 conv, FFMA2) -------------------------
__global__ void pack_w(const float* __restrict__ W, float2* __restrict__ Wp,
                       int KT, int CIN) {
  int total = KT * (CIN / 2) * COUT;
  for (int i = blockIdx.x * blockDim.x + threadIdx.x; i < total;
       i += gridDim.x * blockDim.x) {
    int c  = i % COUT;
    int cp = (i / COUT) % (CIN / 2);
    int k  = i / (COUT * (CIN / 2));
    Wp[i] = make_float2(W[((size_t)k * CIN + 2 * cp) * COUT + c],
                        W[((size_t)k * CIN + 2 * cp + 1) * COUT + c]);
  }
}

__global__ __launch_bounds__(256, 2)
void dconv_kernel(const float* __restrict__ X, const float2* __restrict__ Wp,
                  float* __restrict__ out, int n) {
  constexpr int CIN = CIN1;
  constexpr int STRIDE = CIN + 8;
  __shared__ float xs[64 * STRIDE];
  const int t = threadIdx.x;
  const int n0 = blockIdx.x * 64;
  const int tcol = t & 31, trow = t >> 5;
  const int c0 = tcol * 4, p0 = trow * 8;
  const int r = t >> 2, seg = t & 3;
  {
    int src = n0 + r;
    if (src >= n) src = n - 1;
    const float4* rp = (const float4*)(X + (size_t)src * CIN);
#pragma unroll
    for (int j = 0; j < CIN / 16; j++)
      *(float4*)&xs[r * STRIDE + (seg + 4 * j) * 4] = rp[seg + 4 * j];
  }
  __syncthreads();
  unsigned long long acc[8][4];
#pragma unroll
  for (int p = 0; p < 8; p++)
#pragma unroll
    for (int i = 0; i < 4; i++) acc[p][i] = 0ull;
  const unsigned long long* wrow = (const unsigned long long*)Wp;
#pragma unroll 2
  for (int cp = 0; cp < CIN / 2; cp += 2) {
    const unsigned long long* wb0 = wrow + (size_t)cp * COUT + c0;
    const unsigned long long* wb1 = wrow + (size_t)(cp + 1) * COUT + c0;
    ulonglong2 wa = *(const ulonglong2*)wb0, wa2 = *(const ulonglong2*)(wb0 + 2);
    ulonglong2 wc = *(const ulonglong2*)wb1, wc2 = *(const ulonglong2*)(wb1 + 2);
#pragma unroll
    for (int p = 0; p < 8; p++) {
      ulonglong2 xv = *(const ulonglong2*)&xs[(p0 + p) * STRIDE + 2 * cp];
      acc[p][0] = fma2(xv.x, wa.x,  acc[p][0]);
      acc[p][1] = fma2(xv.x, wa.y,  acc[p][1]);
      acc[p][2] = fma2(xv.x, wa2.x, acc[p][2]);
      acc[p][3] = fma2(xv.x, wa2.y, acc[p][3]);
      acc[p][0] = fma2(xv.y, wc.x,  acc[p][0]);
      acc[p][1] = fma2(xv.y, wc.y,  acc[p][1]);
      acc[p][2] = fma2(xv.y, wc2.x, acc[p][2]);
      acc[p][3] = fma2(xv.y, wc2.y, acc[p][3]);
    }
  }
#pragma unroll
  for (int p = 0; p < 8; p++) {
    int np = n0 + p0 + p;
    if (np < n) {
      float2 a0 = *(float2*)&acc[p][0], a1 = *(float2*)&acc[p][1];
      float2 a2 = *(float2*)&acc[p][2], a3 = *(float2*)&acc[p][3];
      float4 o = make_float4(a0.x + a0.y, a1.x + a1.y, a2.x + a2.y, a3.x + a3.y);
      *(float4*)&out[(size_t)np * COUT + c0] = o;
    }
  }
}

// ------------------------- res BN stats (two-stage) + final -------------------------
__global__ void stats_partial(const float* __restrict__ h,
                              float* __restrict__ part, int n) {
  int c = threadIdx.x, b = blockIdx.x;
  float s = 0.f, q = 0.f;
  for (int r = b; r < n; r += 256) {
    float v = h[(size_t)r * COUT + c];
    s += v;
    q += v * v;
  }
  part[b * COUT + c] = s;
  part[256 * COUT + b * COUT + c] = q;
}

__global__ void stats_final(const float* __restrict__ part,
                            const float* __restrict__ g,
                            const float* __restrict__ bta,
                            float* __restrict__ st, int n) {
  int c = threadIdx.x;
  float s = 0.f, q = 0.f;
  for (int b = 0; b < 256; b++) {
    s += part[b * COUT + c];
    q += part[256 * COUT + b * COUT + c];
  }
  float mu  = s / (float)n;
  float var = q / (float)n - mu * mu;
  float sc  = g[c] * rsqrtf(var + 1e-5f);
  st[c]        = sc;
  st[COUT + c] = bta[c] - mu * sc;
}

__global__ void final_add(const float* __restrict__ h2,
                          const float* __restrict__ res,
                          const float* __restrict__ st2,
                          const float* __restrict__ std_,
                          float* __restrict__ out, int n) {
  int i = blockIdx.x * blockDim.x + threadIdx.x;
  int total = n * (COUT / 4);
  if (i < total) {
    int c0 = (i & (COUT / 4 - 1)) * 4;
    float4 h = ((const float4*)h2)[i];
    float4 r = ((const float4*)res)[i];
    float4 s2 = *(const float4*)&st2[c0];
    float4 t2 = *(const float4*)&st2[COUT + c0];
    float4 sd = *(const float4*)&std_[c0];
    float4 td = *(const float4*)&std_[COUT + c0];
    float4 o;
    o.x = fmaxf(0.f, h.x * s2.x + t2.x) + (r.x * sd.x + td.x);
    o.y = fmaxf(0.f, h.y * s2.y + t2.y) + (r.y * sd.y + td.y);
    o.z = fmaxf(0.f, h.z * s2.z + t2.z) + (r.z * sd.z + td.z);
    o.w = fmaxf(0.f, h.w * s2.w + t2.w) + (r.w * sd.w + td.w);
    ((float4*)out)[i] = o;
  }
}

extern "C" void kernel_launch(void* const* d_in, const int* in_sizes, int n_in,
                              void* d_out, int out_size) {
  const float* x   = (const float*)d_in[0];
  const int*   nbr = (const int*)d_in[1];   // JAX x64 disabled -> int32
  const float* W1  = (const float*)d_in[2];
  const float* g1  = (const float*)d_in[3];
  const float* b1  = (const float*)d_in[4];
  const float* W2  = (const float*)d_in[5];
  const float* g2  = (const float*)d_in[6];
  const float* b2  = (const float*)d_in[7];
  const float* Wd  = (const float*)d_in[8];
  const float* gd  = (const float*)d_in[9];
  const float* bd  = (const float*)d_in[10];
  float*       out = (float*)d_out;
  const int n = in_sizes[0] / CIN1;

  float *h1, *h2, *res, *part, *st;
  float2* Wdp;
  char *B1, *B2;
  __half *X1h, *X2h;
  cudaGetSymbolAddress((void**)&h1,  g_h1);
  cudaGetSymbolAddress((void**)&h2,  g_h2);
  cudaGetSymbolAddress((void**)&res, g_res);
  cudaGetSymbolAddress((void**)&B1,  g_B1);
  cudaGetSymbolAddress((void**)&B2,  g_B2);
  cudaGetSymbolAddress((void**)&X1h, g_X1h);
  cudaGetSymbolAddress((void**)&X2h, g_X2h);
  cudaGetSymbolAddress((void**)&Wdp, g_Wdp);
  cudaGetSymbolAddress((void**)&part, g_part);
  cudaGetSymbolAddress((void**)&st,  g_st);

  const int smem = NSTAGE * 2 * TILEB + 256;   // 131328 B
  cudaFuncSetAttribute(mma_conv<1>,
                       cudaFuncAttributeMaxDynamicSharedMemorySize, smem);
  cudaFuncSetAttribute(mma_conv<2>,
                       cudaFuncAttributeMaxDynamicSharedMemorySize, smem);

  pack_w_f16<<<432, 256>>>(W1, B1, KTAPS, CIN1);
  pack_w_f16<<<864, 256>>>(W2, B2, KTAPS, COUT);
  pack_w<<<16, 256>>>(Wd, Wdp, 1, CIN1);

  const int nbm = (n + 127) / 128;
  const int nb64 = (n + 63) / 64;

  // pre-convert x -> fp16
  const int t41 = n * CIN1 / 4;
  conv_f16<<<(t41 + 255) / 256, 256>>>(x, X1h, t41);

  // conv1 (fp16) -> h1pre + fused bn1 partials; finalize bn1
  mma_conv<1><<<nbm, 384, smem>>>(X1h, nbr, B1, h1, part, n);
  stats_final_conv<<<1, 128>>>(part, nbm, g1, b1, st + 0, n);

  // downsample branch: respre = x @ Wd; bn_d stats
  dconv_kernel<<<nb64, 256>>>(x, Wdp, res, n);
  stats_partial<<<256, 128>>>(res, part, n);
  stats_final<<<1, 128>>>(part, gd, bd, st + 2 * COUT, n);

  // h1 -> relu(bn1(h1)) -> fp16
  const int t42 = n * COUT / 4;
  conv_bn_f16<<<(t42 + 255) / 256, 256>>>(h1, st + 0, X2h, t42);

  // conv2 (fp16) -> h2pre + fused bn2 partials; finalize bn2
  mma_conv<2><<<nbm, 384, smem>>>(X2h, nbr, B2, h2, part, n);
  stats_final_conv<<<1, 128>>>(part, nbm, g2, b2, st + 4 * COUT, n);

  // out = relu(bn2(h2pre)) + bn_d(respre)
  final_add<<<(t42 + 255) / 256, 256>>>(h2, res, st + 4 * COUT, st + 2 * COUT,
                                        out, n);
}

// round 14
// speedup vs baseline: 6.1842x; 1.1913x over previous
#include <cuda_runtime.h>
#include <cuda_fp16.h>
#include <cstdint>

#define CIN1  64
#define COUT  128
#define KTAPS 27
#define NMAX  131072
#define MT    192      // rows per block
#define ATILE (MT * 128)     // 24576
#define BTILE 16384
#define STAGE (ATILE + BTILE)
#define NSTAGE 3

// ---- scratch (static device globals; no allocation in kernel_launch) ----
__device__ float g_h1[(size_t)NMAX * COUT];
__device__ float g_h2[(size_t)NMAX * COUT];
__device__ float g_res[(size_t)NMAX * COUT];
__device__ __half g_X1h[(size_t)NMAX * CIN1];
__device__ __half g_X2h[(size_t)NMAX * COUT];
// pre-swizzled fp16 weight tiles: [step = tap*NC+chunk][128 rows][64 f16]
__device__ __align__(16) char g_B1[KTAPS * 1 * BTILE];
__device__ __align__(16) char g_B2[KTAPS * 2 * BTILE];
__device__ float2 g_Wdp[(CIN1 / 2) * COUT];
__device__ float  g_part[1024 * 256];
__device__ float  g_st[6 * COUT];   // [s1|t1|sd|td|s2|t2]

// ------------------------- helpers -------------------------
__device__ __forceinline__ uint32_t smem_u32(const void* p) {
  uint32_t a;
  asm("{ .reg .u64 t; cvta.to.shared.u64 t, %1; cvt.u32.u64 %0, t; }"
      : "=r"(a) : "l"(p));
  return a;
}
__device__ __forceinline__ unsigned long long fma2(unsigned long long a,
                                                   unsigned long long b,
                                                   unsigned long long c) {
  unsigned long long d;
  asm("fma.rn.f32x2 %0, %1, %2, %3;" : "=l"(d) : "l"(a), "l"(b), "l"(c));
  return d;
}
__device__ __forceinline__ void ldsm4(uint32_t* r, uint32_t addr) {
  asm volatile("ldmatrix.sync.aligned.m8n8.x4.shared.b16 {%0,%1,%2,%3}, [%4];"
               : "=r"(r[0]), "=r"(r[1]), "=r"(r[2]), "=r"(r[3]) : "r"(addr));
}
__device__ __forceinline__ void mma_f16(float* c, const uint32_t* a,
                                        const uint32_t* b) {
  asm volatile(
      "mma.sync.aligned.m16n8k16.row.col.f32.f16.f16.f32 "
      "{%0,%1,%2,%3}, {%4,%5,%6,%7}, {%8,%9}, {%0,%1,%2,%3};"
      : "+f"(c[0]), "+f"(c[1]), "+f"(c[2]), "+f"(c[3])
      : "r"(a[0]), "r"(a[1]), "r"(a[2]), "r"(a[3]), "r"(b[0]), "r"(b[1]));
}
// 16B-chunk XOR swizzle inside a 128B row
__device__ __host__ __forceinline__ uint32_t swz16(uint32_t c, uint32_t r7) {
  return (c & ~7u) | ((c ^ r7) & 7u);
}
#define BAR_SYNC(id)   asm volatile("bar.sync %0, 512;"   :: "r"(id) : "memory")
#define BAR_ARRIVE(id) asm volatile("bar.arrive %0, 512;" :: "r"(id) : "memory")
#define CP16(dst, src) \
  asm volatile("cp.async.cg.shared.global [%0], [%1], 16;" \
               :: "r"(dst), "l"(src))

// ------------------------- weight packing -------------------------
__global__ void pack_w_f16(const float* __restrict__ W, char* __restrict__ B,
                           int KT, int CIN) {
  int NC = CIN / 64;
  int total = KT * CIN * COUT;
  for (int i = blockIdx.x * blockDim.x + threadIdx.x; i < total;
       i += gridDim.x * blockDim.x) {
    int cout = i % COUT;
    int cin  = (i / COUT) % CIN;
    int k    = i / (COUT * CIN);
    float v = W[((size_t)k * CIN + cin) * COUT + cout];
    int step = k * NC + (cin >> 6);
    uint32_t e = (uint32_t)cin & 63;
    uint32_t off = (uint32_t)cout * 128 + swz16(e >> 3, cout & 7) * 16 +
                   (e & 7) * 2;
    *(__half*)(B + (size_t)step * BTILE + off) = __float2half_rn(v);
  }
}

// ------------------------- fp16 convert passes -------------------------
__global__ void conv_f16(const float* __restrict__ X, __half* __restrict__ Xh,
                         int total4) {
  int i = blockIdx.x * blockDim.x + threadIdx.x;
  if (i < total4) {
    float4 v = ((const float4*)X)[i];
    __half2 h0 = __floats2half2_rn(v.x, v.y);
    __half2 h1 = __floats2half2_rn(v.z, v.w);
    ((uint2*)Xh)[i] = make_uint2(*(uint32_t*)&h0, *(uint32_t*)&h1);
  }
}

// h1 fp32 -> relu(bn1(h1)) -> fp16
__global__ void conv_bn_f16(const float* __restrict__ H,
                            const float* __restrict__ st,
                            __half* __restrict__ Xh, int total4) {
  int i = blockIdx.x * blockDim.x + threadIdx.x;
  if (i < total4) {
    int c0 = (i & 31) * 4;   // channel of first element (COUT=128)
    float4 v = ((const float4*)H)[i];
    float4 sc = *(const float4*)&st[c0];
    float4 tb = *(const float4*)&st[COUT + c0];
    v.x = fmaxf(0.f, v.x * sc.x + tb.x);
    v.y = fmaxf(0.f, v.y * sc.y + tb.y);
    v.z = fmaxf(0.f, v.z * sc.z + tb.z);
    v.w = fmaxf(0.f, v.w * sc.w + tb.w);
    __half2 h0 = __floats2half2_rn(v.x, v.y);
    __half2 h1 = __floats2half2_rn(v.z, v.w);
    ((uint2*)Xh)[i] = make_uint2(*(uint32_t*)&h0, *(uint32_t*)&h1);
  }
}

// ------------------------- warp-specialized fp16 mma gathered conv -------------
// 512 threads: warps 0-11 = consumers (MMA + fused BN-stat partials, 192 rows),
// warps 12-15 = producers (pure cp.async, deferred completion: issue step s,
// wait_group 1, arrive FULL(s-1) -> memory latency overlaps next step's issue).
// acc += x*w (single fp16 term). Stage = [A 24K][B 16K], NSTAGE=3.
template <int NC>
__global__ __launch_bounds__(512, 1)
void mma_conv(const __half* __restrict__ Xh, const int* __restrict__ nbr,
              const char* __restrict__ Bg,
              float* __restrict__ out, float* __restrict__ part, int n) {
  constexpr int CIN    = NC * 64;
  constexpr int STEPS  = KTAPS * NC;
  extern __shared__ char dsm_raw[];
  char* dsm = (char*)(((uintptr_t)dsm_raw + 127) & ~(uintptr_t)127);
  __shared__ int idx_s[MT * KTAPS];

  const int t = threadIdx.x, lane = t & 31, wid = t >> 5;
  const int n0 = blockIdx.x * MT;

  for (int i = t; i < MT * KTAPS; i += 512) {
    int row = n0 + i / KTAPS;
    idx_s[i] = (row < n) ? nbr[(size_t)row * KTAPS + (i % KTAPS)] : 0;
  }
  __syncthreads();

  const uint32_t Du = smem_u32(dsm);
  // barrier ids: FULL(b) = 1+b (1..3), FREE(b) = 4+b (4..6), epilogue = 7

  if (wid >= 12) {
    // ======================= producer =======================
    const int pr = t - 384;                  // 0..127
    for (int s = 0; s < STEPS; s++) {
      const int b = s % NSTAGE;
      if (s >= NSTAGE) BAR_SYNC(4 + b);
      int tap = s / NC, ch = s % NC;
      // A rows pr, pr+128 (if < MT)
      for (int row = pr; row < MT; row += 128) {
        const uint32_t r7 = (uint32_t)(row & 7);
        int src = idx_s[row * KTAPS + tap];
        const char* sh = (const char*)(Xh + (size_t)src * CIN + ch * 64);
        uint32_t dh = Du + b * STAGE + row * 128;
#pragma unroll
        for (uint32_t d = 0; d < 8; d++)
          CP16(dh + d * 16, sh + (d ^ r7) * 16);
      }
      // B row pr (pre-swizzled: verbatim copy)
      {
        const char* sb = Bg + (size_t)s * BTILE + pr * 128;
        uint32_t db = Du + b * STAGE + ATILE + pr * 128;
#pragma unroll
        for (uint32_t d = 0; d < 8; d++)
          CP16(db + d * 16, sb + d * 16);
      }
      asm volatile("cp.async.commit_group;" ::: "memory");
      if (s >= 1) {
        asm volatile("cp.async.wait_group 1;" ::: "memory");
        BAR_ARRIVE(1 + (s - 1) % NSTAGE);
      }
    }
    asm volatile("cp.async.wait_group 0;" ::: "memory");
    BAR_ARRIVE(1 + (STEPS - 1) % NSTAGE);
    return;   // producers done
  }

  // ======================= consumer =======================
  const int wm = wid % 6, wn = wid / 6;     // 6 row-tiles x 2 col-halves
  const int aRowL = lane & 15, aKh = lane >> 4;
  const int bRowL = ((lane >> 4) << 3) | (lane & 7);
  const int bKh   = (lane >> 3) & 1;

  float acc[2][8][4];
#pragma unroll
  for (int m = 0; m < 2; m++)
#pragma unroll
    for (int f = 0; f < 8; f++)
#pragma unroll
      for (int q = 0; q < 4; q++) acc[m][f][q] = 0.f;

  uint32_t ah[2][2][4], bb[2][16];

  for (int s = 0; s < STEPS; s++) {
    const int b = s % NSTAGE;
    const uint32_t AHu = Du + b * STAGE, Bu = AHu + ATILE;
    BAR_SYNC(1 + b);

#define LDFRAG(ks, pb)                                                      \
    {                                                                       \
      uint32_t cbase = 2 * (ks);                                            \
      _Pragma("unroll")                                                     \
      for (int mt = 0; mt < 2; mt++) {                                      \
        uint32_t row = wm * 32 + mt * 16 + aRowL;                           \
        uint32_t off = row * 128 + swz16(cbase + aKh, row & 7) * 16;        \
        ldsm4(ah[pb][mt], AHu + off);                                       \
      }                                                                     \
      _Pragma("unroll")                                                     \
      for (int i = 0; i < 4; i++) {                                         \
        uint32_t row = wn * 64 + i * 16 + bRowL;                            \
        uint32_t off = row * 128 + swz16(cbase + bKh, row & 7) * 16;        \
        ldsm4(&bb[pb][i * 4], Bu + off);                                    \
      }                                                                     \
    }

    LDFRAG(0, 0);
#pragma unroll
    for (int ks = 0; ks < 4; ks++) {
      const int cur = ks & 1;
      if (ks < 3) {
        LDFRAG(ks + 1, cur ^ 1);
      } else {
        BAR_ARRIVE(4 + b);   // all stage data now in registers
      }
#pragma unroll
      for (int mt = 0; mt < 2; mt++)
#pragma unroll
        for (int f = 0; f < 8; f++)
          mma_f16(acc[mt][f], ah[cur][mt], &bb[cur][f * 2]);
    }
#undef LDFRAG
  }

  // ---- epilogue 1: fragment regs -> gmem ----
#pragma unroll
  for (int mt = 0; mt < 2; mt++)
#pragma unroll
    for (int f = 0; f < 8; f++) {
      int row = n0 + wm * 32 + mt * 16 + (lane >> 2);
      int col = wn * 64 + f * 8 + 2 * (lane & 3);
      if (row < n)
        *(float2*)&out[(size_t)row * COUT + col] =
            make_float2(acc[mt][f][0], acc[mt][f][1]);
      if (row + 8 < n)
        *(float2*)&out[(size_t)(row + 8) * COUT + col] =
            make_float2(acc[mt][f][2], acc[mt][f][3]);
    }

  // ---- epilogue 2: fused BN-stat partials (masked, deterministic) ----
  {
    int r0 = n0 + wm * 32 + (lane >> 2);
    bool vA0 = r0 < n, vA1 = r0 + 8 < n;        // mt = 0
    bool vB0 = r0 + 16 < n, vB1 = r0 + 24 < n;  // mt = 1
    float sums[8][2], sqs[8][2];
#pragma unroll
    for (int f = 0; f < 8; f++)
#pragma unroll
      for (int e = 0; e < 2; e++) {
        float a0 = vA0 ? acc[0][f][e] : 0.f;
        float a1 = vA1 ? acc[0][f][e + 2] : 0.f;
        float b0 = vB0 ? acc[1][f][e] : 0.f;
        float b1 = vB1 ? acc[1][f][e + 2] : 0.f;
        sums[f][e] = a0 + a1 + b0 + b1;
        sqs[f][e]  = a0 * a0 + a1 * a1 + b0 * b0 + b1 * b1;
      }
#pragma unroll
    for (int off = 4; off < 32; off <<= 1)
#pragma unroll
      for (int f = 0; f < 8; f++)
#pragma unroll
        for (int e = 0; e < 2; e++) {
          sums[f][e] += __shfl_down_sync(0xffffffffu, sums[f][e], off);
          sqs[f][e]  += __shfl_down_sync(0xffffffffu, sqs[f][e],  off);
        }
    float* S = (float*)dsm;          // [6][128]
    float* Q = S + 768;              // [6][128]
    if (lane < 4) {
#pragma unroll
      for (int f = 0; f < 8; f++)
#pragma unroll
        for (int e = 0; e < 2; e++) {
          int col = wn * 64 + f * 8 + 2 * lane + e;
          S[wm * 128 + col] = sums[f][e];
          Q[wm * 128 + col] = sqs[f][e];
        }
    }
    asm volatile("bar.sync 7, 384;" ::: "memory");
    if (t < 128) {
      float s = 0.f, q = 0.f;
#pragma unroll
      for (int g = 0; g < 6; g++) {
        s += S[g * 128 + t];
        q += Q[g * 128 + t];
      }
      part[(size_t)blockIdx.x * 256 + t] = s;
      part[(size_t)blockIdx.x * 256 + 128 + t] = q;
    }
  }
}

// single-block finalize over conv block partials (deterministic)
__global__ void stats_final_conv(const float* __restrict__ part, int nb,
                                 const float* __restrict__ g,
                                 const float* __restrict__ bta,
                                 float* __restrict__ st, int n) {
  int c = threadIdx.x;   // 128
  float s = 0.f, q = 0.f;
  for (int b = 0; b < nb; b++) {
    s += part[(size_t)b * 256 + c];
    q += part[(size_t)b * 256 + 128 + c];
  }
  float mu  = s / (float)n;
  float var = q / (float)n - mu * mu;
  float sc  = g[c] * rsqrtf(var + 1e-5f);
  st[c]        = sc;
  st[COUT + c] = bta[c] - mu * sc;
}

// ------------------------- downsample (1x1 conv, FFMA2) -------------------------
__global__ void pack_w(const float* __restrict__ W, float2* __restrict__ Wp,
                       int KT, int CIN) {
  int total = KT * (CIN / 2) * COUT;
  for (int i = blockIdx.x * blockDim.x + threadIdx.x; i < total;
       i += gridDim.x * blockDim.x) {
    int c  = i % COUT;
    int cp = (i / COUT) % (CIN / 2);
    int k  = i / (COUT * (CIN / 2));
    Wp[i] = make_float2(W[((size_t)k * CIN + 2 * cp) * COUT + c],
                        W[((size_t)k * CIN + 2 * cp + 1) * COUT + c]);
  }
}

__global__ __launch_bounds__(256, 2)
void dconv_kernel(const float* __restrict__ X, const float2* __restrict__ Wp,
                  float* __restrict__ out, int n) {
  constexpr int CIN = CIN1;
  constexpr int STRIDE = CIN + 8;
  __shared__ float xs[64 * STRIDE];
  const int t = threadIdx.x;
  const int n0 = blockIdx.x * 64;
  const int tcol = t & 31, trow = t >> 5;
  const int c0 = tcol * 4, p0 = trow * 8;
  const int r = t >> 2, seg = t & 3;
  {
    int src = n0 + r;
    if (src >= n) src = n - 1;
    const float4* rp = (const float4*)(X + (size_t)src * CIN);
#pragma unroll
    for (int j = 0; j < CIN / 16; j++)
      *(float4*)&xs[r * STRIDE + (seg + 4 * j) * 4] = rp[seg + 4 * j];
  }
  __syncthreads();
  unsigned long long acc[8][4];
#pragma unroll
  for (int p = 0; p < 8; p++)
#pragma unroll
    for (int i = 0; i < 4; i++) acc[p][i] = 0ull;
  const unsigned long long* wrow = (const unsigned long long*)Wp;
#pragma unroll 2
  for (int cp = 0; cp < CIN / 2; cp += 2) {
    const unsigned long long* wb0 = wrow + (size_t)cp * COUT + c0;
    const unsigned long long* wb1 = wrow + (size_t)(cp + 1) * COUT + c0;
    ulonglong2 wa = *(const ulonglong2*)wb0, wa2 = *(const ulonglong2*)(wb0 + 2);
    ulonglong2 wc = *(const ulonglong2*)wb1, wc2 = *(const ulonglong2*)(wb1 + 2);
#pragma unroll
    for (int p = 0; p < 8; p++) {
      ulonglong2 xv = *(const ulonglong2*)&xs[(p0 + p) * STRIDE + 2 * cp];
      acc[p][0] = fma2(xv.x, wa.x,  acc[p][0]);
      acc[p][1] = fma2(xv.x, wa.y,  acc[p][1]);
      acc[p][2] = fma2(xv.x, wa2.x, acc[p][2]);
      acc[p][3] = fma2(xv.x, wa2.y, acc[p][3]);
      acc[p][0] = fma2(xv.y, wc.x,  acc[p][0]);
      acc[p][1] = fma2(xv.y, wc.y,  acc[p][1]);
      acc[p][2] = fma2(xv.y, wc2.x, acc[p][2]);
      acc[p][3] = fma2(xv.y, wc2.y, acc[p][3]);
    }
  }
#pragma unroll
  for (int p = 0; p < 8; p++) {
    int np = n0 + p0 + p;
    if (np < n) {
      float2 a0 = *(float2*)&acc[p][0], a1 = *(float2*)&acc[p][1];
      float2 a2 = *(float2*)&acc[p][2], a3 = *(float2*)&acc[p][3];
      float4 o = make_float4(a0.x + a0.y, a1.x + a1.y, a2.x + a2.y, a3.x + a3.y);
      *(float4*)&out[(size_t)np * COUT + c0] = o;
    }
  }
}

// ------------------------- res BN stats (two-stage) + final -------------------------
__global__ void stats_partial(const float* __restrict__ h,
                              float* __restrict__ part, int n) {
  int c = threadIdx.x, b = blockIdx.x;
  float s = 0.f, q = 0.f;
  for (int r = b; r < n; r += 256) {
    float v = h[(size_t)r * COUT + c];
    s += v;
    q += v * v;
  }
  part[b * COUT + c] = s;
  part[256 * COUT + b * COUT + c] = q;
}

__global__ void stats_final(const float* __restrict__ part,
                            const float* __restrict__ g,
                            const float* __restrict__ bta,
                            float* __restrict__ st, int n) {
  int c = threadIdx.x;
  float s = 0.f, q = 0.f;
  for (int b = 0; b < 256; b++) {
    s += part[b * COUT + c];
    q += part[256 * COUT + b * COUT + c];
  }
  float mu  = s / (float)n;
  float var = q / (float)n - mu * mu;
  float sc  = g[c] * rsqrtf(var + 1e-5f);
  st[c]        = sc;
  st[COUT + c] = bta[c] - mu * sc;
}

__global__ void final_add(const float* __restrict__ h2,
                          const float* __restrict__ res,
                          const float* __restrict__ st2,
                          const float* __restrict__ std_,
                          float* __restrict__ out, int n) {
  int i = blockIdx.x * blockDim.x + threadIdx.x;
  int total = n * (COUT / 4);
  if (i < total) {
    int c0 = (i & (COUT / 4 - 1)) * 4;
    float4 h = ((const float4*)h2)[i];
    float4 r = ((const float4*)res)[i];
    float4 s2 = *(const float4*)&st2[c0];
    float4 t2 = *(const float4*)&st2[COUT + c0];
    float4 sd = *(const float4*)&std_[c0];
    float4 td = *(const float4*)&std_[COUT + c0];
    float4 o;
    o.x = fmaxf(0.f, h.x * s2.x + t2.x) + (r.x * sd.x + td.x);
    o.y = fmaxf(0.f, h.y * s2.y + t2.y) + (r.y * sd.y + td.y);
    o.z = fmaxf(0.f, h.z * s2.z + t2.z) + (r.z * sd.z + td.z);
    o.w = fmaxf(0.f, h.w * s2.w + t2.w) + (r.w * sd.w + td.w);
    ((float4*)out)[i] = o;
  }
}

extern "C" void kernel_launch(void* const* d_in, const int* in_sizes, int n_in,
                              void* d_out, int out_size) {
  const float* x   = (const float*)d_in[0];
  const int*   nbr = (const int*)d_in[1];   // JAX x64 disabled -> int32
  const float* W1  = (const float*)d_in[2];
  const float* g1  = (const float*)d_in[3];
  const float* b1  = (const float*)d_in[4];
  const float* W2  = (const float*)d_in[5];
  const float* g2  = (const float*)d_in[6];
  const float* b2  = (const float*)d_in[7];
  const float* Wd  = (const float*)d_in[8];
  const float* gd  = (const float*)d_in[9];
  const float* bd  = (const float*)d_in[10];
  float*       out = (float*)d_out;
  const int n = in_sizes[0] / CIN1;

  float *h1, *h2, *res, *part, *st;
  float2* Wdp;
  char *B1, *B2;
  __half *X1h, *X2h;
  cudaGetSymbolAddress((void**)&h1,  g_h1);
  cudaGetSymbolAddress((void**)&h2,  g_h2);
  cudaGetSymbolAddress((void**)&res, g_res);
  cudaGetSymbolAddress((void**)&B1,  g_B1);
  cudaGetSymbolAddress((void**)&B2,  g_B2);
  cudaGetSymbolAddress((void**)&X1h, g_X1h);
  cudaGetSymbolAddress((void**)&X2h, g_X2h);
  cudaGetSymbolAddress((void**)&Wdp, g_Wdp);
  cudaGetSymbolAddress((void**)&part, g_part);
  cudaGetSymbolAddress((void**)&st,  g_st);

  const int smem = NSTAGE * STAGE + 256;   // 123136 B
  cudaFuncSetAttribute(mma_conv<1>,
                       cudaFuncAttributeMaxDynamicSharedMemorySize, smem);
  cudaFuncSetAttribute(mma_conv<2>,
                       cudaFuncAttributeMaxDynamicSharedMemorySize, smem);

  pack_w_f16<<<432, 256>>>(W1, B1, KTAPS, CIN1);
  pack_w_f16<<<864, 256>>>(W2, B2, KTAPS, COUT);
  pack_w<<<16, 256>>>(Wd, Wdp, 1, CIN1);

  const int nbm = (n + MT - 1) / MT;
  const int nb64 = (n + 63) / 64;

  // pre-convert x -> fp16
  const int t41 = n * CIN1 / 4;
  conv_f16<<<(t41 + 255) / 256, 256>>>(x, X1h, t41);

  // conv1 (fp16) -> h1pre + fused bn1 partials; finalize bn1
  mma_conv<1><<<nbm, 512, smem>>>(X1h, nbr, B1, h1, part, n);
  stats_final_conv<<<1, 128>>>(part, nbm, g1, b1, st + 0, n);

  // downsample branch: respre = x @ Wd; bn_d stats
  dconv_kernel<<<nb64, 256>>>(x, Wdp, res, n);
  stats_partial<<<256, 128>>>(res, part, n);
  stats_final<<<1, 128>>>(part, gd, bd, st + 2 * COUT, n);

  // h1 -> relu(bn1(h1)) -> fp16
  const int t42 = n * COUT / 4;
  conv_bn_f16<<<(t42 + 255) / 256, 256>>>(h1, st + 0, X2h, t42);

  // conv2 (fp16) -> h2pre + fused bn2 partials; finalize bn2
  mma_conv<2><<<nbm, 512, smem>>>(X2h, nbr, B2, h2, part, n);
  stats_final_conv<<<1, 128>>>(part, nbm, g2, b2, st + 4 * COUT, n);

  // out = relu(bn2(h2pre)) + bn_d(respre)
  final_add<<<(t42 + 255) / 256, 256>>>(h2, res, st + 4 * COUT, st + 2 * COUT,
                                        out, n);
}

// round 15
// speedup vs baseline: 7.8304x; 1.2662x over previous
#include <cuda_runtime.h>
#include <cuda_fp16.h>
#include <cstdint>

#define CIN1  64
#define COUT  128
#define KTAPS 27
#define NMAX  131072
#define MT    224              // rows per conv block (7 x 32)
#define ATILE (MT * 128)       // 28672
#define BTILE 16384
#define STAGE (ATILE + BTILE)  // 45056
#define NSTAGE 3
#define DGRID 304              // persistent dconv grid (2/SM)

// ---- scratch (static device globals; no allocation in kernel_launch) ----
__device__ __half g_h1[(size_t)NMAX * COUT];
__device__ __half g_h2[(size_t)NMAX * COUT];
__device__ float  g_res[(size_t)NMAX * COUT];
__device__ __half g_X1h[(size_t)NMAX * CIN1];
__device__ __half g_X2h[(size_t)NMAX * COUT];
// pre-swizzled fp16 weight tiles: [step = tap*NC+chunk][128 rows][64 f16]
__device__ __align__(16) char g_B1[KTAPS * 1 * BTILE];
__device__ __align__(16) char g_B2[KTAPS * 2 * BTILE];
__device__ float2 g_Wdp[(CIN1 / 2) * COUT];
__device__ float  g_part[1024 * 256];
__device__ float  g_st[6 * COUT];   // [s1|t1|sd|td|s2|t2]

// ------------------------- helpers -------------------------
__device__ __forceinline__ uint32_t smem_u32(const void* p) {
  uint32_t a;
  asm("{ .reg .u64 t; cvta.to.shared.u64 t, %1; cvt.u32.u64 %0, t; }"
      : "=r"(a) : "l"(p));
  return a;
}
__device__ __forceinline__ unsigned long long fma2(unsigned long long a,
                                                   unsigned long long b,
                                                   unsigned long long c) {
  unsigned long long d;
  asm("fma.rn.f32x2 %0, %1, %2, %3;" : "=l"(d) : "l"(a), "l"(b), "l"(c));
  return d;
}
__device__ __forceinline__ void ldsm4(uint32_t* r, uint32_t addr) {
  asm volatile("ldmatrix.sync.aligned.m8n8.x4.shared.b16 {%0,%1,%2,%3}, [%4];"
               : "=r"(r[0]), "=r"(r[1]), "=r"(r[2]), "=r"(r[3]) : "r"(addr));
}
__device__ __forceinline__ void mma_f16(float* c, const uint32_t* a,
                                        const uint32_t* b) {
  asm volatile(
      "mma.sync.aligned.m16n8k16.row.col.f32.f16.f16.f32 "
      "{%0,%1,%2,%3}, {%4,%5,%6,%7}, {%8,%9}, {%0,%1,%2,%3};"
      : "+f"(c[0]), "+f"(c[1]), "+f"(c[2]), "+f"(c[3])
      : "r"(a[0]), "r"(a[1]), "r"(a[2]), "r"(a[3]), "r"(b[0]), "r"(b[1]));
}
// 16B-chunk XOR swizzle inside a 128B row
__device__ __host__ __forceinline__ uint32_t swz16(uint32_t c, uint32_t r7) {
  return (c & ~7u) | ((c ^ r7) & 7u);
}
#define BAR_SYNC(id)   asm volatile("bar.sync %0, 512;"   :: "r"(id) : "memory")
#define BAR_ARRIVE(id) asm volatile("bar.arrive %0, 512;" :: "r"(id) : "memory")
#define CP16(dst, src) \
  asm volatile("cp.async.cg.shared.global [%0], [%1], 16;" \
               :: "r"(dst), "l"(src))

// ------------------------- weight packing -------------------------
__global__ void pack_w_f16(const float* __restrict__ W, char* __restrict__ B,
                           int KT, int CIN) {
  int NC = CIN / 64;
  int total = KT * CIN * COUT;
  for (int i = blockIdx.x * blockDim.x + threadIdx.x; i < total;
       i += gridDim.x * blockDim.x) {
    int cout = i % COUT;
    int cin  = (i / COUT) % CIN;
    int k    = i / (COUT * CIN);
    float v = W[((size_t)k * CIN + cin) * COUT + cout];
    int step = k * NC + (cin >> 6);
    uint32_t e = (uint32_t)cin & 63;
    uint32_t off = (uint32_t)cout * 128 + swz16(e >> 3, cout & 7) * 16 +
                   (e & 7) * 2;
    *(__half*)(B + (size_t)step * BTILE + off) = __float2half_rn(v);
  }
}

// ------------------------- fp16 convert passes -------------------------
__global__ void conv_f16(const float* __restrict__ X, __half* __restrict__ Xh,
                         int total4) {
  int i = blockIdx.x * blockDim.x + threadIdx.x;
  if (i < total4) {
    float4 v = ((const float4*)X)[i];
    __half2 h0 = __floats2half2_rn(v.x, v.y);
    __half2 h1 = __floats2half2_rn(v.z, v.w);
    ((uint2*)Xh)[i] = make_uint2(*(uint32_t*)&h0, *(uint32_t*)&h1);
  }
}

// h1 (fp16) -> relu(bn1(h1)) -> fp16
__global__ void conv_bn_f16(const __half* __restrict__ H,
                            const float* __restrict__ st,
                            __half* __restrict__ Xh, int total4) {
  int i = blockIdx.x * blockDim.x + threadIdx.x;
  if (i < total4) {
    int c0 = (i & 31) * 4;   // channel of first element (COUT=128)
    uint2 raw = ((const uint2*)H)[i];
    __half2 a = *(__half2*)&raw.x, b = *(__half2*)&raw.y;
    float4 v = make_float4(__low2float(a), __high2float(a),
                           __low2float(b), __high2float(b));
    float4 sc = *(const float4*)&st[c0];
    float4 tb = *(const float4*)&st[COUT + c0];
    v.x = fmaxf(0.f, v.x * sc.x + tb.x);
    v.y = fmaxf(0.f, v.y * sc.y + tb.y);
    v.z = fmaxf(0.f, v.z * sc.z + tb.z);
    v.w = fmaxf(0.f, v.w * sc.w + tb.w);
    __half2 h0 = __floats2half2_rn(v.x, v.y);
    __half2 h1 = __floats2half2_rn(v.z, v.w);
    ((uint2*)Xh)[i] = make_uint2(*(uint32_t*)&h0, *(uint32_t*)&h1);
  }
}

// ------------------------- warp-specialized fp16 mma gathered conv -------------
// 512 threads: warps 0-13 = consumers (MMA + fused BN-stat partials, 224 rows),
// warps 14-15 = producers (pure cp.async, deferred completion).
// acc += x*w (single fp16 term). Stage = [A 28K][B 16K], NSTAGE=3.
template <int NC>
__global__ __launch_bounds__(512, 1)
void mma_conv(const __half* __restrict__ Xh, const int* __restrict__ nbr,
              const char* __restrict__ Bg,
              __half* __restrict__ out, float* __restrict__ part, int n) {
  constexpr int CIN    = NC * 64;
  constexpr int STEPS  = KTAPS * NC;
  extern __shared__ char dsm_raw[];
  char* dsm = (char*)(((uintptr_t)dsm_raw + 127) & ~(uintptr_t)127);
  __shared__ int idx_s[MT * KTAPS];

  const int t = threadIdx.x, lane = t & 31, wid = t >> 5;
  const int n0 = blockIdx.x * MT;

  for (int i = t; i < MT * KTAPS; i += 512) {
    int row = n0 + i / KTAPS;
    idx_s[i] = (row < n) ? nbr[(size_t)row * KTAPS + (i % KTAPS)] : 0;
  }
  __syncthreads();

  const uint32_t Du = smem_u32(dsm);
  // barrier ids: FULL(b) = 1+b (1..3), FREE(b) = 4+b (4..6), epilogue = 7

  if (wid >= 14) {
    // ======================= producer =======================
    const int pr = t - 448;                  // 0..63
    for (int s = 0; s < STEPS; s++) {
      const int b = s % NSTAGE;
      if (s >= NSTAGE) BAR_SYNC(4 + b);
      int tap = s / NC, ch = s % NC;
      // A rows pr, pr+64, pr+128, pr+192 (< MT)
      for (int row = pr; row < MT; row += 64) {
        const uint32_t r7 = (uint32_t)(row & 7);
        int src = idx_s[row * KTAPS + tap];
        const char* sh = (const char*)(Xh + (size_t)src * CIN + ch * 64);
        uint32_t dh = Du + b * STAGE + row * 128;
#pragma unroll
        for (uint32_t d = 0; d < 8; d++)
          CP16(dh + d * 16, sh + (d ^ r7) * 16);
      }
      // B rows pr, pr+64 (pre-swizzled: verbatim copy)
      for (int row = pr; row < 128; row += 64) {
        const char* sb = Bg + (size_t)s * BTILE + row * 128;
        uint32_t db = Du + b * STAGE + ATILE + row * 128;
#pragma unroll
        for (uint32_t d = 0; d < 8; d++)
          CP16(db + d * 16, sb + d * 16);
      }
      asm volatile("cp.async.commit_group;" ::: "memory");
      if (s >= 1) {
        asm volatile("cp.async.wait_group 1;" ::: "memory");
        BAR_ARRIVE(1 + (s - 1) % NSTAGE);
      }
    }
    asm volatile("cp.async.wait_group 0;" ::: "memory");
    BAR_ARRIVE(1 + (STEPS - 1) % NSTAGE);
    return;   // producers done
  }

  // ======================= consumer =======================
  const int wm = wid % 7, wn = wid / 7;     // 7 row-tiles x 2 col-halves
  const int aRowL = lane & 15, aKh = lane >> 4;
  const int bRowL = ((lane >> 4) << 3) | (lane & 7);
  const int bKh   = (lane >> 3) & 1;

  float acc[2][8][4];
#pragma unroll
  for (int m = 0; m < 2; m++)
#pragma unroll
    for (int f = 0; f < 8; f++)
#pragma unroll
      for (int q = 0; q < 4; q++) acc[m][f][q] = 0.f;

  uint32_t ah[2][2][4], bb[2][16];

  for (int s = 0; s < STEPS; s++) {
    const int b = s % NSTAGE;
    const uint32_t AHu = Du + b * STAGE, Bu = AHu + ATILE;
    BAR_SYNC(1 + b);

#define LDFRAG(ks, pb)                                                      \
    {                                                                       \
      uint32_t cbase = 2 * (ks);                                            \
      _Pragma("unroll")                                                     \
      for (int mt = 0; mt < 2; mt++) {                                      \
        uint32_t row = wm * 32 + mt * 16 + aRowL;                           \
        uint32_t off = row * 128 + swz16(cbase + aKh, row & 7) * 16;        \
        ldsm4(ah[pb][mt], AHu + off);                                       \
      }                                                                     \
      _Pragma("unroll")                                                     \
      for (int i = 0; i < 4; i++) {                                         \
        uint32_t row = wn * 64 + i * 16 + bRowL;                            \
        uint32_t off = row * 128 + swz16(cbase + bKh, row & 7) * 16;        \
        ldsm4(&bb[pb][i * 4], Bu + off);                                    \
      }                                                                     \
    }

    LDFRAG(0, 0);
#pragma unroll
    for (int ks = 0; ks < 4; ks++) {
      const int cur = ks & 1;
      if (ks < 3) {
        LDFRAG(ks + 1, cur ^ 1);
      } else {
        BAR_ARRIVE(4 + b);   // all stage data now in registers
      }
#pragma unroll
      for (int mt = 0; mt < 2; mt++)
#pragma unroll
        for (int f = 0; f < 8; f++)
          mma_f16(acc[mt][f], ah[cur][mt], &bb[cur][f * 2]);
    }
#undef LDFRAG
  }

  // ---- epilogue 1: fragment regs -> gmem (fp16) ----
#pragma unroll
  for (int mt = 0; mt < 2; mt++)
#pragma unroll
    for (int f = 0; f < 8; f++) {
      int row = n0 + wm * 32 + mt * 16 + (lane >> 2);
      int col = wn * 64 + f * 8 + 2 * (lane & 3);
      if (row < n)
        *(__half2*)&out[(size_t)row * COUT + col] =
            __floats2half2_rn(acc[mt][f][0], acc[mt][f][1]);
      if (row + 8 < n)
        *(__half2*)&out[(size_t)(row + 8) * COUT + col] =
            __floats2half2_rn(acc[mt][f][2], acc[mt][f][3]);
    }

  // ---- epilogue 2: fused BN-stat partials (masked, deterministic) ----
  {
    int r0 = n0 + wm * 32 + (lane >> 2);
    bool vA0 = r0 < n, vA1 = r0 + 8 < n;        // mt = 0
    bool vB0 = r0 + 16 < n, vB1 = r0 + 24 < n;  // mt = 1
    float sums[8][2], sqs[8][2];
#pragma unroll
    for (int f = 0; f < 8; f++)
#pragma unroll
      for (int e = 0; e < 2; e++) {
        float a0 = vA0 ? acc[0][f][e] : 0.f;
        float a1 = vA1 ? acc[0][f][e + 2] : 0.f;
        float b0 = vB0 ? acc[1][f][e] : 0.f;
        float b1 = vB1 ? acc[1][f][e + 2] : 0.f;
        sums[f][e] = a0 + a1 + b0 + b1;
        sqs[f][e]  = a0 * a0 + a1 * a1 + b0 * b0 + b1 * b1;
      }
#pragma unroll
    for (int off = 4; off < 32; off <<= 1)
#pragma unroll
      for (int f = 0; f < 8; f++)
#pragma unroll
        for (int e = 0; e < 2; e++) {
          sums[f][e] += __shfl_down_sync(0xffffffffu, sums[f][e], off);
          sqs[f][e]  += __shfl_down_sync(0xffffffffu, sqs[f][e],  off);
        }
    float* S = (float*)dsm;          // [7][128]
    float* Q = S + 896;              // [7][128]
    if (lane < 4) {
#pragma unroll
      for (int f = 0; f < 8; f++)
#pragma unroll
        for (int e = 0; e < 2; e++) {
          int col = wn * 64 + f * 8 + 2 * lane + e;
          S[wm * 128 + col] = sums[f][e];
          Q[wm * 128 + col] = sqs[f][e];
        }
    }
    asm volatile("bar.sync 7, 448;" ::: "memory");
    if (t < 128) {
      float s = 0.f, q = 0.f;
#pragma unroll
      for (int g = 0; g < 7; g++) {
        s += S[g * 128 + t];
        q += Q[g * 128 + t];
      }
      part[(size_t)blockIdx.x * 256 + t] = s;
      part[(size_t)blockIdx.x * 256 + 128 + t] = q;
    }
  }
}

// single-block finalize over block partials (deterministic)
__global__ void stats_final_conv(const float* __restrict__ part, int nb,
                                 const float* __restrict__ g,
                                 const float* __restrict__ bta,
                                 float* __restrict__ st, int n) {
  int c = threadIdx.x;   // 128
  float s = 0.f, q = 0.f;
  for (int b = 0; b < nb; b++) {
    s += part[(size_t)b * 256 + c];
    q += part[(size_t)b * 256 + 128 + c];
  }
  float mu  = s / (float)n;
  float var = q / (float)n - mu * mu;
  float sc  = g[c] * rsqrtf(var + 1e-5f);
  st[c]        = sc;
  st[COUT + c] = bta[c] - mu * sc;
}

// ------------------------- downsample (persistent, fused stats) ----------------
__global__ void pack_w(const float* __restrict__ W, float2* __restrict__ Wp,
                       int KT, int CIN) {
  int total = KT * (CIN / 2) * COUT;
  for (int i = blockIdx.x * blockDim.x + threadIdx.x; i < total;
       i += gridDim.x * blockDim.x) {
    int c  = i % COUT;
    int cp = (i / COUT) % (CIN / 2);
    int k  = i / (COUT * (CIN / 2));
    Wp[i] = make_float2(W[((size_t)k * CIN + 2 * cp) * COUT + c],
                        W[((size_t)k * CIN + 2 * cp + 1) * COUT + c]);
  }
}

__global__ __launch_bounds__(256, 2)
void dconv_kernel(const float* __restrict__ X, const float2* __restrict__ Wp,
                  float* __restrict__ out, float* __restrict__ part, int n) {
  constexpr int CIN = CIN1;
  constexpr int STRIDE = CIN + 8;
  __shared__ float xs[64 * STRIDE];
  __shared__ float S[8][128], Q[8][128];
  const int t = threadIdx.x;
  const int tcol = t & 31, trow = t >> 5;
  const int c0 = tcol * 4, p0 = trow * 8;
  const int r = t >> 2, seg = t & 3;
  const unsigned long long* wrow = (const unsigned long long*)Wp;

  float csum[4] = {0.f, 0.f, 0.f, 0.f};
  float csq[4]  = {0.f, 0.f, 0.f, 0.f};

  for (int n0 = blockIdx.x * 64; n0 < n; n0 += DGRID * 64) {
    {
      int src = n0 + r;
      if (src >= n) src = n - 1;
      const float4* rp = (const float4*)(X + (size_t)src * CIN);
#pragma unroll
      for (int j = 0; j < CIN / 16; j++)
        *(float4*)&xs[r * STRIDE + (seg + 4 * j) * 4] = rp[seg + 4 * j];
    }
    __syncthreads();
    unsigned long long acc[8][4];
#pragma unroll
    for (int p = 0; p < 8; p++)
#pragma unroll
      for (int i = 0; i < 4; i++) acc[p][i] = 0ull;
#pragma unroll 2
    for (int cp = 0; cp < CIN / 2; cp += 2) {
      const unsigned long long* wb0 = wrow + (size_t)cp * COUT + c0;
      const unsigned long long* wb1 = wrow + (size_t)(cp + 1) * COUT + c0;
      ulonglong2 wa = *(const ulonglong2*)wb0, wa2 = *(const ulonglong2*)(wb0 + 2);
      ulonglong2 wc = *(const ulonglong2*)wb1, wc2 = *(const ulonglong2*)(wb1 + 2);
#pragma unroll
      for (int p = 0; p < 8; p++) {
        ulonglong2 xv = *(const ulonglong2*)&xs[(p0 + p) * STRIDE + 2 * cp];
        acc[p][0] = fma2(xv.x, wa.x,  acc[p][0]);
        acc[p][1] = fma2(xv.x, wa.y,  acc[p][1]);
        acc[p][2] = fma2(xv.x, wa2.x, acc[p][2]);
        acc[p][3] = fma2(xv.x, wa2.y, acc[p][3]);
        acc[p][0] = fma2(xv.y, wc.x,  acc[p][0]);
        acc[p][1] = fma2(xv.y, wc.y,  acc[p][1]);
        acc[p][2] = fma2(xv.y, wc2.x, acc[p][2]);
        acc[p][3] = fma2(xv.y, wc2.y, acc[p][3]);
      }
    }
#pragma unroll
    for (int p = 0; p < 8; p++) {
      int np = n0 + p0 + p;
      if (np < n) {
        float2 a0 = *(float2*)&acc[p][0], a1 = *(float2*)&acc[p][1];
        float2 a2 = *(float2*)&acc[p][2], a3 = *(float2*)&acc[p][3];
        float4 o = make_float4(a0.x + a0.y, a1.x + a1.y, a2.x + a2.y, a3.x + a3.y);
        *(float4*)&out[(size_t)np * COUT + c0] = o;
        csum[0] += o.x; csum[1] += o.y; csum[2] += o.z; csum[3] += o.w;
        csq[0] += o.x * o.x; csq[1] += o.y * o.y;
        csq[2] += o.z * o.z; csq[3] += o.w * o.w;
      }
    }
    __syncthreads();
  }

  // fused BN-stat partials
#pragma unroll
  for (int j = 0; j < 4; j++) {
    S[trow][c0 + j] = csum[j];
    Q[trow][c0 + j] = csq[j];
  }
  __syncthreads();
  if (t < 128) {
    float s = 0.f, q = 0.f;
#pragma unroll
    for (int g = 0; g < 8; g++) {
      s += S[g][t];
      q += Q[g][t];
    }
    part[(size_t)blockIdx.x * 256 + t] = s;
    part[(size_t)blockIdx.x * 256 + 128 + t] = q;
  }
}

__global__ void final_add(const __half* __restrict__ h2,
                          const float* __restrict__ res,
                          const float* __restrict__ st2,
                          const float* __restrict__ std_,
                          float* __restrict__ out, int n) {
  int i = blockIdx.x * blockDim.x + threadIdx.x;
  int total = n * (COUT / 4);
  if (i < total) {
    int c0 = (i & (COUT / 4 - 1)) * 4;
    uint2 raw = ((const uint2*)h2)[i];
    __half2 ha = *(__half2*)&raw.x, hb = *(__half2*)&raw.y;
    float4 h = make_float4(__low2float(ha), __high2float(ha),
                           __low2float(hb), __high2float(hb));
    float4 r = ((const float4*)res)[i];
    float4 s2 = *(const float4*)&st2[c0];
    float4 t2 = *(const float4*)&st2[COUT + c0];
    float4 sd = *(const float4*)&std_[c0];
    float4 td = *(const float4*)&std_[COUT + c0];
    float4 o;
    o.x = fmaxf(0.f, h.x * s2.x + t2.x) + (r.x * sd.x + td.x);
    o.y = fmaxf(0.f, h.y * s2.y + t2.y) + (r.y * sd.y + td.y);
    o.z = fmaxf(0.f, h.z * s2.z + t2.z) + (r.z * sd.z + td.z);
    o.w = fmaxf(0.f, h.w * s2.w + t2.w) + (r.w * sd.w + td.w);
    ((float4*)out)[i] = o;
  }
}

extern "C" void kernel_launch(void* const* d_in, const int* in_sizes, int n_in,
                              void* d_out, int out_size) {
  const float* x   = (const float*)d_in[0];
  const int*   nbr = (const int*)d_in[1];   // JAX x64 disabled -> int32
  const float* W1  = (const float*)d_in[2];
  const float* g1  = (const float*)d_in[3];
  const float* b1  = (const float*)d_in[4];
  const float* W2  = (const float*)d_in[5];
  const float* g2  = (const float*)d_in[6];
  const float* b2  = (const float*)d_in[7];
  const float* Wd  = (const float*)d_in[8];
  const float* gd  = (const float*)d_in[9];
  const float* bd  = (const float*)d_in[10];
  float*       out = (float*)d_out;
  const int n = in_sizes[0] / CIN1;

  float *res, *part, *st;
  float2* Wdp;
  char *B1, *B2;
  __half *h1, *h2, *X1h, *X2h;
  cudaGetSymbolAddress((void**)&h1,  g_h1);
  cudaGetSymbolAddress((void**)&h2,  g_h2);
  cudaGetSymbolAddress((void**)&res, g_res);
  cudaGetSymbolAddress((void**)&B1,  g_B1);
  cudaGetSymbolAddress((void**)&B2,  g_B2);
  cudaGetSymbolAddress((void**)&X1h, g_X1h);
  cudaGetSymbolAddress((void**)&X2h, g_X2h);
  cudaGetSymbolAddress((void**)&Wdp, g_Wdp);
  cudaGetSymbolAddress((void**)&part, g_part);
  cudaGetSymbolAddress((void**)&st,  g_st);

  const int smem = NSTAGE * STAGE + 256;   // 135424 B
  cudaFuncSetAttribute(mma_conv<1>,
                       cudaFuncAttributeMaxDynamicSharedMemorySize, smem);
  cudaFuncSetAttribute(mma_conv<2>,
                       cudaFuncAttributeMaxDynamicSharedMemorySize, smem);

  pack_w_f16<<<432, 256>>>(W1, B1, KTAPS, CIN1);
  pack_w_f16<<<864, 256>>>(W2, B2, KTAPS, COUT);
  pack_w<<<16, 256>>>(Wd, Wdp, 1, CIN1);

  const int nbm = (n + MT - 1) / MT;

  // pre-convert x -> fp16
  const int t41 = n * CIN1 / 4;
  conv_f16<<<(t41 + 255) / 256, 256>>>(x, X1h, t41);

  // conv1 (fp16) -> h1pre (fp16) + fused bn1 partials; finalize bn1
  mma_conv<1><<<nbm, 512, smem>>>(X1h, nbr, B1, h1, part, n);
  stats_final_conv<<<1, 128>>>(part, nbm, g1, b1, st + 0, n);

  // downsample branch: respre = x @ Wd (persistent, fused bn_d partials)
  dconv_kernel<<<DGRID, 256>>>(x, Wdp, res, part, n);
  stats_final_conv<<<1, 128>>>(part, DGRID, gd, bd, st + 2 * COUT, n);

  // h1 -> relu(bn1(h1)) -> fp16
  const int t42 = n * COUT / 4;
  conv_bn_f16<<<(t42 + 255) / 256, 256>>>(h1, st + 0, X2h, t42);

  // conv2 (fp16) -> h2pre (fp16) + fused bn2 partials; finalize bn2
  mma_conv<2><<<nbm, 512, smem>>>(X2h, nbr, B2, h2, part, n);
  stats_final_conv<<<1, 128>>>(part, nbm, g2, b2, st + 4 * COUT, n);

  // out = relu(bn2(h2pre)) + bn_d(respre)
  final_add<<<(t42 + 255) / 256, 256>>>(h2, res, st + 4 * COUT, st + 2 * COUT,
                                        out, n);
}

// round 17
// speedup vs baseline: 8.3154x; 1.0619x over previous
#include <cuda_runtime.h>
#include <cuda_fp16.h>
#include <cstdint>

#define CIN1  64
#define COUT  128
#define KTAPS 27
#define NMAX  131072
#define MT    224              // rows per conv block (7 x 32)
#define ATILE (MT * 128)       // 28672
#define BTILE 16384
#define STAGE (ATILE + BTILE)  // 45056
#define NSTAGE 4
#define DGRID 304              // persistent dconv grid (2/SM)

// ---- scratch (static device globals; no allocation in kernel_launch) ----
__device__ __half g_h1[(size_t)NMAX * COUT];
__device__ __half g_h2[(size_t)NMAX * COUT];
__device__ __half g_res[(size_t)NMAX * COUT];
__device__ __half g_X1h[(size_t)NMAX * CIN1];
__device__ __half g_X2h[(size_t)NMAX * COUT];
// pre-swizzled fp16 weight tiles: [step = tap*NC+chunk][128 rows][64 f16]
__device__ __align__(16) char g_B1[KTAPS * 1 * BTILE];
__device__ __align__(16) char g_B2[KTAPS * 2 * BTILE];
__device__ float2 g_Wdp[(CIN1 / 2) * COUT];
__device__ float  g_part[1024 * 256];
__device__ float  g_st[6 * COUT];   // [s1|t1|sd|td|s2|t2]

// ------------------------- helpers -------------------------
__device__ __forceinline__ uint32_t smem_u32(const void* p) {
  uint32_t a;
  asm("{ .reg .u64 t; cvta.to.shared.u64 t, %1; cvt.u32.u64 %0, t; }"
      : "=r"(a) : "l"(p));
  return a;
}
__device__ __forceinline__ unsigned long long fma2(unsigned long long a,
                                                   unsigned long long b,
                                                   unsigned long long c) {
  unsigned long long d;
  asm("fma.rn.f32x2 %0, %1, %2, %3;" : "=l"(d) : "l"(a), "l"(b), "l"(c));
  return d;
}
__device__ __forceinline__ void ldsm4(uint32_t* r, uint32_t addr) {
  asm volatile("ldmatrix.sync.aligned.m8n8.x4.shared.b16 {%0,%1,%2,%3}, [%4];"
               : "=r"(r[0]), "=r"(r[1]), "=r"(r[2]), "=r"(r[3]) : "r"(addr));
}
__device__ __forceinline__ void mma_f16(float* c, const uint32_t* a,
                                        const uint32_t* b) {
  asm volatile(
      "mma.sync.aligned.m16n8k16.row.col.f32.f16.f16.f32 "
      "{%0,%1,%2,%3}, {%4,%5,%6,%7}, {%8,%9}, {%0,%1,%2,%3};"
      : "+f"(c[0]), "+f"(c[1]), "+f"(c[2]), "+f"(c[3])
      : "r"(a[0]), "r"(a[1]), "r"(a[2]), "r"(a[3]), "r"(b[0]), "r"(b[1]));
}
// 16B-chunk XOR swizzle inside a 128B row
__device__ __host__ __forceinline__ uint32_t swz16(uint32_t c, uint32_t r7) {
  return (c & ~7u) | ((c ^ r7) & 7u);
}
#define BAR_SYNC(id)   asm volatile("bar.sync %0, 512;"   :: "r"(id) : "memory")
#define BAR_ARRIVE(id) asm volatile("bar.arrive %0, 512;" :: "r"(id) : "memory")
#define CP16(dst, src) \
  asm volatile("cp.async.cg.shared.global [%0], [%1], 16;" \
               :: "r"(dst), "l"(src))

// ------------------------- weight packing -------------------------
__global__ void pack_w_f16(const float* __restrict__ W, char* __restrict__ B,
                           int KT, int CIN) {
  int NC = CIN / 64;
  int total = KT * CIN * COUT;
  for (int i = blockIdx.x * blockDim.x + threadIdx.x; i < total;
       i += gridDim.x * blockDim.x) {
    int cout = i % COUT;
    int cin  = (i / COUT) % CIN;
    int k    = i / (COUT * CIN);
    float v = W[((size_t)k * CIN + cin) * COUT + cout];
    int step = k * NC + (cin >> 6);
    uint32_t e = (uint32_t)cin & 63;
    uint32_t off = (uint32_t)cout * 128 + swz16(e >> 3, cout & 7) * 16 +
                   (e & 7) * 2;
    *(__half*)(B + (size_t)step * BTILE + off) = __float2half_rn(v);
  }
}

// ------------------------- fp16 convert passes -------------------------
__global__ void conv_f16(const float* __restrict__ X, __half* __restrict__ Xh,
                         int total4) {
  int i = blockIdx.x * blockDim.x + threadIdx.x;
  if (i < total4) {
    float4 v = ((const float4*)X)[i];
    __half2 h0 = __floats2half2_rn(v.x, v.y);
    __half2 h1 = __floats2half2_rn(v.z, v.w);
    ((uint2*)Xh)[i] = make_uint2(*(uint32_t*)&h0, *(uint32_t*)&h1);
  }
}

// h1 (fp16) -> relu(bn1(h1)) -> fp16
__global__ void conv_bn_f16(const __half* __restrict__ H,
                            const float* __restrict__ st,
                            __half* __restrict__ Xh, int total4) {
  int i = blockIdx.x * blockDim.x + threadIdx.x;
  if (i < total4) {
    int c0 = (i & 31) * 4;   // channel of first element (COUT=128)
    uint2 raw = ((const uint2*)H)[i];
    __half2 a = *(__half2*)&raw.x, b = *(__half2*)&raw.y;
    float4 v = make_float4(__low2float(a), __high2float(a),
                           __low2float(b), __high2float(b));
    float4 sc = *(const float4*)&st[c0];
    float4 tb = *(const float4*)&st[COUT + c0];
    v.x = fmaxf(0.f, v.x * sc.x + tb.x);
    v.y = fmaxf(0.f, v.y * sc.y + tb.y);
    v.z = fmaxf(0.f, v.z * sc.z + tb.z);
    v.w = fmaxf(0.f, v.w * sc.w + tb.w);
    __half2 h0 = __floats2half2_rn(v.x, v.y);
    __half2 h1 = __floats2half2_rn(v.z, v.w);
    ((uint2*)Xh)[i] = make_uint2(*(uint32_t*)&h0, *(uint32_t*)&h1);
  }
}

// ------------------------- warp-specialized fp16 mma gathered conv -------------
// 512 threads: warps 0-13 = consumers (MMA + fused BN-stat partials, 224 rows),
// warps 14-15 = producers (pure cp.async, deferred completion).
// One pipeline step = one K=64 chunk (R15-proven structure). Stage=[A 28K][B 16K].
// NSTAGE=4. Barrier ids: FULL(b)=1+b (1..4), FREE(b)=5+b (5..8), epilogue=9.
template <int NC>
__global__ __launch_bounds__(512, 1)
void mma_conv(const __half* __restrict__ Xh, const int* __restrict__ nbr,
              const char* __restrict__ Bg,
              __half* __restrict__ out, float* __restrict__ part, int n) {
  constexpr int CIN    = NC * 64;
  constexpr int STEPS  = KTAPS * NC;
  extern __shared__ char dsm_raw[];
  char* dsm = (char*)(((uintptr_t)dsm_raw + 127) & ~(uintptr_t)127);
  __shared__ int idx_s[MT * KTAPS];

  const int t = threadIdx.x, lane = t & 31, wid = t >> 5;
  const int n0 = blockIdx.x * MT;

  for (int i = t; i < MT * KTAPS; i += 512) {
    int row = n0 + i / KTAPS;
    idx_s[i] = (row < n) ? nbr[(size_t)row * KTAPS + (i % KTAPS)] : 0;
  }
  __syncthreads();

  const uint32_t Du = smem_u32(dsm);

  if (wid >= 14) {
    // ======================= producer =======================
    const int pr = t - 448;                  // 0..63
    for (int s = 0; s < STEPS; s++) {
      const int b = s % NSTAGE;
      if (s >= NSTAGE) BAR_SYNC(5 + b);
      int tap = s / NC, ch = s % NC;
      // A rows pr, pr+64, pr+128, pr+192 (< MT)
      for (int row = pr; row < MT; row += 64) {
        const uint32_t r7 = (uint32_t)(row & 7);
        int src = idx_s[row * KTAPS + tap];
        const char* sh = (const char*)(Xh + (size_t)src * CIN + ch * 64);
        uint32_t dh = Du + b * STAGE + row * 128;
#pragma unroll
        for (uint32_t d = 0; d < 8; d++)
          CP16(dh + d * 16, sh + (d ^ r7) * 16);
      }
      // B rows pr, pr+64 (pre-swizzled: verbatim copy)
      for (int row = pr; row < 128; row += 64) {
        const char* sb = Bg + (size_t)s * BTILE + row * 128;
        uint32_t db = Du + b * STAGE + ATILE + row * 128;
#pragma unroll
        for (uint32_t d = 0; d < 8; d++)
          CP16(db + d * 16, sb + d * 16);
      }
      asm volatile("cp.async.commit_group;" ::: "memory");
      if (s >= 1) {
        asm volatile("cp.async.wait_group 1;" ::: "memory");
        BAR_ARRIVE(1 + (s - 1) % NSTAGE);
      }
    }
    asm volatile("cp.async.wait_group 0;" ::: "memory");
    BAR_ARRIVE(1 + (STEPS - 1) % NSTAGE);
    return;   // producers done
  }

  // ======================= consumer =======================
  const int wm = wid % 7, wn = wid / 7;     // 7 row-tiles x 2 col-halves
  const int aRowL = lane & 15, aKh = lane >> 4;
  const int bRowL = ((lane >> 4) << 3) | (lane & 7);
  const int bKh   = (lane >> 3) & 1;

  float acc[2][8][4];
#pragma unroll
  for (int m = 0; m < 2; m++)
#pragma unroll
    for (int f = 0; f < 8; f++)
#pragma unroll
      for (int q = 0; q < 4; q++) acc[m][f][q] = 0.f;

  uint32_t ah[2][2][4], bb[2][16];

  for (int s = 0; s < STEPS; s++) {
    const int b = s % NSTAGE;
    const uint32_t AHu = Du + b * STAGE, Bu = AHu + ATILE;
    BAR_SYNC(1 + b);

#define LDFRAG(ks, pb)                                                      \
    {                                                                       \
      uint32_t cbase = 2 * (ks);                                            \
      _Pragma("unroll")                                                     \
      for (int mt = 0; mt < 2; mt++) {                                      \
        uint32_t row = wm * 32 + mt * 16 + aRowL;                           \
        uint32_t off = row * 128 + swz16(cbase + aKh, row & 7) * 16;        \
        ldsm4(ah[pb][mt], AHu + off);                                       \
      }                                                                     \
      _Pragma("unroll")                                                     \
      for (int i = 0; i < 4; i++) {                                         \
        uint32_t row = wn * 64 + i * 16 + bRowL;                            \
        uint32_t off = row * 128 + swz16(cbase + bKh, row & 7) * 16;        \
        ldsm4(&bb[pb][i * 4], Bu + off);                                    \
      }                                                                     \
    }

    LDFRAG(0, 0);
#pragma unroll
    for (int ks = 0; ks < 4; ks++) {
      const int cur = ks & 1;
      if (ks < 3) {
        LDFRAG(ks + 1, cur ^ 1);
      } else {
        BAR_ARRIVE(5 + b);   // all stage data now in registers
      }
#pragma unroll
      for (int mt = 0; mt < 2; mt++)
#pragma unroll
        for (int f = 0; f < 8; f++)
          mma_f16(acc[mt][f], ah[cur][mt], &bb[cur][f * 2]);
    }
#undef LDFRAG
  }

  // ---- epilogue 1: fragment regs -> gmem (fp16) ----
#pragma unroll
  for (int mt = 0; mt < 2; mt++)
#pragma unroll
    for (int f = 0; f < 8; f++) {
      int row = n0 + wm * 32 + mt * 16 + (lane >> 2);
      int col = wn * 64 + f * 8 + 2 * (lane & 3);
      if (row < n)
        *(__half2*)&out[(size_t)row * COUT + col] =
            __floats2half2_rn(acc[mt][f][0], acc[mt][f][1]);
      if (row + 8 < n)
        *(__half2*)&out[(size_t)(row + 8) * COUT + col] =
            __floats2half2_rn(acc[mt][f][2], acc[mt][f][3]);
    }

  // ---- epilogue 2: fused BN-stat partials (masked, deterministic) ----
  {
    int r0 = n0 + wm * 32 + (lane >> 2);
    bool vA0 = r0 < n, vA1 = r0 + 8 < n;        // mt = 0
    bool vB0 = r0 + 16 < n, vB1 = r0 + 24 < n;  // mt = 1
    float sums[8][2], sqs[8][2];
#pragma unroll
    for (int f = 0; f < 8; f++)
#pragma unroll
      for (int e = 0; e < 2; e++) {
        float a0 = vA0 ? acc[0][f][e] : 0.f;
        float a1 = vA1 ? acc[0][f][e + 2] : 0.f;
        float b0 = vB0 ? acc[1][f][e] : 0.f;
        float b1 = vB1 ? acc[1][f][e + 2] : 0.f;
        sums[f][e] = a0 + a1 + b0 + b1;
        sqs[f][e]  = a0 * a0 + a1 * a1 + b0 * b0 + b1 * b1;
      }
#pragma unroll
    for (int off = 4; off < 32; off <<= 1)
#pragma unroll
      for (int f = 0; f < 8; f++)
#pragma unroll
        for (int e = 0; e < 2; e++) {
          sums[f][e] += __shfl_down_sync(0xffffffffu, sums[f][e], off);
          sqs[f][e]  += __shfl_down_sync(0xffffffffu, sqs[f][e],  off);
        }
    float* S = (float*)dsm;          // [7][128]
    float* Q = S + 896;              // [7][128]
    if (lane < 4) {
#pragma unroll
      for (int f = 0; f < 8; f++)
#pragma unroll
        for (int e = 0; e < 2; e++) {
          int col = wn * 64 + f * 8 + 2 * lane + e;
          S[wm * 128 + col] = sums[f][e];
          Q[wm * 128 + col] = sqs[f][e];
        }
    }
    asm volatile("bar.sync 9, 448;" ::: "memory");
    if (t < 128) {
      float s = 0.f, q = 0.f;
#pragma unroll
      for (int g = 0; g < 7; g++) {
        s += S[g * 128 + t];
        q += Q[g * 128 + t];
      }
      part[(size_t)blockIdx.x * 256 + t] = s;
      part[(size_t)blockIdx.x * 256 + 128 + t] = q;
    }
  }
}

// parallel finalize over block partials (deterministic: fixed slice order)
__global__ void stats_final_conv(const float* __restrict__ part, int nb,
                                 const float* __restrict__ g,
                                 const float* __restrict__ bta,
                                 float* __restrict__ st, int n) {
  __shared__ float S[4][128], Q[4][128];
  int t = threadIdx.x;          // 512
  int c = t & 127, sl = t >> 7; // 4 slices
  float s = 0.f, q = 0.f;
  for (int b = sl; b < nb; b += 4) {
    s += part[(size_t)b * 256 + c];
    q += part[(size_t)b * 256 + 128 + c];
  }
  S[sl][c] = s;
  Q[sl][c] = q;
  __syncthreads();
  if (t < 128) {
    float ss = S[0][t] + S[1][t] + S[2][t] + S[3][t];
    float qq = Q[0][t] + Q[1][t] + Q[2][t] + Q[3][t];
    float mu  = ss / (float)n;
    float var = qq / (float)n - mu * mu;
    float sc  = g[t] * rsqrtf(var + 1e-5f);
    st[t]        = sc;
    st[COUT + t] = bta[t] - mu * sc;
  }
}

// ------------------------- downsample (persistent, fused stats) ----------------
__global__ void pack_w(const float* __restrict__ W, float2* __restrict__ Wp,
                       int KT, int CIN) {
  int total = KT * (CIN / 2) * COUT;
  for (int i = blockIdx.x * blockDim.x + threadIdx.x; i < total;
       i += gridDim.x * blockDim.x) {
    int c  = i % COUT;
    int cp = (i / COUT) % (CIN / 2);
    int k  = i / (COUT * (CIN / 2));
    Wp[i] = make_float2(W[((size_t)k * CIN + 2 * cp) * COUT + c],
                        W[((size_t)k * CIN + 2 * cp + 1) * COUT + c]);
  }
}

__global__ __launch_bounds__(256, 2)
void dconv_kernel(const float* __restrict__ X, const float2* __restrict__ Wp,
                  __half* __restrict__ out, float* __restrict__ part, int n) {
  constexpr int CIN = CIN1;
  constexpr int STRIDE = CIN + 8;
  __shared__ float xs[64 * STRIDE];
  __shared__ float S[8][128], Q[8][128];
  const int t = threadIdx.x;
  const int tcol = t & 31, trow = t >> 5;
  const int c0 = tcol * 4, p0 = trow * 8;
  const int r = t >> 2, seg = t & 3;
  const unsigned long long* wrow = (const unsigned long long*)Wp;

  float csum[4] = {0.f, 0.f, 0.f, 0.f};
  float csq[4]  = {0.f, 0.f, 0.f, 0.f};

  for (int n0 = blockIdx.x * 64; n0 < n; n0 += DGRID * 64) {
    {
      int src = n0 + r;
      if (src >= n) src = n - 1;
      const float4* rp = (const float4*)(X + (size_t)src * CIN);
#pragma unroll
      for (int j = 0; j < CIN / 16; j++)
        *(float4*)&xs[r * STRIDE + (seg + 4 * j) * 4] = rp[seg + 4 * j];
    }
    __syncthreads();
    unsigned long long acc[8][4];
#pragma unroll
    for (int p = 0; p < 8; p++)
#pragma unroll
      for (int i = 0; i < 4; i++) acc[p][i] = 0ull;
#pragma unroll 2
    for (int cp = 0; cp < CIN / 2; cp += 2) {
      const unsigned long long* wb0 = wrow + (size_t)cp * COUT + c0;
      const unsigned long long* wb1 = wrow + (size_t)(cp + 1) * COUT + c0;
      ulonglong2 wa = *(const ulonglong2*)wb0, wa2 = *(const ulonglong2*)(wb0 + 2);
      ulonglong2 wc = *(const ulonglong2*)wb1, wc2 = *(const ulonglong2*)(wb1 + 2);
#pragma unroll
      for (int p = 0; p < 8; p++) {
        ulonglong2 xv = *(const ulonglong2*)&xs[(p0 + p) * STRIDE + 2 * cp];
        acc[p][0] = fma2(xv.x, wa.x,  acc[p][0]);
        acc[p][1] = fma2(xv.x, wa.y,  acc[p][1]);
        acc[p][2] = fma2(xv.x, wa2.x, acc[p][2]);
        acc[p][3] = fma2(xv.x, wa2.y, acc[p][3]);
        acc[p][0] = fma2(xv.y, wc.x,  acc[p][0]);
        acc[p][1] = fma2(xv.y, wc.y,  acc[p][1]);
        acc[p][2] = fma2(xv.y, wc2.x, acc[p][2]);
        acc[p][3] = fma2(xv.y, wc2.y, acc[p][3]);
      }
    }
#pragma unroll
    for (int p = 0; p < 8; p++) {
      int np = n0 + p0 + p;
      if (np < n) {
        float2 a0 = *(float2*)&acc[p][0], a1 = *(float2*)&acc[p][1];
        float2 a2 = *(float2*)&acc[p][2], a3 = *(float2*)&acc[p][3];
        float4 o = make_float4(a0.x + a0.y, a1.x + a1.y, a2.x + a2.y, a3.x + a3.y);
        __half2 o0 = __floats2half2_rn(o.x, o.y);
        __half2 o1 = __floats2half2_rn(o.z, o.w);
        *(uint2*)&out[(size_t)np * COUT + c0] =
            make_uint2(*(uint32_t*)&o0, *(uint32_t*)&o1);
        csum[0] += o.x; csum[1] += o.y; csum[2] += o.z; csum[3] += o.w;
        csq[0] += o.x * o.x; csq[1] += o.y * o.y;
        csq[2] += o.z * o.z; csq[3] += o.w * o.w;
      }
    }
    __syncthreads();
  }

  // fused BN-stat partials
#pragma unroll
  for (int j = 0; j < 4; j++) {
    S[trow][c0 + j] = csum[j];
    Q[trow][c0 + j] = csq[j];
  }
  __syncthreads();
  if (t < 128) {
    float s = 0.f, q = 0.f;
#pragma unroll
    for (int g = 0; g < 8; g++) {
      s += S[g][t];
      q += Q[g][t];
    }
    part[(size_t)blockIdx.x * 256 + t] = s;
    part[(size_t)blockIdx.x * 256 + 128 + t] = q;
  }
}

__global__ void final_add(const __half* __restrict__ h2,
                          const __half* __restrict__ res,
                          const float* __restrict__ st2,
                          const float* __restrict__ std_,
                          float* __restrict__ out, int n) {
  int i = blockIdx.x * blockDim.x + threadIdx.x;
  int total = n * (COUT / 4);
  if (i < total) {
    int c0 = (i & (COUT / 4 - 1)) * 4;
    uint2 raw = ((const uint2*)h2)[i];
    __half2 ha = *(__half2*)&raw.x, hb = *(__half2*)&raw.y;
    float4 h = make_float4(__low2float(ha), __high2float(ha),
                           __low2float(hb), __high2float(hb));
    uint2 rr = ((const uint2*)res)[i];
    __half2 ra = *(__half2*)&rr.x, rb = *(__half2*)&rr.y;
    float4 r = make_float4(__low2float(ra), __high2float(ra),
                           __low2float(rb), __high2float(rb));
    float4 s2 = *(const float4*)&st2[c0];
    float4 t2 = *(const float4*)&st2[COUT + c0];
    float4 sd = *(const float4*)&std_[c0];
    float4 td = *(const float4*)&std_[COUT + c0];
    float4 o;
    o.x = fmaxf(0.f, h.x * s2.x + t2.x) + (r.x * sd.x + td.x);
    o.y = fmaxf(0.f, h.y * s2.y + t2.y) + (r.y * sd.y + td.y);
    o.z = fmaxf(0.f, h.z * s2.z + t2.z) + (r.z * sd.z + td.z);
    o.w = fmaxf(0.f, h.w * s2.w + t2.w) + (r.w * sd.w + td.w);
    ((float4*)out)[i] = o;
  }
}

extern "C" void kernel_launch(void* const* d_in, const int* in_sizes, int n_in,
                              void* d_out, int out_size) {
  const float* x   = (const float*)d_in[0];
  const int*   nbr = (const int*)d_in[1];   // JAX x64 disabled -> int32
  const float* W1  = (const float*)d_in[2];
  const float* g1  = (const float*)d_in[3];
  const float* b1  = (const float*)d_in[4];
  const float* W2  = (const float*)d_in[5];
  const float* g2  = (const float*)d_in[6];
  const float* b2  = (const float*)d_in[7];
  const float* Wd  = (const float*)d_in[8];
  const float* gd  = (const float*)d_in[9];
  const float* bd  = (const float*)d_in[10];
  float*       out = (float*)d_out;
  const int n = in_sizes[0] / CIN1;

  float *part, *st;
  float2* Wdp;
  char *B1, *B2;
  __half *h1, *h2, *res, *X1h, *X2h;
  cudaGetSymbolAddress((void**)&h1,  g_h1);
  cudaGetSymbolAddress((void**)&h2,  g_h2);
  cudaGetSymbolAddress((void**)&res, g_res);
  cudaGetSymbolAddress((void**)&B1,  g_B1);
  cudaGetSymbolAddress((void**)&B2,  g_B2);
  cudaGetSymbolAddress((void**)&X1h, g_X1h);
  cudaGetSymbolAddress((void**)&X2h, g_X2h);
  cudaGetSymbolAddress((void**)&Wdp, g_Wdp);
  cudaGetSymbolAddress((void**)&part, g_part);
  cudaGetSymbolAddress((void**)&st,  g_st);

  const int smem = NSTAGE * STAGE + 256;   // 180480 B
  cudaFuncSetAttribute(mma_conv<1>,
                       cudaFuncAttributeMaxDynamicSharedMemorySize, smem);
  cudaFuncSetAttribute(mma_conv<2>,
                       cudaFuncAttributeMaxDynamicSharedMemorySize, smem);

  pack_w_f16<<<432, 256>>>(W1, B1, KTAPS, CIN1);
  pack_w_f16<<<864, 256>>>(W2, B2, KTAPS, COUT);
  pack_w<<<16, 256>>>(Wd, Wdp, 1, CIN1);

  const int nbm = (n + MT - 1) / MT;

  // pre-convert x -> fp16
  const int t41 = n * CIN1 / 4;
  conv_f16<<<(t41 + 255) / 256, 256>>>(x, X1h, t41);

  // conv1 (fp16) -> h1pre (fp16) + fused bn1 partials; finalize bn1
  mma_conv<1><<<nbm, 512, smem>>>(X1h, nbr, B1, h1, part, n);
  stats_final_conv<<<1, 512>>>(part, nbm, g1, b1, st + 0, n);

  // downsample branch: respre = x @ Wd (persistent, fused bn_d partials)
  dconv_kernel<<<DGRID, 256>>>(x, Wdp, res, part, n);
  stats_final_conv<<<1, 512>>>(part, DGRID, gd, bd, st + 2 * COUT, n);

  // h1 -> relu(bn1(h1)) -> fp16
  const int t42 = n * COUT / 4;
  conv_bn_f16<<<(t42 + 255) / 256, 256>>>(h1, st + 0, X2h, t42);

  // conv2 (fp16) -> h2pre (fp16) + fused bn2 partials; finalize bn2
  mma_conv<2><<<nbm, 512, smem>>>(X2h, nbr, B2, h2, part, n);
  stats_final_conv<<<1, 512>>>(part, nbm, g2, b2, st + 4 * COUT, n);

  // out = relu(bn2(h2pre)) + bn_d(respre)
  final_add<<<(t42 + 255) / 256, 256>>>(h2, res, st + 4 * COUT, st + 2 * COUT,
                                        out, n);
}